// round 1
// baseline (speedup 1.0000x reference)
#include <cuda_runtime.h>
#include <math.h>

// ---------------- problem constants ----------------
static constexpr int B_  = 8;
static constexpr int K_  = 1024;   // seq len of mamba-a / kf tokens
static constexpr int N_  = 98;     // imageFeature rows / mamba-a d_model
static constexpr int DM_ = 2048;   // d_model of mamba-c
static constexpr int DIA = 196;    // mamba-a d_inner
static constexpr int DRA = 7;      // mamba-a dt_rank
static constexpr int DIC = 4096;   // mamba-c d_inner
static constexpr int DRC = 128;    // mamba-c dt_rank
static constexpr int NS  = 16;     // d_state
static constexpr int LA  = 1024;   // mamba-a seq len
static constexpr int LC  = 98;     // mamba-c seq len
static constexpr int LDBA = DRA + 2 * NS;   // 39
static constexpr int LDBC = DRC + 2 * NS;   // 160

// ---------------- scratch arena (floats) ----------------
static constexpr size_t OFF_KFT   = 0;
static constexpr size_t SZ_KFT    = (size_t)B_ * K_ * DM_;        // 16.78M
static constexpr size_t OFF_IFT   = OFF_KFT + SZ_KFT;
static constexpr size_t SZ_IFT    = (size_t)DM_ * N_;
static constexpr size_t OFF_SCORE = OFF_IFT + SZ_IFT;
static constexpr size_t SZ_SCORE  = (size_t)B_ * K_ * N_;
static constexpr size_t OFF_XZA   = OFF_SCORE + SZ_SCORE;
static constexpr size_t SZ_XZA    = (size_t)B_ * K_ * 2 * DIA;
static constexpr size_t OFF_XIA   = OFF_XZA + SZ_XZA;
static constexpr size_t SZ_XIA    = (size_t)B_ * K_ * DIA;
static constexpr size_t OFF_XDBLA = OFF_XIA + SZ_XIA;
static constexpr size_t SZ_XDBLA  = (size_t)B_ * K_ * LDBA;
static constexpr size_t OFF_DTA   = OFF_XDBLA + SZ_XDBLA;
static constexpr size_t SZ_DTA    = (size_t)B_ * K_ * DIA;
static constexpr size_t OFF_YA    = OFF_DTA + SZ_DTA;
static constexpr size_t SZ_YA     = (size_t)B_ * K_ * DIA;
static constexpr size_t OFF_SC2   = OFF_YA + SZ_YA;
static constexpr size_t SZ_SC2    = (size_t)B_ * K_ * N_;
static constexpr size_t OFF_S     = OFF_SC2 + SZ_SC2;
static constexpr size_t SZ_S      = (size_t)B_ * K_;
static constexpr size_t OFF_H     = OFF_S + SZ_S;
static constexpr size_t SZ_H      = (size_t)B_ * LC * DM_;
static constexpr size_t OFF_XZC   = OFF_H + SZ_H;
static constexpr size_t SZ_XZC    = (size_t)B_ * LC * 2 * DIC;
static constexpr size_t OFF_XIC   = OFF_XZC + SZ_XZC;
static constexpr size_t SZ_XIC    = (size_t)B_ * LC * DIC;
static constexpr size_t OFF_XDBLC = OFF_XIC + SZ_XIC;
static constexpr size_t SZ_XDBLC  = (size_t)B_ * LC * LDBC;
static constexpr size_t OFF_DTC   = OFF_XDBLC + SZ_XDBLC;
static constexpr size_t SZ_DTC    = (size_t)B_ * LC * DIC;
static constexpr size_t OFF_YC    = OFF_DTC + SZ_DTC;
static constexpr size_t SZ_YC     = (size_t)B_ * LC * DIC;
static constexpr size_t SCRATCH_TOTAL = OFF_YC + SZ_YC;

__device__ float g_scratch[SCRATCH_TOTAL];
__device__ int   g_ind[B_ * N_];
__device__ float g_vtop[B_ * N_];

// ---------------- helpers ----------------
__device__ __forceinline__ float siluf(float x) { return x / (1.f + __expf(-x)); }
__device__ __forceinline__ float softplusf(float x) {
    return x > 20.f ? x : log1pf(__expf(x));
}

// ---------------- generic fp32 GEMM: C[M,N] = A[M,K] * B[K,N] ----------------
// 128x64 tile, BK=16, 256 threads, 8x4 microtile per thread.
#define GBM 128
#define GBN 64
#define GBK 16
#define GTM 8
#define GTN 4

__global__ __launch_bounds__(256) void sgemm_kernel(
    const float* __restrict__ A, int lda,
    const float* __restrict__ Bp, int ldb,
    float* __restrict__ C, int ldc,
    int M, int N, int K)
{
    __shared__ float As[GBK][GBM + 1];           // pad row to 129 -> conflict-lite stores
    __shared__ __align__(16) float Bs[GBK][GBN];

    const int tid  = threadIdx.x;
    const int row0 = blockIdx.y * GBM;
    const int col0 = blockIdx.x * GBN;
    const int tx   = tid & 15;   // 16 column groups * 4 cols = 64
    const int ty   = tid >> 4;   // 16 row groups * 8 rows = 128

    float acc[GTM][GTN];
#pragma unroll
    for (int i = 0; i < GTM; i++)
#pragma unroll
        for (int j = 0; j < GTN; j++) acc[i][j] = 0.f;

    for (int k0 = 0; k0 < K; k0 += GBK) {
        // load A tile (transposed into smem): warp reads 16 consecutive k per row
#pragma unroll
        for (int p = 0; p < (GBM * GBK) / 256; p++) {
            int idx = tid + p * 256;
            int m = idx >> 4;
            int k = idx & 15;
            int gm = row0 + m, gk = k0 + k;
            As[k][m] = (gm < M && gk < K) ? A[(size_t)gm * lda + gk] : 0.f;
        }
        // load B tile: coalesced along n
#pragma unroll
        for (int p = 0; p < (GBK * GBN) / 256; p++) {
            int idx = tid + p * 256;
            int k = idx >> 6;
            int n = idx & 63;
            int gk = k0 + k, gn = col0 + n;
            Bs[k][n] = (gk < K && gn < N) ? Bp[(size_t)gk * ldb + gn] : 0.f;
        }
        __syncthreads();

#pragma unroll
        for (int k = 0; k < GBK; k++) {
            float am[GTM];
#pragma unroll
            for (int i = 0; i < GTM; i++) am[i] = As[k][ty * GTM + i];
            float4 b4 = *(const float4*)&Bs[k][tx * GTN];
            float bn[GTN] = {b4.x, b4.y, b4.z, b4.w};
#pragma unroll
            for (int i = 0; i < GTM; i++)
#pragma unroll
                for (int j = 0; j < GTN; j++)
                    acc[i][j] = fmaf(am[i], bn[j], acc[i][j]);
        }
        __syncthreads();
    }

#pragma unroll
    for (int i = 0; i < GTM; i++) {
        int gm = row0 + ty * GTM + i;
        if (gm >= M) break;
#pragma unroll
        for (int j = 0; j < GTN; j++) {
            int gn = col0 + tx * GTN + j;
            if (gn < N) C[(size_t)gm * ldc + gn] = acc[i][j];
        }
    }
}

// ---------------- transpose: in[R,C] -> out[C,R] ----------------
__global__ void transpose_kernel(const float* __restrict__ in, float* __restrict__ out,
                                 int R, int C)
{
    __shared__ float t[32][33];
    int c0 = blockIdx.x * 32, r0 = blockIdx.y * 32;
    int tx = threadIdx.x, ty = threadIdx.y;  // 32 x 8
#pragma unroll
    for (int i = 0; i < 32; i += 8) {
        int r = r0 + ty + i, c = c0 + tx;
        if (r < R && c < C) t[ty + i][tx] = in[(size_t)r * C + c];
    }
    __syncthreads();
#pragma unroll
    for (int i = 0; i < 32; i += 8) {
        int c = c0 + ty + i, r = r0 + tx;
        if (c < C && r < R) out[(size_t)c * R + r] = t[tx][ty + i];
    }
}

// ---------------- depthwise causal conv (k=4) + silu ----------------
// xz row = (b*L + l), stride ldxz; channel ch lives at column ch.
__global__ void conv_silu_kernel(const float* __restrict__ xz, int ldxz,
                                 const float* __restrict__ w, const float* __restrict__ bias,
                                 float* __restrict__ xi, int Bn, int L, int dinner)
{
    int idx = blockIdx.x * blockDim.x + threadIdx.x;
    int total = Bn * L * dinner;
    if (idx >= total) return;
    int ch = idx % dinner;
    int l  = (idx / dinner) % L;
    int b  = idx / (dinner * L);
    const float* x0 = xz + (size_t)(b * L) * ldxz + ch;
    float acc = bias[ch];
    float w0 = w[ch * 4 + 0], w1 = w[ch * 4 + 1], w2 = w[ch * 4 + 2], w3 = w[ch * 4 + 3];
    if (l >= 3) acc = fmaf(w0, x0[(size_t)(l - 3) * ldxz], acc);
    if (l >= 2) acc = fmaf(w1, x0[(size_t)(l - 2) * ldxz], acc);
    if (l >= 1) acc = fmaf(w2, x0[(size_t)(l - 1) * ldxz], acc);
    acc = fmaf(w3, x0[(size_t)l * ldxz], acc);
    xi[idx] = siluf(acc);
}

// ---------------- dt = softplus(dt_raw + bias) (in place) ----------------
__global__ void softplus_bias_kernel(float* __restrict__ dt, const float* __restrict__ bias,
                                     int total, int dinner)
{
    int idx = blockIdx.x * blockDim.x + threadIdx.x;
    if (idx >= total) return;
    dt[idx] = softplusf(dt[idx] + bias[idx % dinner]);
}

// ---------------- y *= silu(z) ----------------
__global__ void mul_silu_kernel(float* __restrict__ y, const float* __restrict__ xz,
                                int ldxz, int zoff, int total, int dinner)
{
    int idx = blockIdx.x * blockDim.x + threadIdx.x;
    if (idx >= total) return;
    int row = idx / dinner, ch = idx % dinner;
    y[idx] *= siluf(xz[(size_t)row * ldxz + zoff + ch]);
}

// ---------------- selective scan: one warp = 2 channels, 16 lanes = d_state ----------------
__global__ void scan_kernel(const float* __restrict__ u, const float* __restrict__ dt,
                            const float* __restrict__ xdbl, int ld_dbl, int boff, int coff,
                            const float* __restrict__ A_log, const float* __restrict__ Dp,
                            float* __restrict__ y, int Bn, int L, int dinner)
{
    int gwarp = (blockIdx.x * blockDim.x + threadIdx.x) >> 5;
    int lane  = threadIdx.x & 31;
    int half  = lane >> 4;
    int n     = lane & 15;
    int gd    = gwarp * 2 + half;          // global channel index over (b, d)
    int total_d = Bn * dinner;
    if (gd >= total_d) return;
    int b   = gd / dinner;
    int dch = gd % dinner;

    float a  = -__expf(A_log[dch * NS + n]);
    float Dv = Dp[dch];
    float h = 0.f;

    const float* urow  = u    + (size_t)b * L * dinner + dch;
    const float* dtrow = dt   + (size_t)b * L * dinner + dch;
    const float* brow  = xdbl + (size_t)b * L * ld_dbl + boff + n;
    const float* crow  = xdbl + (size_t)b * L * ld_dbl + coff + n;
    float*       yrow  = y    + (size_t)b * L * dinner + dch;

    for (int t = 0; t < L; t++) {
        float dtv = dtrow[(size_t)t * dinner];
        float uv  = urow[(size_t)t * dinner];
        float Bv  = brow[(size_t)t * ld_dbl];
        float Cv  = crow[(size_t)t * ld_dbl];
        float dA  = __expf(dtv * a);
        h = fmaf(dA, h, dtv * Bv * uv);
        float p = h * Cv;
        p += __shfl_xor_sync(0xffffffffu, p, 8);
        p += __shfl_xor_sync(0xffffffffu, p, 4);
        p += __shfl_xor_sync(0xffffffffu, p, 2);
        p += __shfl_xor_sync(0xffffffffu, p, 1);
        if (n == 0) yrow[(size_t)t * dinner] = p + uv * Dv;
    }
}

// ---------------- mean over N_ then softmax over K_ (per batch) ----------------
__global__ void mean_softmax_kernel(const float* __restrict__ sc, float* __restrict__ s)
{
    __shared__ float sv[K_];
    __shared__ float red[256];
    int b = blockIdx.x, tid = threadIdx.x;
    for (int k = tid; k < K_; k += 256) {
        const float* row = sc + ((size_t)b * K_ + k) * N_;
        float acc = 0.f;
        for (int nn = 0; nn < N_; nn++) acc += row[nn];
        sv[k] = acc / (float)N_;
    }
    __syncthreads();
    float m = -1e30f;
    for (int k = tid; k < K_; k += 256) m = fmaxf(m, sv[k]);
    red[tid] = m; __syncthreads();
    for (int st = 128; st > 0; st >>= 1) {
        if (tid < st) red[tid] = fmaxf(red[tid], red[tid + st]);
        __syncthreads();
    }
    float mx = red[0]; __syncthreads();
    float sum = 0.f;
    for (int k = tid; k < K_; k += 256) { float e = __expf(sv[k] - mx); sv[k] = e; sum += e; }
    red[tid] = sum; __syncthreads();
    for (int st = 128; st > 0; st >>= 1) {
        if (tid < st) red[tid] += red[tid + st];
        __syncthreads();
    }
    float inv = 1.f / red[0];
    for (int k = tid; k < K_; k += 256) s[(size_t)b * K_ + k] = sv[k] * inv;
}

// ---------------- top-k(98 of 1024) via full bitonic sort (desc value, asc index) ----------------
__global__ void topk_kernel(const float* __restrict__ s, int* __restrict__ ind,
                            float* __restrict__ vtop)
{
    __shared__ float sv[K_];
    __shared__ int   si[K_];
    int b = blockIdx.x, tid = threadIdx.x;
    for (int i = tid; i < K_; i += 256) { sv[i] = s[(size_t)b * K_ + i]; si[i] = i; }
    __syncthreads();
    for (int k = 2; k <= K_; k <<= 1) {
        for (int j = k >> 1; j > 0; j >>= 1) {
            for (int i = tid; i < K_; i += 256) {
                int ixj = i ^ j;
                if (ixj > i) {
                    float v1 = sv[i], v2 = sv[ixj];
                    int   i1 = si[i], i2 = si[ixj];
                    bool lt_ji = (v2 > v1) || (v2 == v1 && i2 < i1); // e[ixj] before e[i]
                    bool lt_ij = (v1 > v2) || (v1 == v2 && i1 < i2); // e[i] before e[ixj]
                    bool asc = ((i & k) == 0);
                    if (asc ? lt_ji : lt_ij) {
                        sv[i] = v2; sv[ixj] = v1;
                        si[i] = i2; si[ixj] = i1;
                    }
                }
            }
            __syncthreads();
        }
    }
    for (int i = tid; i < N_; i += 256) {
        ind[b * N_ + i]  = si[i];
        vtop[b * N_ + i] = sv[i];
    }
}

// ---------------- h = imageFeature + gather(kfT, ind) * vtop ----------------
__global__ void build_h_kernel(const float* __restrict__ imf, const float* __restrict__ kfT,
                               const int* __restrict__ ind, const float* __restrict__ vtop,
                               float* __restrict__ h)
{
    int idx = blockIdx.x * blockDim.x + threadIdx.x;
    int total = B_ * LC * DM_;
    if (idx >= total) return;
    int d = idx % DM_;
    int j = (idx / DM_) % LC;
    int b = idx / (DM_ * LC);
    int r = ind[b * N_ + j];
    h[idx] = imf[(size_t)j * DM_ + d] +
             kfT[((size_t)b * K_ + r) * DM_ + d] * vtop[b * N_ + j];
}

// ---------------- host ----------------
extern "C" void kernel_launch(void* const* d_in, const int* in_sizes, int n_in,
                              void* d_out, int out_size)
{
    const float* imf      = (const float*)d_in[0];
    const float* kf       = (const float*)d_in[1];
    const float* a_in_w   = (const float*)d_in[2];
    const float* a_conv_w = (const float*)d_in[3];
    const float* a_conv_b = (const float*)d_in[4];
    const float* a_xproj_w= (const float*)d_in[5];
    const float* a_dt_w   = (const float*)d_in[6];
    const float* a_dt_b   = (const float*)d_in[7];
    const float* a_A_log  = (const float*)d_in[8];
    const float* a_D      = (const float*)d_in[9];
    const float* a_out_w  = (const float*)d_in[10];
    const float* c_in_w   = (const float*)d_in[11];
    const float* c_conv_w = (const float*)d_in[12];
    const float* c_conv_b = (const float*)d_in[13];
    const float* c_xproj_w= (const float*)d_in[14];
    const float* c_dt_w   = (const float*)d_in[15];
    const float* c_dt_b   = (const float*)d_in[16];
    const float* c_A_log  = (const float*)d_in[17];
    const float* c_D      = (const float*)d_in[18];
    const float* c_out_w  = (const float*)d_in[19];
    float* out = (float*)d_out;

    float* sc = nullptr;
    cudaGetSymbolAddress((void**)&sc, g_scratch);
    int*   p_ind  = nullptr;
    float* p_vtop = nullptr;
    cudaGetSymbolAddress((void**)&p_ind, g_ind);
    cudaGetSymbolAddress((void**)&p_vtop, g_vtop);

    float* kfT   = sc + OFF_KFT;
    float* ifT   = sc + OFF_IFT;
    float* score = sc + OFF_SCORE;
    float* xza   = sc + OFF_XZA;
    float* xia   = sc + OFF_XIA;
    float* xdbla = sc + OFF_XDBLA;
    float* dta   = sc + OFF_DTA;
    float* ya    = sc + OFF_YA;
    float* sc2   = sc + OFF_SC2;
    float* sbuf  = sc + OFF_S;
    float* hbuf  = sc + OFF_H;
    float* xzc   = sc + OFF_XZC;
    float* xic   = sc + OFF_XIC;
    float* xdblc = sc + OFF_XDBLC;
    float* dtc   = sc + OFF_DTC;
    float* yc    = sc + OFF_YC;

    dim3 tb(32, 8);

    // kf (b, DM, K) -> kfT (b, K, DM)
    for (int b = 0; b < B_; b++)
        transpose_kernel<<<dim3(K_ / 32, DM_ / 32), tb>>>(
            kf + (size_t)b * DM_ * K_, kfT + (size_t)b * K_ * DM_, DM_, K_);
    // imageFeature (N, DM) -> ifT (DM, N)
    transpose_kernel<<<dim3(DM_ / 32, (N_ + 31) / 32), tb>>>(imf, ifT, N_, DM_);

    // score = kfT (8192 x 2048) @ ifT (2048 x 98)
    sgemm_kernel<<<dim3((N_ + GBN - 1) / GBN, (B_ * K_) / GBM), 256>>>(
        kfT, DM_, ifT, N_, score, N_, B_ * K_, N_, DM_);

    // ---- mamba a ----
    sgemm_kernel<<<dim3((2 * DIA + GBN - 1) / GBN, (B_ * K_) / GBM), 256>>>(
        score, N_, a_in_w, 2 * DIA, xza, 2 * DIA, B_ * K_, 2 * DIA, N_);
    conv_silu_kernel<<<(B_ * LA * DIA) / 256, 256>>>(xza, 2 * DIA, a_conv_w, a_conv_b,
                                                     xia, B_, LA, DIA);
    sgemm_kernel<<<dim3((LDBA + GBN - 1) / GBN, (B_ * K_) / GBM), 256>>>(
        xia, DIA, a_xproj_w, LDBA, xdbla, LDBA, B_ * K_, LDBA, DIA);
    sgemm_kernel<<<dim3((DIA + GBN - 1) / GBN, (B_ * K_) / GBM), 256>>>(
        xdbla, LDBA, a_dt_w, DIA, dta, DIA, B_ * K_, DIA, DRA);
    softplus_bias_kernel<<<(B_ * K_ * DIA + 255) / 256, 256>>>(dta, a_dt_b, B_ * K_ * DIA, DIA);
    scan_kernel<<<(B_ * DIA / 2 * 32) / 256, 256>>>(xia, dta, xdbla, LDBA, DRA, DRA + NS,
                                                    a_A_log, a_D, ya, B_, LA, DIA);
    mul_silu_kernel<<<(B_ * K_ * DIA + 255) / 256, 256>>>(ya, xza, 2 * DIA, DIA,
                                                          B_ * K_ * DIA, DIA);
    sgemm_kernel<<<dim3((N_ + GBN - 1) / GBN, (B_ * K_) / GBM), 256>>>(
        ya, DIA, a_out_w, N_, sc2, N_, B_ * K_, N_, DIA);

    // ---- softmax / topk / gather ----
    mean_softmax_kernel<<<B_, 256>>>(sc2, sbuf);
    topk_kernel<<<B_, 256>>>(sbuf, p_ind, p_vtop);
    build_h_kernel<<<(B_ * LC * DM_ + 255) / 256, 256>>>(imf, kfT, p_ind, p_vtop, hbuf);

    // ---- mamba c ----
    int Mc = B_ * LC;  // 784
    sgemm_kernel<<<dim3((2 * DIC) / GBN, (Mc + GBM - 1) / GBM), 256>>>(
        hbuf, DM_, c_in_w, 2 * DIC, xzc, 2 * DIC, Mc, 2 * DIC, DM_);
    conv_silu_kernel<<<(B_ * LC * DIC + 255) / 256, 256>>>(xzc, 2 * DIC, c_conv_w, c_conv_b,
                                                           xic, B_, LC, DIC);
    sgemm_kernel<<<dim3((LDBC + GBN - 1) / GBN, (Mc + GBM - 1) / GBM), 256>>>(
        xic, DIC, c_xproj_w, LDBC, xdblc, LDBC, Mc, LDBC, DIC);
    sgemm_kernel<<<dim3(DIC / GBN, (Mc + GBM - 1) / GBM), 256>>>(
        xdblc, LDBC, c_dt_w, DIC, dtc, DIC, Mc, DIC, DRC);
    softplus_bias_kernel<<<(B_ * LC * DIC + 255) / 256, 256>>>(dtc, c_dt_b, B_ * LC * DIC, DIC);
    scan_kernel<<<(B_ * DIC / 2 * 32) / 256, 256>>>(xic, dtc, xdblc, LDBC, DRC, DRC + NS,
                                                    c_A_log, c_D, yc, B_, LC, DIC);
    mul_silu_kernel<<<(B_ * LC * DIC + 255) / 256, 256>>>(yc, xzc, 2 * DIC, DIC,
                                                          B_ * LC * DIC, DIC);
    sgemm_kernel<<<dim3(DM_ / GBN, (Mc + GBM - 1) / GBM), 256>>>(
        yc, DIC, c_out_w, DM_, out, DM_, Mc, DM_, DIC);
}

// round 2
// speedup vs baseline: 1.1519x; 1.1519x over previous
#include <cuda_runtime.h>
#include <math.h>

// ---------------- problem constants ----------------
static constexpr int B_  = 8;
static constexpr int K_  = 1024;
static constexpr int N_  = 98;
static constexpr int DM_ = 2048;
static constexpr int DIA = 196;
static constexpr int DRA = 7;
static constexpr int DIC = 4096;
static constexpr int DRC = 128;
static constexpr int NS  = 16;
static constexpr int LA  = 1024;
static constexpr int LC  = 98;
static constexpr int LDBA = DRA + 2 * NS;   // 39
static constexpr int LDBC = DRC + 2 * NS;   // 160

static constexpr int SPLITK_SCORE = 4;
static constexpr int SPLITK_XPC   = 8;
static constexpr int SPLITK_COUT  = 2;

// ---------------- scratch arena ----------------
static constexpr size_t SZ_SCOREP = (size_t)SPLITK_SCORE * B_ * K_ * N_;   // 3.2M
static constexpr size_t SZ_XZA    = (size_t)B_ * K_ * 2 * DIA;
static constexpr size_t SZ_XIA    = (size_t)B_ * K_ * DIA;
static constexpr size_t SZ_XDBLA  = (size_t)B_ * K_ * LDBA;
static constexpr size_t SZ_DTA    = (size_t)B_ * K_ * DIA;
static constexpr size_t SZ_YA     = (size_t)B_ * K_ * DIA;
static constexpr size_t SZ_SC2    = (size_t)B_ * K_ * N_;
static constexpr size_t SZ_S      = (size_t)B_ * K_;
static constexpr size_t SZ_H      = (size_t)B_ * LC * DM_;
static constexpr size_t SZ_XZC    = (size_t)B_ * LC * 2 * DIC;
static constexpr size_t SZ_XIC    = (size_t)B_ * LC * DIC;
static constexpr size_t SZ_XDBLC  = (size_t)B_ * LC * LDBC;
static constexpr size_t SZ_XPCP   = (size_t)SPLITK_XPC * B_ * LC * LDBC;
static constexpr size_t SZ_DTC    = (size_t)B_ * LC * DIC;
static constexpr size_t SZ_YC     = (size_t)B_ * LC * DIC;
static constexpr size_t SZ_OUTP   = (size_t)SPLITK_COUT * B_ * LC * DM_;

static constexpr size_t OFF_SCOREP = 0;
static constexpr size_t OFF_XZA    = OFF_SCOREP + SZ_SCOREP;
static constexpr size_t OFF_XIA    = OFF_XZA + SZ_XZA;
static constexpr size_t OFF_XDBLA  = OFF_XIA + SZ_XIA;
static constexpr size_t OFF_DTA    = OFF_XDBLA + SZ_XDBLA;
static constexpr size_t OFF_YA     = OFF_DTA + SZ_DTA;
static constexpr size_t OFF_SC2    = OFF_YA + SZ_YA;
static constexpr size_t OFF_S      = OFF_SC2 + SZ_SC2;
static constexpr size_t OFF_H      = OFF_S + SZ_S;
static constexpr size_t OFF_XZC    = OFF_H + SZ_H;
static constexpr size_t OFF_XIC    = OFF_XZC + SZ_XZC;
static constexpr size_t OFF_XDBLC  = OFF_XIC + SZ_XIC;
static constexpr size_t OFF_XPCP   = OFF_XDBLC + SZ_XDBLC;
static constexpr size_t OFF_DTC    = OFF_XPCP + SZ_XPCP;
static constexpr size_t OFF_YC     = OFF_DTC + SZ_DTC;
static constexpr size_t OFF_OUTP   = OFF_YC + SZ_YC;
static constexpr size_t SCRATCH_TOTAL = OFF_OUTP + SZ_OUTP;

__device__ float g_scratch[SCRATCH_TOTAL];
__device__ int   g_ind[B_ * N_];
__device__ float g_vtop[B_ * N_];

// ---------------- helpers ----------------
__device__ __forceinline__ float siluf(float x) { return x / (1.f + __expf(-x)); }
__device__ __forceinline__ float softplusf(float x) {
    return x > 20.f ? x : log1pf(__expf(x));
}
static inline int ceil_div(int a, int b) { return (a + b - 1) / b; }

// ---------------- GEMM: 128x128x16, double-buffered, 8x8 microtile ----------------
// TT:    A element (m,k) at A[k*lda+m], B element (k,n) at B[n*ldb+k]
// AMODE: 0 plain, 1 A *= silu(Z[m*ldz+k]), 2 A = sum of 4 partials (stride asum_stride)
// EPI:   softplus(acc + bias[n])
#define GBK 16
#define BMP 132   // 128 + 4 pad

template<bool TT, int AMODE, bool EPI>
__global__ __launch_bounds__(256) void gemm128(
    const float* __restrict__ A, int lda,
    const float* __restrict__ Bp, int ldb,
    float* __restrict__ C, int ldc,
    int M, int N, int Ktot,
    int splitk,
    size_t batchA, size_t batchC, size_t strideS,
    const float* __restrict__ Zp, int ldz,
    size_t asum_stride,
    const float* __restrict__ bias)
{
    __shared__ __align__(16) float As[2][GBK][BMP];
    __shared__ __align__(16) float Bs[2][GBK][BMP];

    const int tid  = threadIdx.x;
    const int tx   = tid & 15;
    const int ty   = tid >> 4;
    const int row0 = blockIdx.y * 128;
    const int col0 = blockIdx.x * 128;

    const int z = blockIdx.z;
    const int b = z / splitk;
    const int s = z - b * splitk;
    const float* Ab = A + (size_t)b * batchA;
    float*       Cb = C + (size_t)b * batchC + (size_t)s * strideS;
    const int kchunk = Ktot / splitk;
    const int kbeg = s * kchunk;
    const int kend = (s == splitk - 1) ? Ktot : kbeg + kchunk;

    float acc[8][8];
#pragma unroll
    for (int i = 0; i < 8; i++)
#pragma unroll
        for (int j = 0; j < 8; j++) acc[i][j] = 0.f;

    float ra[8], rb[8];

#define LOAD_TILES(K0)                                                          \
    _Pragma("unroll")                                                           \
    for (int p = 0; p < 8; p++) {                                               \
        int idx = tid + p * 256;                                                \
        int am, ak;                                                             \
        if (TT) { am = idx & 127; ak = idx >> 7; }                              \
        else    { am = idx >> 4;  ak = idx & 15; }                              \
        int gm = row0 + am, gk = (K0) + ak;                                     \
        float v = 0.f;                                                          \
        if (gm < M && gk < kend) {                                              \
            size_t aoff = TT ? ((size_t)gk * lda + gm)                          \
                             : ((size_t)gm * lda + gk);                         \
            v = Ab[aoff];                                                       \
            if (AMODE == 1) v *= siluf(Zp[(size_t)gm * ldz + gk]);              \
            if (AMODE == 2) {                                                   \
                v += Ab[aoff + asum_stride];                                    \
                v += Ab[aoff + 2 * asum_stride];                                \
                v += Ab[aoff + 3 * asum_stride];                                \
            }                                                                   \
        }                                                                       \
        ra[p] = v;                                                              \
        int bn, bk;                                                             \
        if (TT) { bn = idx >> 4; bk = idx & 15; }                               \
        else    { bk = idx >> 7; bn = idx & 127; }                              \
        int gn = col0 + bn; gk = (K0) + bk;                                     \
        v = 0.f;                                                                \
        if (gn < N && gk < kend)                                                \
            v = Bp[TT ? ((size_t)gn * ldb + gk) : ((size_t)gk * ldb + gn)];     \
        rb[p] = v;                                                              \
    }

#define STORE_TILES(BUF)                                                        \
    _Pragma("unroll")                                                           \
    for (int p = 0; p < 8; p++) {                                               \
        int idx = tid + p * 256;                                                \
        int am, ak, bn, bk;                                                     \
        if (TT) { am = idx & 127; ak = idx >> 7; bn = idx >> 4; bk = idx & 15; }\
        else    { am = idx >> 4;  ak = idx & 15; bk = idx >> 7; bn = idx & 127;}\
        As[BUF][ak][am] = ra[p];                                                \
        Bs[BUF][bk][bn] = rb[p];                                                \
    }

    LOAD_TILES(kbeg);
    STORE_TILES(0);
    __syncthreads();

    int buf = 0;
    for (int k0 = kbeg; k0 < kend; k0 += GBK) {
        const bool more = (k0 + GBK) < kend;
        if (more) { LOAD_TILES(k0 + GBK); }

#pragma unroll
        for (int kk = 0; kk < GBK; kk++) {
            const float* Ar = &As[buf][kk][0];
            const float* Br = &Bs[buf][kk][0];
            float4 a0 = *(const float4*)(Ar + ty * 4);
            float4 a1 = *(const float4*)(Ar + 64 + ty * 4);
            float4 b0 = *(const float4*)(Br + tx * 4);
            float4 b1 = *(const float4*)(Br + 64 + tx * 4);
            float av[8] = {a0.x, a0.y, a0.z, a0.w, a1.x, a1.y, a1.z, a1.w};
            float bv[8] = {b0.x, b0.y, b0.z, b0.w, b1.x, b1.y, b1.z, b1.w};
#pragma unroll
            for (int i = 0; i < 8; i++)
#pragma unroll
                for (int j = 0; j < 8; j++)
                    acc[i][j] = fmaf(av[i], bv[j], acc[i][j]);
        }

        if (more) { STORE_TILES(buf ^ 1); }
        __syncthreads();
        buf ^= 1;
    }

#pragma unroll
    for (int i = 0; i < 8; i++) {
        int gm = row0 + ((i < 4) ? (ty * 4 + i) : (64 + ty * 4 + i - 4));
        if (gm >= M) continue;
#pragma unroll
        for (int j = 0; j < 8; j++) {
            int gn = col0 + ((j < 4) ? (tx * 4 + j) : (64 + tx * 4 + j - 4));
            if (gn >= N) continue;
            float v = acc[i][j];
            if (EPI) v = softplusf(v + bias[gn]);
            Cb[(size_t)gm * ldc + gn] = v;
        }
    }
#undef LOAD_TILES
#undef STORE_TILES
}

// ---------------- fixed-order split-K reduction ----------------
__global__ void reduce_sum_kernel(const float* __restrict__ part, float* __restrict__ out,
                                  int total, size_t stride, int ns)
{
    int i = blockIdx.x * blockDim.x + threadIdx.x;
    if (i >= total) return;
    float a = 0.f;
    for (int s = 0; s < ns; s++) a += part[(size_t)s * stride + i];
    out[i] = a;
}

// ---------------- depthwise causal conv (k=4) + silu ----------------
__global__ void conv_silu_kernel(const float* __restrict__ xz, int ldxz,
                                 const float* __restrict__ w, const float* __restrict__ bias,
                                 float* __restrict__ xi, int Bn, int L, int dinner)
{
    int idx = blockIdx.x * blockDim.x + threadIdx.x;
    int total = Bn * L * dinner;
    if (idx >= total) return;
    int ch = idx % dinner;
    int l  = (idx / dinner) % L;
    int b  = idx / (dinner * L);
    const float* x0 = xz + (size_t)(b * L) * ldxz + ch;
    float acc = bias[ch];
    float w0 = w[ch * 4 + 0], w1 = w[ch * 4 + 1], w2 = w[ch * 4 + 2], w3 = w[ch * 4 + 3];
    if (l >= 3) acc = fmaf(w0, x0[(size_t)(l - 3) * ldxz], acc);
    if (l >= 2) acc = fmaf(w1, x0[(size_t)(l - 2) * ldxz], acc);
    if (l >= 1) acc = fmaf(w2, x0[(size_t)(l - 1) * ldxz], acc);
    acc = fmaf(w3, x0[(size_t)l * ldxz], acc);
    xi[idx] = siluf(acc);
}

// ---------------- selective scan, TCH-step chunks ----------------
template<int TCH>
__global__ void scan_kernel(const float* __restrict__ u, const float* __restrict__ dt,
                            const float* __restrict__ xdbl, int ld_dbl, int boff, int coff,
                            const float* __restrict__ A_log, const float* __restrict__ Dp,
                            float* __restrict__ y, int Bn, int L, int dinner)
{
    int gwarp = (blockIdx.x * blockDim.x + threadIdx.x) >> 5;
    int lane  = threadIdx.x & 31;
    int half  = lane >> 4;
    int n     = lane & 15;
    int gd    = gwarp * 2 + half;
    if (gd >= Bn * dinner) return;
    int b   = gd / dinner;
    int dch = gd - b * dinner;

    float a  = -__expf(A_log[dch * NS + n]);
    float Dv = Dp[dch];
    float h  = 0.f;

    const float* urow  = u    + (size_t)b * L * dinner + dch;
    const float* dtrow = dt   + (size_t)b * L * dinner + dch;
    const float* brow  = xdbl + (size_t)b * L * ld_dbl + boff + n;
    const float* crow  = xdbl + (size_t)b * L * ld_dbl + coff + n;
    float*       yrow  = y    + (size_t)b * L * dinner + dch;

    for (int t0 = 0; t0 < L; t0 += TCH) {
        float vdt[TCH], vu[TCH], vB[TCH], vC[TCH];
#pragma unroll
        for (int tt = 0; tt < TCH; tt++) {
            size_t t = (size_t)(t0 + tt);
            vdt[tt] = dtrow[t * dinner];
            vu[tt]  = urow[t * dinner];
            vB[tt]  = brow[t * ld_dbl];
            vC[tt]  = crow[t * ld_dbl];
        }
        float p[TCH];
#pragma unroll
        for (int tt = 0; tt < TCH; tt++) {
            float dA = __expf(vdt[tt] * a);
            h = fmaf(dA, h, vdt[tt] * vB[tt] * vu[tt]);
            p[tt] = h * vC[tt] + ((n == 0) ? vu[tt] * Dv : 0.f);
        }
#pragma unroll
        for (int tt = 0; tt < TCH; tt++) p[tt] += __shfl_xor_sync(0xffffffffu, p[tt], 8);
#pragma unroll
        for (int tt = 0; tt < TCH; tt++) p[tt] += __shfl_xor_sync(0xffffffffu, p[tt], 4);
#pragma unroll
        for (int tt = 0; tt < TCH; tt++) p[tt] += __shfl_xor_sync(0xffffffffu, p[tt], 2);
#pragma unroll
        for (int tt = 0; tt < TCH; tt++) p[tt] += __shfl_xor_sync(0xffffffffu, p[tt], 1);
#pragma unroll
        for (int tt = 0; tt < TCH; tt++)
            if (n == tt) yrow[(size_t)(t0 + tt) * dinner] = p[tt];
    }
}

// ---------------- mean over N_ then softmax over K_ ----------------
__global__ void mean_softmax_kernel(const float* __restrict__ sc, float* __restrict__ s)
{
    __shared__ float sv[K_];
    __shared__ float red[256];
    int b = blockIdx.x, tid = threadIdx.x;
    for (int k = tid; k < K_; k += 256) {
        const float* row = sc + ((size_t)b * K_ + k) * N_;
        float acc = 0.f;
        for (int nn = 0; nn < N_; nn++) acc += row[nn];
        sv[k] = acc / (float)N_;
    }
    __syncthreads();
    float m = -1e30f;
    for (int k = tid; k < K_; k += 256) m = fmaxf(m, sv[k]);
    red[tid] = m; __syncthreads();
    for (int st = 128; st > 0; st >>= 1) {
        if (tid < st) red[tid] = fmaxf(red[tid], red[tid + st]);
        __syncthreads();
    }
    float mx = red[0]; __syncthreads();
    float sum = 0.f;
    for (int k = tid; k < K_; k += 256) { float e = __expf(sv[k] - mx); sv[k] = e; sum += e; }
    red[tid] = sum; __syncthreads();
    for (int st = 128; st > 0; st >>= 1) {
        if (tid < st) red[tid] += red[tid + st];
        __syncthreads();
    }
    float inv = 1.f / red[0];
    for (int k = tid; k < K_; k += 256) s[(size_t)b * K_ + k] = sv[k] * inv;
}

// ---------------- top-k(98 of 1024) bitonic (desc value, asc index ties) ----------------
__global__ void topk_kernel(const float* __restrict__ s, int* __restrict__ ind,
                            float* __restrict__ vtop)
{
    __shared__ float sv[K_];
    __shared__ int   si[K_];
    int b = blockIdx.x, tid = threadIdx.x;
    for (int i = tid; i < K_; i += 256) { sv[i] = s[(size_t)b * K_ + i]; si[i] = i; }
    __syncthreads();
    for (int k = 2; k <= K_; k <<= 1) {
        for (int j = k >> 1; j > 0; j >>= 1) {
            for (int i = tid; i < K_; i += 256) {
                int ixj = i ^ j;
                if (ixj > i) {
                    float v1 = sv[i], v2 = sv[ixj];
                    int   i1 = si[i], i2 = si[ixj];
                    bool lt_ji = (v2 > v1) || (v2 == v1 && i2 < i1);
                    bool lt_ij = (v1 > v2) || (v1 == v2 && i1 < i2);
                    bool asc = ((i & k) == 0);
                    if (asc ? lt_ji : lt_ij) {
                        sv[i] = v2; sv[ixj] = v1;
                        si[i] = i2; si[ixj] = i1;
                    }
                }
            }
            __syncthreads();
        }
    }
    for (int i = tid; i < N_; i += 256) {
        ind[b * N_ + i]  = si[i];
        vtop[b * N_ + i] = sv[i];
    }
}

// ---------------- h = imageFeature + gather(kf, ind) * vtop (kf native layout) ----------------
__global__ void build_h_kernel(const float* __restrict__ imf, const float* __restrict__ kf,
                               const int* __restrict__ ind, const float* __restrict__ vtop,
                               float* __restrict__ h)
{
    int idx = blockIdx.x * blockDim.x + threadIdx.x;
    int total = B_ * LC * DM_;
    if (idx >= total) return;
    int d = idx % DM_;
    int j = (idx / DM_) % LC;
    int b = idx / (DM_ * LC);
    int r = ind[b * N_ + j];
    h[idx] = imf[(size_t)j * DM_ + d] +
             kf[((size_t)b * DM_ + d) * K_ + r] * vtop[b * N_ + j];
}

// ---------------- host ----------------
extern "C" void kernel_launch(void* const* d_in, const int* in_sizes, int n_in,
                              void* d_out, int out_size)
{
    const float* imf      = (const float*)d_in[0];
    const float* kf       = (const float*)d_in[1];
    const float* a_in_w   = (const float*)d_in[2];
    const float* a_conv_w = (const float*)d_in[3];
    const float* a_conv_b = (const float*)d_in[4];
    const float* a_xproj_w= (const float*)d_in[5];
    const float* a_dt_w   = (const float*)d_in[6];
    const float* a_dt_b   = (const float*)d_in[7];
    const float* a_A_log  = (const float*)d_in[8];
    const float* a_D      = (const float*)d_in[9];
    const float* a_out_w  = (const float*)d_in[10];
    const float* c_in_w   = (const float*)d_in[11];
    const float* c_conv_w = (const float*)d_in[12];
    const float* c_conv_b = (const float*)d_in[13];
    const float* c_xproj_w= (const float*)d_in[14];
    const float* c_dt_w   = (const float*)d_in[15];
    const float* c_dt_b   = (const float*)d_in[16];
    const float* c_A_log  = (const float*)d_in[17];
    const float* c_D      = (const float*)d_in[18];
    const float* c_out_w  = (const float*)d_in[19];
    float* out = (float*)d_out;

    float* sc = nullptr;
    cudaGetSymbolAddress((void**)&sc, g_scratch);
    int*   p_ind  = nullptr;
    float* p_vtop = nullptr;
    cudaGetSymbolAddress((void**)&p_ind, g_ind);
    cudaGetSymbolAddress((void**)&p_vtop, g_vtop);

    float* scorep = sc + OFF_SCOREP;
    float* xza    = sc + OFF_XZA;
    float* xia    = sc + OFF_XIA;
    float* xdbla  = sc + OFF_XDBLA;
    float* dta    = sc + OFF_DTA;
    float* ya     = sc + OFF_YA;
    float* sc2    = sc + OFF_SC2;
    float* sbuf   = sc + OFF_S;
    float* hbuf   = sc + OFF_H;
    float* xzc    = sc + OFF_XZC;
    float* xic    = sc + OFF_XIC;
    float* xdblc  = sc + OFF_XDBLC;
    float* xpcp   = sc + OFF_XPCP;
    float* dtc    = sc + OFF_DTC;
    float* yc     = sc + OFF_YC;
    float* outp   = sc + OFF_OUTP;

    const int Ma = B_ * K_;   // 8192
    const int Mc = B_ * LC;   // 784

    // 0: score partials = kf^T @ imf^T (TT, batched over b, split-K=4)
    gemm128<true, 0, false><<<dim3(1, K_ / 128, B_ * SPLITK_SCORE), 256>>>(
        kf, K_, imf, DM_, scorep, N_, K_, N_, DM_, SPLITK_SCORE,
        (size_t)DM_ * K_, (size_t)K_ * N_, (size_t)B_ * K_ * N_,
        nullptr, 0, 0, nullptr);

    // 1: xza = (sum of score partials) @ a_in_w  (AMODE=2 fuses the reduction)
    gemm128<false, 2, false><<<dim3(ceil_div(2 * DIA, 128), Ma / 128, 1), 256>>>(
        scorep, N_, a_in_w, 2 * DIA, xza, 2 * DIA, Ma, 2 * DIA, N_, 1,
        0, 0, 0, nullptr, 0, (size_t)B_ * K_ * N_, nullptr);

    // 2: conv + silu (mamba a)
    conv_silu_kernel<<<ceil_div(B_ * LA * DIA, 256), 256>>>(
        xza, 2 * DIA, a_conv_w, a_conv_b, xia, B_, LA, DIA);

    // 3: x_dbl = xi @ a_xproj_w
    gemm128<false, 0, false><<<dim3(1, Ma / 128, 1), 256>>>(
        xia, DIA, a_xproj_w, LDBA, xdbla, LDBA, Ma, LDBA, DIA, 1,
        0, 0, 0, nullptr, 0, 0, nullptr);

    // 4: dt = softplus(xdbl[:, :7] @ a_dt_w + a_dt_b)  (fused epilogue)
    gemm128<false, 0, true><<<dim3(ceil_div(DIA, 128), Ma / 128, 1), 256>>>(
        xdbla, LDBA, a_dt_w, DIA, dta, DIA, Ma, DIA, DRA, 1,
        0, 0, 0, nullptr, 0, 0, a_dt_b);

    // 5: selective scan (mamba a)
    scan_kernel<16><<<(B_ * DIA / 2 * 32) / 256, 256>>>(
        xia, dta, xdbla, LDBA, DRA, DRA + NS, a_A_log, a_D, ya, B_, LA, DIA);

    // 6: sc2 = (y * silu(z)) @ a_out_w  (fused A-silu)
    gemm128<false, 1, false><<<dim3(1, Ma / 128, 1), 256>>>(
        ya, DIA, a_out_w, N_, sc2, N_, Ma, N_, DIA, 1,
        0, 0, 0, xza + DIA, 2 * DIA, 0, nullptr);

    // 7-9: softmax / topk / gather
    mean_softmax_kernel<<<B_, 256>>>(sc2, sbuf);
    topk_kernel<<<B_, 256>>>(sbuf, p_ind, p_vtop);
    build_h_kernel<<<ceil_div(B_ * LC * DM_, 256), 256>>>(imf, kf, p_ind, p_vtop, hbuf);

    // 10: xzc = h @ c_in_w
    gemm128<false, 0, false><<<dim3((2 * DIC) / 128, ceil_div(Mc, 128), 1), 256>>>(
        hbuf, DM_, c_in_w, 2 * DIC, xzc, 2 * DIC, Mc, 2 * DIC, DM_, 1,
        0, 0, 0, nullptr, 0, 0, nullptr);

    // 11: conv + silu (mamba c)
    conv_silu_kernel<<<ceil_div(B_ * LC * DIC, 256), 256>>>(
        xzc, 2 * DIC, c_conv_w, c_conv_b, xic, B_, LC, DIC);

    // 12: x_dbl partials = xi @ c_xproj_w  (split-K=8)
    gemm128<false, 0, false><<<dim3(ceil_div(LDBC, 128), ceil_div(Mc, 128), SPLITK_XPC), 256>>>(
        xic, DIC, c_xproj_w, LDBC, xpcp, LDBC, Mc, LDBC, DIC, SPLITK_XPC,
        0, 0, (size_t)Mc * LDBC, nullptr, 0, 0, nullptr);

    // 13: reduce partials -> xdblc
    reduce_sum_kernel<<<ceil_div(Mc * LDBC, 256), 256>>>(
        xpcp, xdblc, Mc * LDBC, (size_t)Mc * LDBC, SPLITK_XPC);

    // 14: dt = softplus(xdbl[:, :128] @ c_dt_w + c_dt_b)
    gemm128<false, 0, true><<<dim3(DIC / 128, ceil_div(Mc, 128), 1), 256>>>(
        xdblc, LDBC, c_dt_w, DIC, dtc, DIC, Mc, DIC, DRC, 1,
        0, 0, 0, nullptr, 0, 0, c_dt_b);

    // 15: selective scan (mamba c)
    scan_kernel<14><<<(B_ * DIC / 2 * 32) / 256, 256>>>(
        xic, dtc, xdblc, LDBC, DRC, DRC + NS, c_A_log, c_D, yc, B_, LC, DIC);

    // 16: out partials = (y * silu(z)) @ c_out_w  (fused A-silu, split-K=2)
    gemm128<false, 1, false><<<dim3(DM_ / 128, ceil_div(Mc, 128), SPLITK_COUT), 256>>>(
        yc, DIC, c_out_w, DM_, outp, DM_, Mc, DM_, DIC, SPLITK_COUT,
        0, 0, (size_t)Mc * DM_, xzc + DIC, 2 * DIC, 0, nullptr);

    // 17: reduce partials -> out
    reduce_sum_kernel<<<ceil_div(Mc * DM_, 256), 256>>>(
        outp, out, Mc * DM_, (size_t)Mc * DM_, SPLITK_COUT);
}

// round 3
// speedup vs baseline: 1.3842x; 1.2016x over previous
#include <cuda_runtime.h>
#include <cuda_bf16.h>
#include <math.h>
#include <stdint.h>

// ---------------- problem constants ----------------
static constexpr int B_  = 8;
static constexpr int K_  = 1024;
static constexpr int N_  = 98;
static constexpr int DM_ = 2048;
static constexpr int DIA = 196;
static constexpr int DRA = 7;
static constexpr int DIC = 4096;
static constexpr int DRC = 128;
static constexpr int NS  = 16;
static constexpr int LA  = 1024;
static constexpr int LC  = 98;
static constexpr int LDBA = DRA + 2 * NS;   // 39
static constexpr int LDBC = DRC + 2 * NS;   // 160

static constexpr int SPLITK_SCORE = 4;
static constexpr int SPLITK_XPC   = 8;
static constexpr int SPLITK_COUT  = 2;

// ---------------- scratch arena ----------------
static constexpr size_t SZ_SCOREP = (size_t)SPLITK_SCORE * B_ * K_ * N_;
static constexpr size_t SZ_XZA    = (size_t)B_ * K_ * 2 * DIA;
static constexpr size_t SZ_XIA    = (size_t)B_ * K_ * DIA;
static constexpr size_t SZ_XDBLA  = (size_t)B_ * K_ * LDBA;
static constexpr size_t SZ_DTA    = (size_t)B_ * K_ * DIA;
static constexpr size_t SZ_YA     = (size_t)B_ * K_ * DIA;
static constexpr size_t SZ_SC2    = (size_t)B_ * K_ * N_;
static constexpr size_t SZ_S      = (size_t)B_ * K_;
static constexpr size_t SZ_H      = (size_t)B_ * LC * DM_;
static constexpr size_t SZ_XZC    = (size_t)B_ * LC * 2 * DIC;
static constexpr size_t SZ_XIC    = (size_t)B_ * LC * DIC;
static constexpr size_t SZ_XDBLC  = (size_t)B_ * LC * LDBC;
static constexpr size_t SZ_XPCP   = (size_t)SPLITK_XPC * B_ * LC * LDBC;
static constexpr size_t SZ_DTC    = (size_t)B_ * LC * DIC;
static constexpr size_t SZ_YC     = (size_t)B_ * LC * DIC;
static constexpr size_t SZ_OUTP   = (size_t)SPLITK_COUT * B_ * LC * DM_;

static constexpr size_t OFF_SCOREP = 0;
static constexpr size_t OFF_XZA    = OFF_SCOREP + SZ_SCOREP;
static constexpr size_t OFF_XIA    = OFF_XZA + SZ_XZA;
static constexpr size_t OFF_XDBLA  = OFF_XIA + SZ_XIA;
static constexpr size_t OFF_DTA    = OFF_XDBLA + SZ_XDBLA;
static constexpr size_t OFF_YA     = OFF_DTA + SZ_DTA;
static constexpr size_t OFF_SC2    = OFF_YA + SZ_YA;
static constexpr size_t OFF_S      = OFF_SC2 + SZ_SC2;
static constexpr size_t OFF_H      = OFF_S + SZ_S;
static constexpr size_t OFF_XZC    = OFF_H + SZ_H;
static constexpr size_t OFF_XIC    = OFF_XZC + SZ_XZC;
static constexpr size_t OFF_XDBLC  = OFF_XIC + SZ_XIC;
static constexpr size_t OFF_XPCP   = OFF_XDBLC + SZ_XDBLC;
static constexpr size_t OFF_DTC    = OFF_XPCP + SZ_XPCP;
static constexpr size_t OFF_YC     = OFF_DTC + SZ_DTC;
static constexpr size_t OFF_OUTP   = OFF_YC + SZ_YC;
static constexpr size_t SCRATCH_TOTAL = OFF_OUTP + SZ_OUTP;

__device__ float g_scratch[SCRATCH_TOTAL];
__device__ int   g_ind[B_ * N_];
__device__ float g_vtop[B_ * N_];

// ---------------- helpers ----------------
__device__ __forceinline__ float siluf(float x) { return x / (1.f + __expf(-x)); }
__device__ __forceinline__ float softplusf(float x) {
    return x > 20.f ? x : log1pf(__expf(x));
}
static inline int ceil_div(int a, int b) { return (a + b - 1) / b; }

__device__ __forceinline__ void ldsm_x4(uint32_t (&r)[4], uint32_t addr) {
    asm volatile("ldmatrix.sync.aligned.m8n8.x4.shared.b16 {%0,%1,%2,%3}, [%4];"
                 : "=r"(r[0]), "=r"(r[1]), "=r"(r[2]), "=r"(r[3]) : "r"(addr));
}
__device__ __forceinline__ void ldsm_x4_t(uint32_t (&r)[4], uint32_t addr) {
    asm volatile("ldmatrix.sync.aligned.m8n8.x4.trans.shared.b16 {%0,%1,%2,%3}, [%4];"
                 : "=r"(r[0]), "=r"(r[1]), "=r"(r[2]), "=r"(r[3]) : "r"(addr));
}
__device__ __forceinline__ void mma_bf16(float (&d)[4], const uint32_t (&a)[4],
                                         uint32_t b0, uint32_t b1) {
    asm volatile("mma.sync.aligned.m16n8k16.row.col.f32.bf16.bf16.f32 "
                 "{%0,%1,%2,%3}, {%4,%5,%6,%7}, {%8,%9}, {%0,%1,%2,%3};"
                 : "+f"(d[0]), "+f"(d[1]), "+f"(d[2]), "+f"(d[3])
                 : "r"(a[0]), "r"(a[1]), "r"(a[2]), "r"(a[3]), "r"(b0), "r"(b1));
}
__device__ __forceinline__ void split_bf(float v, __nv_bfloat16& h, __nv_bfloat16& l) {
    h = __float2bfloat16(v);
    l = __float2bfloat16(v - __bfloat162float(h));
}

// ================= tensor-core GEMM (bf16x3): C = A[M,K] @ B[K,N], NN =================
// Block tile 128x128xK32, 256 threads (8 warps, 64x32 warp tiles).
// AMODE: 0 plain, 1 A *= silu(Z), 2 A = sum of 4 partials. EPI: softplus(acc + bias[n]).
static constexpr int SA_STAGE = 128 * 40;        // elems, A padded stride 40
static constexpr int SB_STAGE = 32 * 136;        // elems, B padded stride 136
static constexpr int TC_AHI = 0;
static constexpr int TC_ALO = 2 * SA_STAGE;                 // 10240
static constexpr int TC_BHI = 4 * SA_STAGE;                 // 20480
static constexpr int TC_BLO = TC_BHI + 2 * SB_STAGE;        // 29184
static constexpr int TC_SMEM_ELEMS = TC_BLO + 2 * SB_STAGE; // 37888
static constexpr int TC_SMEM_BYTES = TC_SMEM_ELEMS * 2;     // 75776

template<int AMODE, bool EPI>
__global__ __launch_bounds__(256, 1) void gemm_tc(
    const float* __restrict__ A, int lda,
    const float* __restrict__ Bp, int ldb,
    float* __restrict__ C, int ldc,
    int M, int N, int Ktot, int splitk, size_t strideS,
    const float* __restrict__ Zp, int ldz,
    size_t asum_stride, const float* __restrict__ bias)
{
    extern __shared__ __align__(16) __nv_bfloat16 smem_tc[];

    const int tid  = threadIdx.x;
    const int lane = tid & 31;
    const int wid  = tid >> 5;
    const int wm   = (wid & 1) << 6;   // 0 / 64
    const int wn   = (wid >> 1) << 5;  // 0 / 32 / 64 / 96
    const int row0 = blockIdx.y * 128;
    const int col0 = blockIdx.x * 128;

    const int s = blockIdx.z;
    float* Cb = C + (size_t)s * strideS;
    const int kchunk = Ktot / splitk;
    const int kbeg = s * kchunk;
    const int kend = (s == splitk - 1) ? Ktot : kbeg + kchunk;

    const uint32_t sbase = (uint32_t)__cvta_generic_to_shared(smem_tc);

    // ldmatrix lane addressing
    const int ar = lane & 15;
    const int ac = (lane >> 4) << 3;
    const int br = (lane & 7) + ((lane >> 3) & 1) * 8;
    const int bc = (lane >> 4) << 3;

    float acc[4][4][4];
#pragma unroll
    for (int i = 0; i < 4; i++)
#pragma unroll
        for (int j = 0; j < 4; j++)
#pragma unroll
            for (int q = 0; q < 4; q++) acc[i][j][q] = 0.f;

    float ra[16], rb[16];

#define TC_LOADG(K0)                                                             \
    _Pragma("unroll")                                                            \
    for (int p = 0; p < 16; p++) {                                               \
        int idx = tid + p * 256;                                                 \
        int am = idx >> 5, ak = idx & 31;                                        \
        int gm = row0 + am, gk = (K0) + ak;                                      \
        float v = 0.f;                                                           \
        if (gm < M && gk < kend) {                                               \
            size_t aoff = (size_t)gm * lda + gk;                                 \
            v = A[aoff];                                                         \
            if (AMODE == 1) v *= siluf(Zp[(size_t)gm * ldz + gk]);               \
            if (AMODE == 2) {                                                    \
                v += A[aoff + asum_stride];                                      \
                v += A[aoff + 2 * asum_stride];                                  \
                v += A[aoff + 3 * asum_stride];                                  \
            }                                                                    \
        }                                                                        \
        ra[p] = v;                                                               \
        int bk = idx >> 7, bn = idx & 127;                                       \
        int gk2 = (K0) + bk, gn = col0 + bn;                                     \
        rb[p] = (gk2 < kend && gn < N) ? Bp[(size_t)gk2 * ldb + gn] : 0.f;       \
    }

#define TC_STORES(BUF)                                                           \
    _Pragma("unroll")                                                            \
    for (int p = 0; p < 16; p++) {                                               \
        int idx = tid + p * 256;                                                 \
        int am = idx >> 5, ak = idx & 31;                                        \
        __nv_bfloat16 h, l;                                                      \
        split_bf(ra[p], h, l);                                                   \
        smem_tc[TC_AHI + (BUF) * SA_STAGE + am * 40 + ak] = h;                   \
        smem_tc[TC_ALO + (BUF) * SA_STAGE + am * 40 + ak] = l;                   \
        int bk = idx >> 7, bn = idx & 127;                                       \
        split_bf(rb[p], h, l);                                                   \
        smem_tc[TC_BHI + (BUF) * SB_STAGE + bk * 136 + bn] = h;                  \
        smem_tc[TC_BLO + (BUF) * SB_STAGE + bk * 136 + bn] = l;                  \
    }

    TC_LOADG(kbeg);
    TC_STORES(0);
    __syncthreads();

    int buf = 0;
    for (int k0 = kbeg; k0 < kend; k0 += 32) {
        const bool more = (k0 + 32) < kend;
        if (more) { TC_LOADG(k0 + 32); }

        const uint32_t sa_hi = sbase + (TC_AHI + buf * SA_STAGE) * 2;
        const uint32_t sa_lo = sbase + (TC_ALO + buf * SA_STAGE) * 2;
        const uint32_t sb_hi = sbase + (TC_BHI + buf * SB_STAGE) * 2;
        const uint32_t sb_lo = sbase + (TC_BLO + buf * SB_STAGE) * 2;

#pragma unroll
        for (int sub = 0; sub < 2; sub++) {
            const int kk0 = sub * 16;
            uint32_t ah[4][4], al[4][4], bh[2][4], bl[2][4];
#pragma unroll
            for (int i = 0; i < 4; i++) {
                uint32_t off = ((wm + i * 16 + ar) * 40 + kk0 + ac) * 2;
                ldsm_x4(ah[i], sa_hi + off);
                ldsm_x4(al[i], sa_lo + off);
            }
#pragma unroll
            for (int g = 0; g < 2; g++) {
                uint32_t off = ((kk0 + br) * 136 + wn + g * 16 + bc) * 2;
                ldsm_x4_t(bh[g], sb_hi + off);
                ldsm_x4_t(bl[g], sb_lo + off);
            }
#pragma unroll
            for (int i = 0; i < 4; i++)
#pragma unroll
                for (int j = 0; j < 4; j++) {
                    const int g = j >> 1, t = (j & 1) * 2;
                    mma_bf16(acc[i][j], ah[i], bh[g][t], bh[g][t + 1]);
                    mma_bf16(acc[i][j], ah[i], bl[g][t], bl[g][t + 1]);
                    mma_bf16(acc[i][j], al[i], bh[g][t], bh[g][t + 1]);
                }
        }

        if (more) { TC_STORES(buf ^ 1); }
        __syncthreads();
        buf ^= 1;
    }

    // epilogue
    const int er = lane >> 2;
    const int ec = (lane & 3) * 2;
#pragma unroll
    for (int i = 0; i < 4; i++) {
#pragma unroll
        for (int j = 0; j < 4; j++) {
            int gm0 = row0 + wm + i * 16 + er;
            int gn  = col0 + wn + j * 8 + ec;
            if (gn >= N) continue;
            float v0 = acc[i][j][0], v1 = acc[i][j][1];
            float v2 = acc[i][j][2], v3 = acc[i][j][3];
            if (EPI) {
                float b0 = bias[gn];
                float b1 = (gn + 1 < N) ? bias[gn + 1] : 0.f;
                v0 = softplusf(v0 + b0); v1 = softplusf(v1 + b1);
                v2 = softplusf(v2 + b0); v3 = softplusf(v3 + b1);
            }
            if (gm0 < M) {
                Cb[(size_t)gm0 * ldc + gn] = v0;
                if (gn + 1 < N) Cb[(size_t)gm0 * ldc + gn + 1] = v1;
            }
            int gm1 = gm0 + 8;
            if (gm1 < M) {
                Cb[(size_t)gm1 * ldc + gn] = v2;
                if (gn + 1 < N) Cb[(size_t)gm1 * ldc + gn + 1] = v3;
            }
        }
    }
#undef TC_LOADG
#undef TC_STORES
}

// ================= fp32 GEMM (kept for the TT-layout score GEMM) =================
#define GBK 16
#define BMP 132

template<bool TT>
__global__ __launch_bounds__(256) void gemm128(
    const float* __restrict__ A, int lda,
    const float* __restrict__ Bp, int ldb,
    float* __restrict__ C, int ldc,
    int M, int N, int Ktot, int splitk,
    size_t batchA, size_t batchC, size_t strideS)
{
    __shared__ __align__(16) float As[2][GBK][BMP];
    __shared__ __align__(16) float Bs[2][GBK][BMP];

    const int tid  = threadIdx.x;
    const int tx   = tid & 15;
    const int ty   = tid >> 4;
    const int row0 = blockIdx.y * 128;
    const int col0 = blockIdx.x * 128;

    const int z = blockIdx.z;
    const int b = z / splitk;
    const int s = z - b * splitk;
    const float* Ab = A + (size_t)b * batchA;
    float*       Cb = C + (size_t)b * batchC + (size_t)s * strideS;
    const int kchunk = Ktot / splitk;
    const int kbeg = s * kchunk;
    const int kend = (s == splitk - 1) ? Ktot : kbeg + kchunk;

    float acc[8][8];
#pragma unroll
    for (int i = 0; i < 8; i++)
#pragma unroll
        for (int j = 0; j < 8; j++) acc[i][j] = 0.f;

    float ra[8], rb[8];

#define LOAD_TILES(K0)                                                          \
    _Pragma("unroll")                                                           \
    for (int p = 0; p < 8; p++) {                                               \
        int idx = tid + p * 256;                                                \
        int am, ak;                                                             \
        if (TT) { am = idx & 127; ak = idx >> 7; }                              \
        else    { am = idx >> 4;  ak = idx & 15; }                              \
        int gm = row0 + am, gk = (K0) + ak;                                     \
        float v = 0.f;                                                          \
        if (gm < M && gk < kend)                                                \
            v = Ab[TT ? ((size_t)gk * lda + gm) : ((size_t)gm * lda + gk)];     \
        ra[p] = v;                                                              \
        int bn, bk;                                                             \
        if (TT) { bn = idx >> 4; bk = idx & 15; }                               \
        else    { bk = idx >> 7; bn = idx & 127; }                              \
        int gn = col0 + bn; gk = (K0) + bk;                                     \
        v = 0.f;                                                                \
        if (gn < N && gk < kend)                                                \
            v = Bp[TT ? ((size_t)gn * ldb + gk) : ((size_t)gk * ldb + gn)];     \
        rb[p] = v;                                                              \
    }

#define STORE_TILES(BUF)                                                        \
    _Pragma("unroll")                                                           \
    for (int p = 0; p < 8; p++) {                                               \
        int idx = tid + p * 256;                                                \
        int am, ak, bn, bk;                                                     \
        if (TT) { am = idx & 127; ak = idx >> 7; bn = idx >> 4; bk = idx & 15; }\
        else    { am = idx >> 4;  ak = idx & 15; bk = idx >> 7; bn = idx & 127;}\
        As[BUF][ak][am] = ra[p];                                                \
        Bs[BUF][bk][bn] = rb[p];                                                \
    }

    LOAD_TILES(kbeg);
    STORE_TILES(0);
    __syncthreads();

    int buf = 0;
    for (int k0 = kbeg; k0 < kend; k0 += GBK) {
        const bool more = (k0 + GBK) < kend;
        if (more) { LOAD_TILES(k0 + GBK); }

#pragma unroll
        for (int kk = 0; kk < GBK; kk++) {
            const float* Ar = &As[buf][kk][0];
            const float* Br = &Bs[buf][kk][0];
            float4 a0 = *(const float4*)(Ar + ty * 4);
            float4 a1 = *(const float4*)(Ar + 64 + ty * 4);
            float4 b0 = *(const float4*)(Br + tx * 4);
            float4 b1 = *(const float4*)(Br + 64 + tx * 4);
            float av[8] = {a0.x, a0.y, a0.z, a0.w, a1.x, a1.y, a1.z, a1.w};
            float bv[8] = {b0.x, b0.y, b0.z, b0.w, b1.x, b1.y, b1.z, b1.w};
#pragma unroll
            for (int i = 0; i < 8; i++)
#pragma unroll
                for (int j = 0; j < 8; j++)
                    acc[i][j] = fmaf(av[i], bv[j], acc[i][j]);
        }

        if (more) { STORE_TILES(buf ^ 1); }
        __syncthreads();
        buf ^= 1;
    }

#pragma unroll
    for (int i = 0; i < 8; i++) {
        int gm = row0 + ((i < 4) ? (ty * 4 + i) : (64 + ty * 4 + i - 4));
        if (gm >= M) continue;
#pragma unroll
        for (int j = 0; j < 8; j++) {
            int gn = col0 + ((j < 4) ? (tx * 4 + j) : (64 + tx * 4 + j - 4));
            if (gn >= N) continue;
            Cb[(size_t)gm * ldc + gn] = acc[i][j];
        }
    }
#undef LOAD_TILES
#undef STORE_TILES
}

// ---------------- fixed-order split-K reduction ----------------
__global__ void reduce_sum_kernel(const float* __restrict__ part, float* __restrict__ out,
                                  int total, size_t stride, int ns)
{
    int i = blockIdx.x * blockDim.x + threadIdx.x;
    if (i >= total) return;
    float a = 0.f;
    for (int s = 0; s < ns; s++) a += part[(size_t)s * stride + i];
    out[i] = a;
}

// ---------------- depthwise causal conv (k=4) + silu ----------------
__global__ void conv_silu_kernel(const float* __restrict__ xz, int ldxz,
                                 const float* __restrict__ w, const float* __restrict__ bias,
                                 float* __restrict__ xi, int Bn, int L, int dinner)
{
    int idx = blockIdx.x * blockDim.x + threadIdx.x;
    int total = Bn * L * dinner;
    if (idx >= total) return;
    int ch = idx % dinner;
    int l  = (idx / dinner) % L;
    int b  = idx / (dinner * L);
    const float* x0 = xz + (size_t)(b * L) * ldxz + ch;
    float acc = bias[ch];
    float w0 = w[ch * 4 + 0], w1 = w[ch * 4 + 1], w2 = w[ch * 4 + 2], w3 = w[ch * 4 + 3];
    if (l >= 3) acc = fmaf(w0, x0[(size_t)(l - 3) * ldxz], acc);
    if (l >= 2) acc = fmaf(w1, x0[(size_t)(l - 2) * ldxz], acc);
    if (l >= 1) acc = fmaf(w2, x0[(size_t)(l - 1) * ldxz], acc);
    acc = fmaf(w3, x0[(size_t)l * ldxz], acc);
    xi[idx] = siluf(acc);
}

// ---------------- selective scan, TCH-step chunks ----------------
template<int TCH>
__global__ void scan_kernel(const float* __restrict__ u, const float* __restrict__ dt,
                            const float* __restrict__ xdbl, int ld_dbl, int boff, int coff,
                            const float* __restrict__ A_log, const float* __restrict__ Dp,
                            float* __restrict__ y, int Bn, int L, int dinner)
{
    int gwarp = (blockIdx.x * blockDim.x + threadIdx.x) >> 5;
    int lane  = threadIdx.x & 31;
    int half  = lane >> 4;
    int n     = lane & 15;
    int gd    = gwarp * 2 + half;
    if (gd >= Bn * dinner) return;
    int b   = gd / dinner;
    int dch = gd - b * dinner;

    float a  = -__expf(A_log[dch * NS + n]);
    float Dv = Dp[dch];
    float h  = 0.f;

    const float* urow  = u    + (size_t)b * L * dinner + dch;
    const float* dtrow = dt   + (size_t)b * L * dinner + dch;
    const float* brow  = xdbl + (size_t)b * L * ld_dbl + boff + n;
    const float* crow  = xdbl + (size_t)b * L * ld_dbl + coff + n;
    float*       yrow  = y    + (size_t)b * L * dinner + dch;

    for (int t0 = 0; t0 < L; t0 += TCH) {
        float vdt[TCH], vu[TCH], vB[TCH], vC[TCH];
#pragma unroll
        for (int tt = 0; tt < TCH; tt++) {
            size_t t = (size_t)(t0 + tt);
            vdt[tt] = dtrow[t * dinner];
            vu[tt]  = urow[t * dinner];
            vB[tt]  = brow[t * ld_dbl];
            vC[tt]  = crow[t * ld_dbl];
        }
        float p[TCH];
#pragma unroll
        for (int tt = 0; tt < TCH; tt++) {
            float dA = __expf(vdt[tt] * a);
            h = fmaf(dA, h, vdt[tt] * vB[tt] * vu[tt]);
            p[tt] = h * vC[tt] + ((n == 0) ? vu[tt] * Dv : 0.f);
        }
#pragma unroll
        for (int tt = 0; tt < TCH; tt++) p[tt] += __shfl_xor_sync(0xffffffffu, p[tt], 8);
#pragma unroll
        for (int tt = 0; tt < TCH; tt++) p[tt] += __shfl_xor_sync(0xffffffffu, p[tt], 4);
#pragma unroll
        for (int tt = 0; tt < TCH; tt++) p[tt] += __shfl_xor_sync(0xffffffffu, p[tt], 2);
#pragma unroll
        for (int tt = 0; tt < TCH; tt++) p[tt] += __shfl_xor_sync(0xffffffffu, p[tt], 1);
#pragma unroll
        for (int tt = 0; tt < TCH; tt++)
            if (n == tt) yrow[(size_t)(t0 + tt) * dinner] = p[tt];
    }
}

// ---------------- mean over N_ then softmax over K_ ----------------
__global__ void mean_softmax_kernel(const float* __restrict__ sc, float* __restrict__ s)
{
    __shared__ float sv[K_];
    __shared__ float red[256];
    int b = blockIdx.x, tid = threadIdx.x;
    for (int k = tid; k < K_; k += 256) {
        const float* row = sc + ((size_t)b * K_ + k) * N_;
        float acc = 0.f;
        for (int nn = 0; nn < N_; nn++) acc += row[nn];
        sv[k] = acc / (float)N_;
    }
    __syncthreads();
    float m = -1e30f;
    for (int k = tid; k < K_; k += 256) m = fmaxf(m, sv[k]);
    red[tid] = m; __syncthreads();
    for (int st = 128; st > 0; st >>= 1) {
        if (tid < st) red[tid] = fmaxf(red[tid], red[tid + st]);
        __syncthreads();
    }
    float mx = red[0]; __syncthreads();
    float sum = 0.f;
    for (int k = tid; k < K_; k += 256) { float e = __expf(sv[k] - mx); sv[k] = e; sum += e; }
    red[tid] = sum; __syncthreads();
    for (int st = 128; st > 0; st >>= 1) {
        if (tid < st) red[tid] += red[tid + st];
        __syncthreads();
    }
    float inv = 1.f / red[0];
    for (int k = tid; k < K_; k += 256) s[(size_t)b * K_ + k] = sv[k] * inv;
}

// ---------------- top-k(98 of 1024) bitonic ----------------
__global__ void topk_kernel(const float* __restrict__ s, int* __restrict__ ind,
                            float* __restrict__ vtop)
{
    __shared__ float sv[K_];
    __shared__ int   si[K_];
    int b = blockIdx.x, tid = threadIdx.x;
    for (int i = tid; i < K_; i += 256) { sv[i] = s[(size_t)b * K_ + i]; si[i] = i; }
    __syncthreads();
    for (int k = 2; k <= K_; k <<= 1) {
        for (int j = k >> 1; j > 0; j >>= 1) {
            for (int i = tid; i < K_; i += 256) {
                int ixj = i ^ j;
                if (ixj > i) {
                    float v1 = sv[i], v2 = sv[ixj];
                    int   i1 = si[i], i2 = si[ixj];
                    bool lt_ji = (v2 > v1) || (v2 == v1 && i2 < i1);
                    bool lt_ij = (v1 > v2) || (v1 == v2 && i1 < i2);
                    bool asc = ((i & k) == 0);
                    if (asc ? lt_ji : lt_ij) {
                        sv[i] = v2; sv[ixj] = v1;
                        si[i] = i2; si[ixj] = i1;
                    }
                }
            }
            __syncthreads();
        }
    }
    for (int i = tid; i < N_; i += 256) {
        ind[b * N_ + i]  = si[i];
        vtop[b * N_ + i] = sv[i];
    }
}

// ---------------- h = imageFeature + gather(kf, ind) * vtop ----------------
__global__ void build_h_kernel(const float* __restrict__ imf, const float* __restrict__ kf,
                               const int* __restrict__ ind, const float* __restrict__ vtop,
                               float* __restrict__ h)
{
    int idx = blockIdx.x * blockDim.x + threadIdx.x;
    int total = B_ * LC * DM_;
    if (idx >= total) return;
    int d = idx % DM_;
    int j = (idx / DM_) % LC;
    int b = idx / (DM_ * LC);
    int r = ind[b * N_ + j];
    h[idx] = imf[(size_t)j * DM_ + d] +
             kf[((size_t)b * DM_ + d) * K_ + r] * vtop[b * N_ + j];
}

// ---------------- host ----------------
extern "C" void kernel_launch(void* const* d_in, const int* in_sizes, int n_in,
                              void* d_out, int out_size)
{
    const float* imf      = (const float*)d_in[0];
    const float* kf       = (const float*)d_in[1];
    const float* a_in_w   = (const float*)d_in[2];
    const float* a_conv_w = (const float*)d_in[3];
    const float* a_conv_b = (const float*)d_in[4];
    const float* a_xproj_w= (const float*)d_in[5];
    const float* a_dt_w   = (const float*)d_in[6];
    const float* a_dt_b   = (const float*)d_in[7];
    const float* a_A_log  = (const float*)d_in[8];
    const float* a_D      = (const float*)d_in[9];
    const float* a_out_w  = (const float*)d_in[10];
    const float* c_in_w   = (const float*)d_in[11];
    const float* c_conv_w = (const float*)d_in[12];
    const float* c_conv_b = (const float*)d_in[13];
    const float* c_xproj_w= (const float*)d_in[14];
    const float* c_dt_w   = (const float*)d_in[15];
    const float* c_dt_b   = (const float*)d_in[16];
    const float* c_A_log  = (const float*)d_in[17];
    const float* c_D      = (const float*)d_in[18];
    const float* c_out_w  = (const float*)d_in[19];
    float* out = (float*)d_out;

    static bool attr_done = false;
    if (!attr_done) {
        cudaFuncSetAttribute(gemm_tc<0, false>, cudaFuncAttributeMaxDynamicSharedMemorySize, TC_SMEM_BYTES);
        cudaFuncSetAttribute(gemm_tc<1, false>, cudaFuncAttributeMaxDynamicSharedMemorySize, TC_SMEM_BYTES);
        cudaFuncSetAttribute(gemm_tc<2, false>, cudaFuncAttributeMaxDynamicSharedMemorySize, TC_SMEM_BYTES);
        cudaFuncSetAttribute(gemm_tc<0, true>,  cudaFuncAttributeMaxDynamicSharedMemorySize, TC_SMEM_BYTES);
        attr_done = true;
    }

    float* sc = nullptr;
    cudaGetSymbolAddress((void**)&sc, g_scratch);
    int*   p_ind  = nullptr;
    float* p_vtop = nullptr;
    cudaGetSymbolAddress((void**)&p_ind, g_ind);
    cudaGetSymbolAddress((void**)&p_vtop, g_vtop);

    float* scorep = sc + OFF_SCOREP;
    float* xza    = sc + OFF_XZA;
    float* xia    = sc + OFF_XIA;
    float* xdbla  = sc + OFF_XDBLA;
    float* dta    = sc + OFF_DTA;
    float* ya     = sc + OFF_YA;
    float* sc2    = sc + OFF_SC2;
    float* sbuf   = sc + OFF_S;
    float* hbuf   = sc + OFF_H;
    float* xzc    = sc + OFF_XZC;
    float* xic    = sc + OFF_XIC;
    float* xdblc  = sc + OFF_XDBLC;
    float* xpcp   = sc + OFF_XPCP;
    float* dtc    = sc + OFF_DTC;
    float* yc     = sc + OFF_YC;
    float* outp   = sc + OFF_OUTP;

    const int Ma = B_ * K_;   // 8192
    const int Mc = B_ * LC;   // 784

    // 0: score partials = kf^T @ imf^T (fp32 TT, batched, split-K=4)
    gemm128<true><<<dim3(1, K_ / 128, B_ * SPLITK_SCORE), 256>>>(
        kf, K_, imf, DM_, scorep, N_, K_, N_, DM_, SPLITK_SCORE,
        (size_t)DM_ * K_, (size_t)K_ * N_, (size_t)B_ * K_ * N_);

    // 1: xza = (sum of 4 score partials) @ a_in_w
    gemm_tc<2, false><<<dim3(ceil_div(2 * DIA, 128), Ma / 128, 1), 256, TC_SMEM_BYTES>>>(
        scorep, N_, a_in_w, 2 * DIA, xza, 2 * DIA, Ma, 2 * DIA, N_, 1, 0,
        nullptr, 0, (size_t)B_ * K_ * N_, nullptr);

    // 2: conv + silu (a)
    conv_silu_kernel<<<ceil_div(B_ * LA * DIA, 256), 256>>>(
        xza, 2 * DIA, a_conv_w, a_conv_b, xia, B_, LA, DIA);

    // 3: x_dbl = xi @ a_xproj_w
    gemm_tc<0, false><<<dim3(1, Ma / 128, 1), 256, TC_SMEM_BYTES>>>(
        xia, DIA, a_xproj_w, LDBA, xdbla, LDBA, Ma, LDBA, DIA, 1, 0,
        nullptr, 0, 0, nullptr);

    // 4: dt = softplus(xdbl[:, :7] @ a_dt_w + b)
    gemm_tc<0, true><<<dim3(ceil_div(DIA, 128), Ma / 128, 1), 256, TC_SMEM_BYTES>>>(
        xdbla, LDBA, a_dt_w, DIA, dta, DIA, Ma, DIA, DRA, 1, 0,
        nullptr, 0, 0, a_dt_b);

    // 5: selective scan (a)
    scan_kernel<16><<<(B_ * DIA / 2 * 32) / 256, 256>>>(
        xia, dta, xdbla, LDBA, DRA, DRA + NS, a_A_log, a_D, ya, B_, LA, DIA);

    // 6: sc2 = (y * silu(z)) @ a_out_w
    gemm_tc<1, false><<<dim3(1, Ma / 128, 1), 256, TC_SMEM_BYTES>>>(
        ya, DIA, a_out_w, N_, sc2, N_, Ma, N_, DIA, 1, 0,
        xza + DIA, 2 * DIA, 0, nullptr);

    // 7-9: softmax / topk / gather
    mean_softmax_kernel<<<B_, 256>>>(sc2, sbuf);
    topk_kernel<<<B_, 256>>>(sbuf, p_ind, p_vtop);
    build_h_kernel<<<ceil_div(B_ * LC * DM_, 256), 256>>>(imf, kf, p_ind, p_vtop, hbuf);

    // 10: xzc = h @ c_in_w   (26.3 GF -> tensor)
    gemm_tc<0, false><<<dim3((2 * DIC) / 128, ceil_div(Mc, 128), 1), 256, TC_SMEM_BYTES>>>(
        hbuf, DM_, c_in_w, 2 * DIC, xzc, 2 * DIC, Mc, 2 * DIC, DM_, 1, 0,
        nullptr, 0, 0, nullptr);

    // 11: conv + silu (c)
    conv_silu_kernel<<<ceil_div(B_ * LC * DIC, 256), 256>>>(
        xzc, 2 * DIC, c_conv_w, c_conv_b, xic, B_, LC, DIC);

    // 12: x_dbl partials = xi @ c_xproj_w (split-K=8)
    gemm_tc<0, false><<<dim3(ceil_div(LDBC, 128), ceil_div(Mc, 128), SPLITK_XPC), 256, TC_SMEM_BYTES>>>(
        xic, DIC, c_xproj_w, LDBC, xpcp, LDBC, Mc, LDBC, DIC, SPLITK_XPC,
        (size_t)Mc * LDBC, nullptr, 0, 0, nullptr);

    // 13: reduce -> xdblc
    reduce_sum_kernel<<<ceil_div(Mc * LDBC, 256), 256>>>(
        xpcp, xdblc, Mc * LDBC, (size_t)Mc * LDBC, SPLITK_XPC);

    // 14: dt = softplus(xdbl[:, :128] @ c_dt_w + b)
    gemm_tc<0, true><<<dim3(DIC / 128, ceil_div(Mc, 128), 1), 256, TC_SMEM_BYTES>>>(
        xdblc, LDBC, c_dt_w, DIC, dtc, DIC, Mc, DIC, DRC, 1, 0,
        nullptr, 0, 0, c_dt_b);

    // 15: selective scan (c)
    scan_kernel<14><<<(B_ * DIC / 2 * 32) / 256, 256>>>(
        xic, dtc, xdblc, LDBC, DRC, DRC + NS, c_A_log, c_D, yc, B_, LC, DIC);

    // 16: out partials = (y * silu(z)) @ c_out_w (13.2 GF -> tensor, split-K=2)
    gemm_tc<1, false><<<dim3(DM_ / 128, ceil_div(Mc, 128), SPLITK_COUT), 256, TC_SMEM_BYTES>>>(
        yc, DIC, c_out_w, DM_, outp, DM_, Mc, DM_, DIC, SPLITK_COUT,
        (size_t)Mc * DM_, xzc + DIC, 2 * DIC, 0, nullptr);

    // 17: reduce -> out
    reduce_sum_kernel<<<ceil_div(Mc * DM_, 256), 256>>>(
        outp, out, Mc * DM_, (size_t)Mc * DM_, SPLITK_COUT);
}

// round 4
// speedup vs baseline: 2.1954x; 1.5861x over previous
#include <cuda_runtime.h>
#include <cuda_bf16.h>
#include <math.h>
#include <stdint.h>

// ---------------- problem constants ----------------
static constexpr int B_  = 8;
static constexpr int K_  = 1024;
static constexpr int N_  = 98;
static constexpr int DM_ = 2048;
static constexpr int DIA = 196;
static constexpr int DRA = 7;
static constexpr int DIC = 4096;
static constexpr int DRC = 128;
static constexpr int NS  = 16;
static constexpr int LA  = 1024;
static constexpr int LC  = 98;
static constexpr int LDBA = DRA + 2 * NS;   // 39
static constexpr int LDBC = DRC + 2 * NS;   // 160

static constexpr int SPLITK_SCT  = 2;
static constexpr int SPLITK_XPC  = 8;
static constexpr int SPLITK_COUT = 2;

// ---------------- scratch arena ----------------
static constexpr size_t SZ_SCT1  = (size_t)B_ * N_ * K_;             // one scoreT copy
static constexpr size_t SZ_SCTP  = (size_t)SPLITK_SCT * SZ_SCT1;
static constexpr size_t SZ_XZA   = (size_t)B_ * K_ * 2 * DIA;
static constexpr size_t SZ_XIA   = (size_t)B_ * K_ * DIA;
static constexpr size_t SZ_XDBLA = (size_t)B_ * K_ * LDBA;
static constexpr size_t SZ_DTA   = (size_t)B_ * K_ * DIA;
static constexpr size_t SZ_YA    = (size_t)B_ * K_ * DIA;
static constexpr size_t SZ_SC2   = (size_t)B_ * K_ * N_;
static constexpr size_t SZ_S     = (size_t)B_ * K_;
static constexpr size_t SZ_H     = (size_t)B_ * LC * DM_;
static constexpr size_t SZ_XZC   = (size_t)B_ * LC * 2 * DIC;
static constexpr size_t SZ_XIC   = (size_t)B_ * LC * DIC;
static constexpr size_t SZ_XDBLC = (size_t)B_ * LC * LDBC;
static constexpr size_t SZ_XPCP  = (size_t)SPLITK_XPC * B_ * LC * LDBC;
static constexpr size_t SZ_DTC   = (size_t)B_ * LC * DIC;
static constexpr size_t SZ_YC    = (size_t)B_ * LC * DIC;
static constexpr size_t SZ_OUTP  = (size_t)SPLITK_COUT * B_ * LC * DM_;

static constexpr size_t OFF_SCTP  = 0;
static constexpr size_t OFF_SCT   = OFF_SCTP + SZ_SCTP;
static constexpr size_t OFF_XZA   = OFF_SCT + SZ_SCT1;
static constexpr size_t OFF_XIA   = OFF_XZA + SZ_XZA;
static constexpr size_t OFF_XDBLA = OFF_XIA + SZ_XIA;
static constexpr size_t OFF_DTA   = OFF_XDBLA + SZ_XDBLA;
static constexpr size_t OFF_YA    = OFF_DTA + SZ_DTA;
static constexpr size_t OFF_SC2   = OFF_YA + SZ_YA;
static constexpr size_t OFF_S     = OFF_SC2 + SZ_SC2;
static constexpr size_t OFF_H     = OFF_S + SZ_S;
static constexpr size_t OFF_XZC   = OFF_H + SZ_H;
static constexpr size_t OFF_XIC   = OFF_XZC + SZ_XZC;
static constexpr size_t OFF_XDBLC = OFF_XIC + SZ_XIC;
static constexpr size_t OFF_XPCP  = OFF_XDBLC + SZ_XDBLC;
static constexpr size_t OFF_DTC   = OFF_XPCP + SZ_XPCP;
static constexpr size_t OFF_YC    = OFF_DTC + SZ_DTC;
static constexpr size_t OFF_OUTP  = OFF_YC + SZ_YC;
static constexpr size_t SCRATCH_TOTAL = OFF_OUTP + SZ_OUTP;

__device__ float g_scratch[SCRATCH_TOTAL];
__device__ int   g_ind[B_ * N_];
__device__ float g_vtop[B_ * N_];

// ---------------- helpers ----------------
__device__ __forceinline__ float siluf(float x) { return x / (1.f + __expf(-x)); }
__device__ __forceinline__ float softplusf(float x) {
    return x > 20.f ? x : log1pf(__expf(x));
}
static inline int ceil_div(int a, int b) { return (a + b - 1) / b; }

__device__ __forceinline__ void ldsm_x4(uint32_t (&r)[4], uint32_t addr) {
    asm volatile("ldmatrix.sync.aligned.m8n8.x4.shared.b16 {%0,%1,%2,%3}, [%4];"
                 : "=r"(r[0]), "=r"(r[1]), "=r"(r[2]), "=r"(r[3]) : "r"(addr));
}
__device__ __forceinline__ void ldsm_x4_t(uint32_t (&r)[4], uint32_t addr) {
    asm volatile("ldmatrix.sync.aligned.m8n8.x4.trans.shared.b16 {%0,%1,%2,%3}, [%4];"
                 : "=r"(r[0]), "=r"(r[1]), "=r"(r[2]), "=r"(r[3]) : "r"(addr));
}
__device__ __forceinline__ void mma_bf16(float (&d)[4], const uint32_t (&a)[4],
                                         uint32_t b0, uint32_t b1) {
    asm volatile("mma.sync.aligned.m16n8k16.row.col.f32.bf16.bf16.f32 "
                 "{%0,%1,%2,%3}, {%4,%5,%6,%7}, {%8,%9}, {%0,%1,%2,%3};"
                 : "+f"(d[0]), "+f"(d[1]), "+f"(d[2]), "+f"(d[3])
                 : "r"(a[0]), "r"(a[1]), "r"(a[2]), "r"(a[3]), "r"(b0), "r"(b1));
}
__device__ __forceinline__ void split_bf(float v, __nv_bfloat16& h, __nv_bfloat16& l) {
    h = __float2bfloat16(v);
    l = __float2bfloat16(v - __bfloat162float(h));
}

// ================= tensor-core GEMM (bf16x3): C = A @ B, NN =================
// Block tile 128x128xK32, 256 threads (8 warps, 64x32 warp tiles).
// AMODE: 0 plain NN; 1 A *= silu(Z) (Zp/ldz); 3 A transposed-batched read:
//        A(m,k) at A[(m>>10)*atrB + k*atrL + (m&1023)]  (ldz := atrL, asum := atrB)
// EPI: softplus(acc + bias[n]).
// VECA/VECB: float4 gmem loads are legal (ld % 4 == 0, base 16B-aligned).
static constexpr int SA_STAGE = 128 * 40;
static constexpr int SB_STAGE = 32 * 136;
static constexpr int TC_AHI = 0;
static constexpr int TC_ALO = 2 * SA_STAGE;
static constexpr int TC_BHI = 4 * SA_STAGE;
static constexpr int TC_BLO = TC_BHI + 2 * SB_STAGE;
static constexpr int TC_SMEM_ELEMS = TC_BLO + 2 * SB_STAGE;
static constexpr int TC_SMEM_BYTES = TC_SMEM_ELEMS * 2;   // 75776

template<int AMODE, bool EPI, bool VECA, bool VECB>
__global__ __launch_bounds__(256, 1) void gemm_tc(
    const float* __restrict__ A, int lda,
    const float* __restrict__ Bp, int ldb,
    float* __restrict__ C, int ldc,
    int M, int N, int Ktot, int splitk,
    size_t batchA, size_t batchB, size_t batchC, size_t strideS,
    const float* __restrict__ Zp, int ldz,
    size_t asum, const float* __restrict__ bias)
{
    extern __shared__ __align__(16) __nv_bfloat16 smem_tc[];

    const int tid  = threadIdx.x;
    const int lane = tid & 31;
    const int wid  = tid >> 5;
    const int wm   = (wid & 1) << 6;
    const int wn   = (wid >> 1) << 5;
    const int row0 = blockIdx.y * 128;
    const int col0 = blockIdx.x * 128;

    const int z = blockIdx.z;
    const int bb = z / splitk;
    const int s  = z - bb * splitk;
    const float* Ab = A + (size_t)bb * batchA;
    const float* Bb = Bp + (size_t)bb * batchB;
    float*       Cb = C + (size_t)bb * batchC + (size_t)s * strideS;
    const int kchunk = Ktot / splitk;
    const int kbeg = s * kchunk;
    const int kend = (s == splitk - 1) ? Ktot : kbeg + kchunk;

    const uint32_t sbase = (uint32_t)__cvta_generic_to_shared(smem_tc);

    const int ar = lane & 15;
    const int ac = (lane >> 4) << 3;
    const int br = (lane & 7) + ((lane >> 3) & 1) * 8;
    const int bc = (lane >> 4) << 3;

    float acc[4][4][4];
#pragma unroll
    for (int i = 0; i < 4; i++)
#pragma unroll
        for (int j = 0; j < 4; j++)
#pragma unroll
            for (int q = 0; q < 4; q++) acc[i][j][q] = 0.f;

    float4 ra4[4], rb4[4];

#define TC_LOADG(K0)                                                             \
    _Pragma("unroll")                                                            \
    for (int p = 0; p < 4; p++) {                                                \
        int idx = tid + p * 256;                                                 \
        float4 v = make_float4(0.f, 0.f, 0.f, 0.f);                              \
        if (AMODE == 3) {                                                        \
            int am4 = (idx & 31) * 4, ak = idx >> 5;                             \
            int gm = row0 + am4, gk = (K0) + ak;                                 \
            if (gm < M && gk < kend) {                                           \
                size_t aoff = (size_t)(gm >> 10) * asum + (size_t)gk * ldz       \
                            + (gm & 1023);                                       \
                v = *(const float4*)(Ab + aoff);                                 \
            }                                                                    \
        } else {                                                                 \
            int am = idx >> 3, ak4 = (idx & 7) * 4;                              \
            int gm = row0 + am, gk = (K0) + ak4;                                 \
            if (gm < M) {                                                        \
                size_t aoff = (size_t)gm * lda + gk;                             \
                if (VECA && gk + 3 < kend) {                                     \
                    v = *(const float4*)(Ab + aoff);                             \
                } else {                                                         \
                    if (gk     < kend) v.x = Ab[aoff];                           \
                    if (gk + 1 < kend) v.y = Ab[aoff + 1];                       \
                    if (gk + 2 < kend) v.z = Ab[aoff + 2];                       \
                    if (gk + 3 < kend) v.w = Ab[aoff + 3];                       \
                }                                                                \
                if (AMODE == 1) {                                                \
                    size_t zoff = (size_t)gm * ldz + gk;                         \
                    float4 zv = make_float4(0.f, 0.f, 0.f, 0.f);                 \
                    if (VECA && gk + 3 < kend) {                                 \
                        zv = *(const float4*)(Zp + zoff);                        \
                    } else {                                                     \
                        if (gk     < kend) zv.x = Zp[zoff];                      \
                        if (gk + 1 < kend) zv.y = Zp[zoff + 1];                  \
                        if (gk + 2 < kend) zv.z = Zp[zoff + 2];                  \
                        if (gk + 3 < kend) zv.w = Zp[zoff + 3];                  \
                    }                                                            \
                    v.x *= siluf(zv.x); v.y *= siluf(zv.y);                      \
                    v.z *= siluf(zv.z); v.w *= siluf(zv.w);                      \
                }                                                                \
            }                                                                    \
        }                                                                        \
        ra4[p] = v;                                                              \
        int bk = idx >> 5, bn4 = (idx & 31) * 4;                                 \
        int gk2 = (K0) + bk, gn = col0 + bn4;                                    \
        float4 w = make_float4(0.f, 0.f, 0.f, 0.f);                             \
        if (gk2 < kend) {                                                        \
            size_t boff = (size_t)gk2 * ldb + gn;                                \
            if (VECB && gn + 3 < N) {                                            \
                w = *(const float4*)(Bb + boff);                                 \
            } else {                                                             \
                if (gn     < N) w.x = Bb[boff];                                  \
                if (gn + 1 < N) w.y = Bb[boff + 1];                              \
                if (gn + 2 < N) w.z = Bb[boff + 2];                              \
                if (gn + 3 < N) w.w = Bb[boff + 3];                              \
            }                                                                    \
        }                                                                        \
        rb4[p] = w;                                                              \
    }

#define TC_STORES(BUF)                                                           \
    _Pragma("unroll")                                                            \
    for (int p = 0; p < 4; p++) {                                                \
        int idx = tid + p * 256;                                                 \
        __nv_bfloat16 h0, h1, h2, h3, l0, l1, l2, l3;                            \
        split_bf(ra4[p].x, h0, l0); split_bf(ra4[p].y, h1, l1);                  \
        split_bf(ra4[p].z, h2, l2); split_bf(ra4[p].w, h3, l3);                  \
        if (AMODE == 3) {                                                        \
            int am4 = (idx & 31) * 4, ak = idx >> 5;                             \
            int o = (BUF) * SA_STAGE + am4 * 40 + ak;                            \
            smem_tc[TC_AHI + o]       = h0; smem_tc[TC_ALO + o]       = l0;      \
            smem_tc[TC_AHI + o + 40]  = h1; smem_tc[TC_ALO + o + 40]  = l1;      \
            smem_tc[TC_AHI + o + 80]  = h2; smem_tc[TC_ALO + o + 80]  = l2;      \
            smem_tc[TC_AHI + o + 120] = h3; smem_tc[TC_ALO + o + 120] = l3;      \
        } else {                                                                 \
            int am = idx >> 3, ak4 = (idx & 7) * 4;                              \
            int o = (BUF) * SA_STAGE + am * 40 + ak4;                            \
            __nv_bfloat162 t;                                                    \
            t.x = h0; t.y = h1;                                                  \
            *(__nv_bfloat162*)&smem_tc[TC_AHI + o] = t;                          \
            t.x = h2; t.y = h3;                                                  \
            *(__nv_bfloat162*)&smem_tc[TC_AHI + o + 2] = t;                      \
            t.x = l0; t.y = l1;                                                  \
            *(__nv_bfloat162*)&smem_tc[TC_ALO + o] = t;                          \
            t.x = l2; t.y = l3;                                                  \
            *(__nv_bfloat162*)&smem_tc[TC_ALO + o + 2] = t;                      \
        }                                                                        \
        split_bf(rb4[p].x, h0, l0); split_bf(rb4[p].y, h1, l1);                  \
        split_bf(rb4[p].z, h2, l2); split_bf(rb4[p].w, h3, l3);                  \
        int bk = idx >> 5, bn4 = (idx & 31) * 4;                                 \
        int ob = (BUF) * SB_STAGE + bk * 136 + bn4;                              \
        __nv_bfloat162 u;                                                        \
        u.x = h0; u.y = h1;                                                      \
        *(__nv_bfloat162*)&smem_tc[TC_BHI + ob] = u;                             \
        u.x = h2; u.y = h3;                                                      \
        *(__nv_bfloat162*)&smem_tc[TC_BHI + ob + 2] = u;                         \
        u.x = l0; u.y = l1;                                                      \
        *(__nv_bfloat162*)&smem_tc[TC_BLO + ob] = u;                             \
        u.x = l2; u.y = l3;                                                      \
        *(__nv_bfloat162*)&smem_tc[TC_BLO + ob + 2] = u;                         \
    }

    TC_LOADG(kbeg);
    TC_STORES(0);
    __syncthreads();

    int buf = 0;
    for (int k0 = kbeg; k0 < kend; k0 += 32) {
        const bool more = (k0 + 32) < kend;
        if (more) { TC_LOADG(k0 + 32); }

        const uint32_t sa_hi = sbase + (TC_AHI + buf * SA_STAGE) * 2;
        const uint32_t sa_lo = sbase + (TC_ALO + buf * SA_STAGE) * 2;
        const uint32_t sb_hi = sbase + (TC_BHI + buf * SB_STAGE) * 2;
        const uint32_t sb_lo = sbase + (TC_BLO + buf * SB_STAGE) * 2;

#pragma unroll
        for (int sub = 0; sub < 2; sub++) {
            const int kk0 = sub * 16;
            uint32_t ah[4][4], al[4][4], bh[2][4], bl[2][4];
#pragma unroll
            for (int i = 0; i < 4; i++) {
                uint32_t off = ((wm + i * 16 + ar) * 40 + kk0 + ac) * 2;
                ldsm_x4(ah[i], sa_hi + off);
                ldsm_x4(al[i], sa_lo + off);
            }
#pragma unroll
            for (int g = 0; g < 2; g++) {
                uint32_t off = ((kk0 + br) * 136 + wn + g * 16 + bc) * 2;
                ldsm_x4_t(bh[g], sb_hi + off);
                ldsm_x4_t(bl[g], sb_lo + off);
            }
#pragma unroll
            for (int i = 0; i < 4; i++)
#pragma unroll
                for (int j = 0; j < 4; j++) {
                    const int g = j >> 1, t = (j & 1) * 2;
                    mma_bf16(acc[i][j], ah[i], bh[g][t], bh[g][t + 1]);
                    mma_bf16(acc[i][j], ah[i], bl[g][t], bl[g][t + 1]);
                    mma_bf16(acc[i][j], al[i], bh[g][t], bh[g][t + 1]);
                }
        }

        if (more) { TC_STORES(buf ^ 1); }
        __syncthreads();
        buf ^= 1;
    }

    const int er = lane >> 2;
    const int ec = (lane & 3) * 2;
#pragma unroll
    for (int i = 0; i < 4; i++) {
#pragma unroll
        for (int j = 0; j < 4; j++) {
            int gm0 = row0 + wm + i * 16 + er;
            int gn  = col0 + wn + j * 8 + ec;
            if (gn >= N) continue;
            float v0 = acc[i][j][0], v1 = acc[i][j][1];
            float v2 = acc[i][j][2], v3 = acc[i][j][3];
            if (EPI) {
                float b0 = bias[gn];
                float b1 = (gn + 1 < N) ? bias[gn + 1] : 0.f;
                v0 = softplusf(v0 + b0); v1 = softplusf(v1 + b1);
                v2 = softplusf(v2 + b0); v3 = softplusf(v3 + b1);
            }
            if (gm0 < M) {
                Cb[(size_t)gm0 * ldc + gn] = v0;
                if (gn + 1 < N) Cb[(size_t)gm0 * ldc + gn + 1] = v1;
            }
            int gm1 = gm0 + 8;
            if (gm1 < M) {
                Cb[(size_t)gm1 * ldc + gn] = v2;
                if (gn + 1 < N) Cb[(size_t)gm1 * ldc + gn + 1] = v3;
            }
        }
    }
#undef TC_LOADG
#undef TC_STORES
}

// ---------------- fixed-order split-K reduction ----------------
__global__ void reduce_sum_kernel(const float* __restrict__ part, float* __restrict__ out,
                                  int total, size_t stride, int ns)
{
    int i = blockIdx.x * blockDim.x + threadIdx.x;
    if (i >= total) return;
    float a = 0.f;
    for (int s = 0; s < ns; s++) a += part[(size_t)s * stride + i];
    out[i] = a;
}

// ---------------- depthwise causal conv (k=4) + silu ----------------
__global__ void conv_silu_kernel(const float* __restrict__ xz, int ldxz,
                                 const float* __restrict__ w, const float* __restrict__ bias,
                                 float* __restrict__ xi, int Bn, int L, int dinner)
{
    int idx = blockIdx.x * blockDim.x + threadIdx.x;
    int total = Bn * L * dinner;
    if (idx >= total) return;
    int ch = idx % dinner;
    int l  = (idx / dinner) % L;
    int b  = idx / (dinner * L);
    const float* x0 = xz + (size_t)(b * L) * ldxz + ch;
    float acc = bias[ch];
    float w0 = w[ch * 4 + 0], w1 = w[ch * 4 + 1], w2 = w[ch * 4 + 2], w3 = w[ch * 4 + 3];
    if (l >= 3) acc = fmaf(w0, x0[(size_t)(l - 3) * ldxz], acc);
    if (l >= 2) acc = fmaf(w1, x0[(size_t)(l - 2) * ldxz], acc);
    if (l >= 1) acc = fmaf(w2, x0[(size_t)(l - 1) * ldxz], acc);
    acc = fmaf(w3, x0[(size_t)l * ldxz], acc);
    xi[idx] = siluf(acc);
}

// ---------------- selective scan, TCH-step chunks, double-buffered ----------------
template<int TCH>
__global__ void scan_kernel(const float* __restrict__ u, const float* __restrict__ dt,
                            const float* __restrict__ xdbl, int ld_dbl, int boff, int coff,
                            const float* __restrict__ A_log, const float* __restrict__ Dp,
                            float* __restrict__ y, int Bn, int L, int dinner)
{
    int gwarp = (blockIdx.x * blockDim.x + threadIdx.x) >> 5;
    int lane  = threadIdx.x & 31;
    int half  = lane >> 4;
    int n     = lane & 15;
    int gd    = gwarp * 2 + half;
    if (gd >= Bn * dinner) return;
    int b   = gd / dinner;
    int dch = gd - b * dinner;

    float a  = -__expf(A_log[dch * NS + n]);
    float Dv = Dp[dch];
    float h  = 0.f;

    const float* urow  = u    + (size_t)b * L * dinner + dch;
    const float* dtrow = dt   + (size_t)b * L * dinner + dch;
    const float* brow  = xdbl + (size_t)b * L * ld_dbl + boff + n;
    const float* crow  = xdbl + (size_t)b * L * ld_dbl + coff + n;
    float*       yrow  = y    + (size_t)b * L * dinner + dch;

    float vdt[2][TCH], vu[2][TCH], vB[2][TCH], vC[2][TCH];

#define SCAN_LOAD(BUF, T0)                                                      \
    _Pragma("unroll")                                                           \
    for (int tt = 0; tt < TCH; tt++) {                                          \
        size_t t = (size_t)((T0) + tt);                                         \
        vdt[BUF][tt] = dtrow[t * dinner];                                       \
        vu[BUF][tt]  = urow[t * dinner];                                        \
        vB[BUF][tt]  = brow[t * ld_dbl];                                        \
        vC[BUF][tt]  = crow[t * ld_dbl];                                        \
    }

#define SCAN_COMPUTE(BUF, T0)                                                   \
    {                                                                           \
        float p[TCH];                                                           \
        _Pragma("unroll")                                                       \
        for (int tt = 0; tt < TCH; tt++) {                                      \
            float dA = __expf(vdt[BUF][tt] * a);                                \
            h = fmaf(dA, h, vdt[BUF][tt] * vB[BUF][tt] * vu[BUF][tt]);          \
            p[tt] = h * vC[BUF][tt] + ((n == 0) ? vu[BUF][tt] * Dv : 0.f);      \
        }                                                                       \
        _Pragma("unroll")                                                       \
        for (int tt = 0; tt < TCH; tt++) p[tt] += __shfl_xor_sync(0xffffffffu, p[tt], 8); \
        _Pragma("unroll")                                                       \
        for (int tt = 0; tt < TCH; tt++) p[tt] += __shfl_xor_sync(0xffffffffu, p[tt], 4); \
        _Pragma("unroll")                                                       \
        for (int tt = 0; tt < TCH; tt++) p[tt] += __shfl_xor_sync(0xffffffffu, p[tt], 2); \
        _Pragma("unroll")                                                       \
        for (int tt = 0; tt < TCH; tt++) p[tt] += __shfl_xor_sync(0xffffffffu, p[tt], 1); \
        _Pragma("unroll")                                                       \
        for (int tt = 0; tt < TCH; tt++)                                        \
            if (n == tt) yrow[(size_t)((T0) + tt) * dinner] = p[tt];            \
    }

    const int nch = L / TCH;   // even for both uses
    SCAN_LOAD(0, 0);
    for (int c = 0; c < nch; c += 2) {
        if (c + 1 < nch) SCAN_LOAD(1, (c + 1) * TCH);
        SCAN_COMPUTE(0, c * TCH);
        if (c + 1 < nch) {
            if (c + 2 < nch) SCAN_LOAD(0, (c + 2) * TCH);
            SCAN_COMPUTE(1, (c + 1) * TCH);
        }
    }
#undef SCAN_LOAD
#undef SCAN_COMPUTE
}

// ---------------- mean over N_ : one warp per row ----------------
__global__ void mean_kernel(const float* __restrict__ sc2, float* __restrict__ sbuf)
{
    int gw = (blockIdx.x * blockDim.x + threadIdx.x) >> 5;
    int lane = threadIdx.x & 31;
    if (gw >= B_ * K_) return;
    const float* row = sc2 + (size_t)gw * N_;
    float a = 0.f;
    for (int i = lane; i < N_; i += 32) a += row[i];
#pragma unroll
    for (int o = 16; o; o >>= 1) a += __shfl_xor_sync(0xffffffffu, a, o);
    if (lane == 0) sbuf[gw] = a / (float)N_;
}

// ---------------- softmax over K_ per batch (in-place, 1024 threads) ----------------
__global__ void softmax_kernel(float* __restrict__ s)
{
    __shared__ float red[32];
    int b = blockIdx.x, tid = threadIdx.x;
    int lane = tid & 31, w = tid >> 5;
    float v = s[(size_t)b * K_ + tid];
    float m = v;
#pragma unroll
    for (int o = 16; o; o >>= 1) m = fmaxf(m, __shfl_xor_sync(0xffffffffu, m, o));
    if (lane == 0) red[w] = m;
    __syncthreads();
    if (tid < 32) {
        float t = red[tid];
#pragma unroll
        for (int o = 16; o; o >>= 1) t = fmaxf(t, __shfl_xor_sync(0xffffffffu, t, o));
        if (tid == 0) red[0] = t;
    }
    __syncthreads();
    m = red[0];
    __syncthreads();
    float e = __expf(v - m);
    float sum = e;
#pragma unroll
    for (int o = 16; o; o >>= 1) sum += __shfl_xor_sync(0xffffffffu, sum, o);
    if (lane == 0) red[w] = sum;
    __syncthreads();
    if (tid < 32) {
        float t = red[tid];
#pragma unroll
        for (int o = 16; o; o >>= 1) t += __shfl_xor_sync(0xffffffffu, t, o);
        if (tid == 0) red[0] = t;
    }
    __syncthreads();
    s[(size_t)b * K_ + tid] = e / red[0];
}

// ---------------- top-k(98 of 1024) bitonic (desc value, asc index ties) ----------------
__global__ void topk_kernel(const float* __restrict__ s, int* __restrict__ ind,
                            float* __restrict__ vtop)
{
    __shared__ float sv[K_];
    __shared__ int   si[K_];
    int b = blockIdx.x, tid = threadIdx.x;
    for (int i = tid; i < K_; i += 256) { sv[i] = s[(size_t)b * K_ + i]; si[i] = i; }
    __syncthreads();
    for (int k = 2; k <= K_; k <<= 1) {
        for (int j = k >> 1; j > 0; j >>= 1) {
            for (int i = tid; i < K_; i += 256) {
                int ixj = i ^ j;
                if (ixj > i) {
                    float v1 = sv[i], v2 = sv[ixj];
                    int   i1 = si[i], i2 = si[ixj];
                    bool lt_ji = (v2 > v1) || (v2 == v1 && i2 < i1);
                    bool lt_ij = (v1 > v2) || (v1 == v2 && i1 < i2);
                    bool asc = ((i & k) == 0);
                    if (asc ? lt_ji : lt_ij) {
                        sv[i] = v2; sv[ixj] = v1;
                        si[i] = i2; si[ixj] = i1;
                    }
                }
            }
            __syncthreads();
        }
    }
    for (int i = tid; i < N_; i += 256) {
        ind[b * N_ + i]  = si[i];
        vtop[b * N_ + i] = sv[i];
    }
}

// ---------------- h = imageFeature + gather(kf, ind) * vtop ----------------
__global__ void build_h_kernel(const float* __restrict__ imf, const float* __restrict__ kf,
                               const int* __restrict__ ind, const float* __restrict__ vtop,
                               float* __restrict__ h)
{
    int idx = blockIdx.x * blockDim.x + threadIdx.x;
    int total = B_ * LC * DM_;
    if (idx >= total) return;
    int d = idx % DM_;
    int j = (idx / DM_) % LC;
    int b = idx / (DM_ * LC);
    int r = ind[b * N_ + j];
    h[idx] = imf[(size_t)j * DM_ + d] +
             kf[((size_t)b * DM_ + d) * K_ + r] * vtop[b * N_ + j];
}

// ---------------- host ----------------
extern "C" void kernel_launch(void* const* d_in, const int* in_sizes, int n_in,
                              void* d_out, int out_size)
{
    const float* imf      = (const float*)d_in[0];
    const float* kf       = (const float*)d_in[1];
    const float* a_in_w   = (const float*)d_in[2];
    const float* a_conv_w = (const float*)d_in[3];
    const float* a_conv_b = (const float*)d_in[4];
    const float* a_xproj_w= (const float*)d_in[5];
    const float* a_dt_w   = (const float*)d_in[6];
    const float* a_dt_b   = (const float*)d_in[7];
    const float* a_A_log  = (const float*)d_in[8];
    const float* a_D      = (const float*)d_in[9];
    const float* a_out_w  = (const float*)d_in[10];
    const float* c_in_w   = (const float*)d_in[11];
    const float* c_conv_w = (const float*)d_in[12];
    const float* c_conv_b = (const float*)d_in[13];
    const float* c_xproj_w= (const float*)d_in[14];
    const float* c_dt_w   = (const float*)d_in[15];
    const float* c_dt_b   = (const float*)d_in[16];
    const float* c_A_log  = (const float*)d_in[17];
    const float* c_D      = (const float*)d_in[18];
    const float* c_out_w  = (const float*)d_in[19];
    float* out = (float*)d_out;

    static bool attr_done = false;
    if (!attr_done) {
        cudaFuncSetAttribute((const void*)gemm_tc<0, false, true,  true >, cudaFuncAttributeMaxDynamicSharedMemorySize, TC_SMEM_BYTES);
        cudaFuncSetAttribute((const void*)gemm_tc<3, false, true,  true >, cudaFuncAttributeMaxDynamicSharedMemorySize, TC_SMEM_BYTES);
        cudaFuncSetAttribute((const void*)gemm_tc<0, false, true,  false>, cudaFuncAttributeMaxDynamicSharedMemorySize, TC_SMEM_BYTES);
        cudaFuncSetAttribute((const void*)gemm_tc<0, true,  false, true >, cudaFuncAttributeMaxDynamicSharedMemorySize, TC_SMEM_BYTES);
        cudaFuncSetAttribute((const void*)gemm_tc<1, false, true,  false>, cudaFuncAttributeMaxDynamicSharedMemorySize, TC_SMEM_BYTES);
        cudaFuncSetAttribute((const void*)gemm_tc<0, true,  true,  true >, cudaFuncAttributeMaxDynamicSharedMemorySize, TC_SMEM_BYTES);
        cudaFuncSetAttribute((const void*)gemm_tc<1, false, true,  true >, cudaFuncAttributeMaxDynamicSharedMemorySize, TC_SMEM_BYTES);
        attr_done = true;
    }

    float* sc = nullptr;
    cudaGetSymbolAddress((void**)&sc, g_scratch);
    int*   p_ind  = nullptr;
    float* p_vtop = nullptr;
    cudaGetSymbolAddress((void**)&p_ind, g_ind);
    cudaGetSymbolAddress((void**)&p_vtop, g_vtop);

    float* sctp   = sc + OFF_SCTP;
    float* sct    = sc + OFF_SCT;
    float* xza    = sc + OFF_XZA;
    float* xia    = sc + OFF_XIA;
    float* xdbla  = sc + OFF_XDBLA;
    float* dta    = sc + OFF_DTA;
    float* ya     = sc + OFF_YA;
    float* sc2    = sc + OFF_SC2;
    float* sbuf   = sc + OFF_S;
    float* hbuf   = sc + OFF_H;
    float* xzc    = sc + OFF_XZC;
    float* xic    = sc + OFF_XIC;
    float* xdblc  = sc + OFF_XDBLC;
    float* xpcp   = sc + OFF_XPCP;
    float* dtc    = sc + OFF_DTC;
    float* yc     = sc + OFF_YC;
    float* outp   = sc + OFF_OUTP;

    const int Ma = B_ * K_;   // 8192
    const int Mc = B_ * LC;   // 784

    // 0: scoreT partials = imf @ kf[b]  (TC, batched over b, split-K=2)
    //    C[b][n][l], M=98, N=1024, K=2048
    gemm_tc<0, false, true, true><<<dim3(K_ / 128, 1, B_ * SPLITK_SCT), 256, TC_SMEM_BYTES>>>(
        imf, DM_, kf, K_, sctp, K_, N_, K_, DM_, SPLITK_SCT,
        0, (size_t)DM_ * K_, (size_t)N_ * K_, SZ_SCT1,
        nullptr, 0, 0, nullptr);

    // 0b: reduce 2 partials -> scoreT
    reduce_sum_kernel<<<ceil_div((int)SZ_SCT1, 256), 256>>>(
        sctp, sct, (int)SZ_SCT1, SZ_SCT1, SPLITK_SCT);

    // 1: xza = score @ a_in_w  (AMODE=3: read scoreT transposed, coalesced)
    gemm_tc<3, false, true, true><<<dim3(ceil_div(2 * DIA, 128), Ma / 128, 1), 256, TC_SMEM_BYTES>>>(
        sct, 0, a_in_w, 2 * DIA, xza, 2 * DIA, Ma, 2 * DIA, N_, 1,
        0, 0, 0, 0, nullptr, K_, (size_t)N_ * K_, nullptr);

    // 2: conv + silu (a)
    conv_silu_kernel<<<ceil_div(B_ * LA * DIA, 256), 256>>>(
        xza, 2 * DIA, a_conv_w, a_conv_b, xia, B_, LA, DIA);

    // 3: x_dbl = xi @ a_xproj_w   (ldb=39 unaligned -> scalar B)
    gemm_tc<0, false, true, false><<<dim3(1, Ma / 128, 1), 256, TC_SMEM_BYTES>>>(
        xia, DIA, a_xproj_w, LDBA, xdbla, LDBA, Ma, LDBA, DIA, 1,
        0, 0, 0, 0, nullptr, 0, 0, nullptr);

    // 4: dt = softplus(xdbl[:, :7] @ a_dt_w + b)  (lda=39 unaligned -> scalar A)
    gemm_tc<0, true, false, true><<<dim3(ceil_div(DIA, 128), Ma / 128, 1), 256, TC_SMEM_BYTES>>>(
        xdbla, LDBA, a_dt_w, DIA, dta, DIA, Ma, DIA, DRA, 1,
        0, 0, 0, 0, nullptr, 0, 0, a_dt_b);

    // 5: selective scan (a)
    scan_kernel<8><<<(B_ * DIA / 2 * 32) / 256, 256>>>(
        xia, dta, xdbla, LDBA, DRA, DRA + NS, a_A_log, a_D, ya, B_, LA, DIA);

    // 6: sc2 = (y * silu(z)) @ a_out_w  (ldb=98 unaligned -> scalar B)
    gemm_tc<1, false, true, false><<<dim3(1, Ma / 128, 1), 256, TC_SMEM_BYTES>>>(
        ya, DIA, a_out_w, N_, sc2, N_, Ma, N_, DIA, 1,
        0, 0, 0, 0, xza + DIA, 2 * DIA, 0, nullptr);

    // 7-10: mean / softmax / topk / gather
    mean_kernel<<<(B_ * K_ * 32) / 256, 256>>>(sc2, sbuf);
    softmax_kernel<<<B_, K_>>>(sbuf);
    topk_kernel<<<B_, 256>>>(sbuf, p_ind, p_vtop);
    build_h_kernel<<<ceil_div(B_ * LC * DM_, 256), 256>>>(imf, kf, p_ind, p_vtop, hbuf);

    // 11: xzc = h @ c_in_w
    gemm_tc<0, false, true, true><<<dim3((2 * DIC) / 128, ceil_div(Mc, 128), 1), 256, TC_SMEM_BYTES>>>(
        hbuf, DM_, c_in_w, 2 * DIC, xzc, 2 * DIC, Mc, 2 * DIC, DM_, 1,
        0, 0, 0, 0, nullptr, 0, 0, nullptr);

    // 12: conv + silu (c)
    conv_silu_kernel<<<ceil_div(B_ * LC * DIC, 256), 256>>>(
        xzc, 2 * DIC, c_conv_w, c_conv_b, xic, B_, LC, DIC);

    // 13: x_dbl partials = xi @ c_xproj_w (split-K=8)
    gemm_tc<0, false, true, true><<<dim3(ceil_div(LDBC, 128), ceil_div(Mc, 128), SPLITK_XPC), 256, TC_SMEM_BYTES>>>(
        xic, DIC, c_xproj_w, LDBC, xpcp, LDBC, Mc, LDBC, DIC, SPLITK_XPC,
        0, 0, 0, (size_t)Mc * LDBC, nullptr, 0, 0, nullptr);

    // 14: reduce -> xdblc
    reduce_sum_kernel<<<ceil_div(Mc * LDBC, 256), 256>>>(
        xpcp, xdblc, Mc * LDBC, (size_t)Mc * LDBC, SPLITK_XPC);

    // 15: dt = softplus(xdbl[:, :128] @ c_dt_w + b)
    gemm_tc<0, true, true, true><<<dim3(DIC / 128, ceil_div(Mc, 128), 1), 256, TC_SMEM_BYTES>>>(
        xdblc, LDBC, c_dt_w, DIC, dtc, DIC, Mc, DIC, DRC, 1,
        0, 0, 0, 0, nullptr, 0, 0, c_dt_b);

    // 16: selective scan (c)
    scan_kernel<7><<<(B_ * DIC / 2 * 32) / 256, 256>>>(
        xic, dtc, xdblc, LDBC, DRC, DRC + NS, c_A_log, c_D, yc, B_, LC, DIC);

    // 17: out partials = (y * silu(z)) @ c_out_w (split-K=2)
    gemm_tc<1, false, true, true><<<dim3(DM_ / 128, ceil_div(Mc, 128), SPLITK_COUT), 256, TC_SMEM_BYTES>>>(
        yc, DIC, c_out_w, DM_, outp, DM_, Mc, DM_, DIC, SPLITK_COUT,
        0, 0, 0, (size_t)Mc * DM_, xzc + DIC, 2 * DIC, 0, nullptr);

    // 18: reduce -> out
    reduce_sum_kernel<<<ceil_div(Mc * DM_, 256), 256>>>(
        outp, out, Mc * DM_, (size_t)Mc * DM_, SPLITK_COUT);
}

// round 6
// speedup vs baseline: 2.7272x; 1.2422x over previous
#include <cuda_runtime.h>
#include <cuda_bf16.h>
#include <math.h>
#include <stdint.h>

// ---------------- problem constants ----------------
static constexpr int B_  = 8;
static constexpr int K_  = 1024;
static constexpr int N_  = 98;
static constexpr int DM_ = 2048;
static constexpr int DIA = 196;
static constexpr int DRA = 7;
static constexpr int DIC = 4096;
static constexpr int DRC = 128;
static constexpr int NS  = 16;
static constexpr int LA  = 1024;
static constexpr int LC  = 98;
static constexpr int LDBA = DRA + 2 * NS;   // 39
static constexpr int LDBC = DRC + 2 * NS;   // 160

static constexpr int SPLITK_SC   = 2;
static constexpr int SPLITK_XPC  = 8;
static constexpr int SPLITK_COUT = 2;

// ---------------- fp32 scratch arena ----------------
static constexpr size_t SZ_SC1   = (size_t)B_ * K_ * N_;
static constexpr size_t SZ_SCP   = (size_t)SPLITK_SC * SZ_SC1;
static constexpr size_t SZ_XZA   = (size_t)B_ * K_ * 2 * DIA;
static constexpr size_t SZ_XIA   = (size_t)B_ * K_ * DIA;
static constexpr size_t SZ_XDBLA = (size_t)B_ * K_ * LDBA;
static constexpr size_t SZ_DTA   = (size_t)B_ * K_ * DIA;
static constexpr size_t SZ_YA    = (size_t)B_ * K_ * DIA;
static constexpr size_t SZ_SC2   = (size_t)B_ * K_ * N_;
static constexpr size_t SZ_S     = (size_t)B_ * K_;
static constexpr size_t SZ_H     = (size_t)B_ * LC * DM_;
static constexpr size_t SZ_XZC   = (size_t)B_ * LC * 2 * DIC;
static constexpr size_t SZ_XIC   = (size_t)B_ * LC * DIC;
static constexpr size_t SZ_XDBLC = (size_t)B_ * LC * LDBC;
static constexpr size_t SZ_XPCP  = (size_t)SPLITK_XPC * B_ * LC * LDBC;
static constexpr size_t SZ_DTC   = (size_t)B_ * LC * DIC;
static constexpr size_t SZ_YC    = (size_t)B_ * LC * DIC;
static constexpr size_t SZ_OUTP  = (size_t)SPLITK_COUT * B_ * LC * DM_;

static constexpr size_t OFF_SCP   = 0;
static constexpr size_t OFF_SC    = OFF_SCP + SZ_SCP;
static constexpr size_t OFF_XZA   = OFF_SC + SZ_SC1;
static constexpr size_t OFF_XIA   = OFF_XZA + SZ_XZA;
static constexpr size_t OFF_XDBLA = OFF_XIA + SZ_XIA;
static constexpr size_t OFF_DTA   = OFF_XDBLA + SZ_XDBLA;
static constexpr size_t OFF_YA    = OFF_DTA + SZ_DTA;
static constexpr size_t OFF_SC2   = OFF_YA + SZ_YA;
static constexpr size_t OFF_S     = OFF_SC2 + SZ_SC2;
static constexpr size_t OFF_H     = OFF_S + SZ_S;
static constexpr size_t OFF_XZC   = OFF_H + SZ_H;
static constexpr size_t OFF_XIC   = OFF_XZC + SZ_XZC;
static constexpr size_t OFF_XDBLC = OFF_XIC + SZ_XIC;
static constexpr size_t OFF_XPCP  = OFF_XDBLC + SZ_XDBLC;
static constexpr size_t OFF_DTC   = OFF_XPCP + SZ_XPCP;
static constexpr size_t OFF_YC    = OFF_DTC + SZ_DTC;
static constexpr size_t OFF_OUTP  = OFF_YC + SZ_YC;
static constexpr size_t SCRATCH_TOTAL = OFF_OUTP + SZ_OUTP;

__device__ float g_scratch[SCRATCH_TOTAL];
__device__ int   g_ind[B_ * N_];
__device__ float g_vtop[B_ * N_];

// ---------------- bf16 hi/lo plane arena (u16) ----------------
static constexpr size_t BSZ_KFT   = (size_t)B_ * K_ * DM_;     // [b][l][d]
static constexpr size_t BSZ_IMF   = (size_t)N_ * DM_;          // [n][d]
static constexpr size_t BSZ_CINW  = (size_t)(2 * DIC) * DM_;   // [n][k]
static constexpr size_t BSZ_COUTW = (size_t)DM_ * DIC;         // [n][k]
static constexpr size_t BSZ_H     = (size_t)B_ * LC * DM_;
static constexpr size_t BSZ_Y     = (size_t)B_ * LC * DIC;

static constexpr size_t BO_KFT_HI   = 0;
static constexpr size_t BO_KFT_LO   = BO_KFT_HI + BSZ_KFT;
static constexpr size_t BO_IMF_HI   = BO_KFT_LO + BSZ_KFT;
static constexpr size_t BO_IMF_LO   = BO_IMF_HI + BSZ_IMF;
static constexpr size_t BO_CINW_HI  = BO_IMF_LO + BSZ_IMF;
static constexpr size_t BO_CINW_LO  = BO_CINW_HI + BSZ_CINW;
static constexpr size_t BO_COUTW_HI = BO_CINW_LO + BSZ_CINW;
static constexpr size_t BO_COUTW_LO = BO_COUTW_HI + BSZ_COUTW;
static constexpr size_t BO_H_HI     = BO_COUTW_LO + BSZ_COUTW;
static constexpr size_t BO_H_LO     = BO_H_HI + BSZ_H;
static constexpr size_t BO_Y_HI     = BO_H_LO + BSZ_H;
static constexpr size_t BO_Y_LO     = BO_Y_HI + BSZ_Y;
static constexpr size_t BF_TOTAL    = BO_Y_LO + BSZ_Y;

__device__ unsigned short g_bf[BF_TOTAL];

// ---------------- helpers ----------------
__device__ __forceinline__ float siluf(float x) { return x / (1.f + __expf(-x)); }
__device__ __forceinline__ float softplusf(float x) {
    return x > 20.f ? x : log1pf(__expf(x));
}
static inline int ceil_div(int a, int b) { return (a + b - 1) / b; }

__device__ __forceinline__ void ldsm_x4(uint32_t (&r)[4], uint32_t addr) {
    asm volatile("ldmatrix.sync.aligned.m8n8.x4.shared.b16 {%0,%1,%2,%3}, [%4];"
                 : "=r"(r[0]), "=r"(r[1]), "=r"(r[2]), "=r"(r[3]) : "r"(addr));
}
__device__ __forceinline__ void ldsm_x4_t(uint32_t (&r)[4], uint32_t addr) {
    asm volatile("ldmatrix.sync.aligned.m8n8.x4.trans.shared.b16 {%0,%1,%2,%3}, [%4];"
                 : "=r"(r[0]), "=r"(r[1]), "=r"(r[2]), "=r"(r[3]) : "r"(addr));
}
__device__ __forceinline__ void mma_bf16(float (&d)[4], const uint32_t (&a)[4],
                                         uint32_t b0, uint32_t b1) {
    asm volatile("mma.sync.aligned.m16n8k16.row.col.f32.bf16.bf16.f32 "
                 "{%0,%1,%2,%3}, {%4,%5,%6,%7}, {%8,%9}, {%0,%1,%2,%3};"
                 : "+f"(d[0]), "+f"(d[1]), "+f"(d[2]), "+f"(d[3])
                 : "r"(a[0]), "r"(a[1]), "r"(a[2]), "r"(a[3]), "r"(b0), "r"(b1));
}
__device__ __forceinline__ void split_bf(float v, __nv_bfloat16& h, __nv_bfloat16& l) {
    h = __float2bfloat16(v);
    l = __float2bfloat16(v - __bfloat162float(h));
}
__device__ __forceinline__ void cpa16(uint32_t dst, const void* src) {
    asm volatile("cp.async.cg.shared.global [%0], [%1], 16;" :: "r"(dst), "l"(src));
}

// ================================================================
//  gemm_bt:  C[M,N] = A[M,K] @ B[N,K]^T   (pre-split bf16 planes)
//  128x128 tile, K-chunks of 32, cp.async double buffer, 256 thr.
//  Inner loop: cp.async + ldmatrix + mma.sync only.
// ================================================================
static constexpr int BT_PL     = 128 * 40;            // elems per plane (stride 40)
static constexpr int BT_PLB    = BT_PL * 2;           // bytes (10240)
static constexpr int BT_STAGEB = 4 * BT_PLB;          // Ahi,Alo,Bhi,Blo (40960)
static constexpr int BT_SMEM   = 2 * BT_STAGEB;       // 81920 B

__global__ __launch_bounds__(256, 1) void gemm_bt(
    const unsigned short* __restrict__ Ahi, const unsigned short* __restrict__ Alo,
    const unsigned short* __restrict__ Bhi, const unsigned short* __restrict__ Blo,
    float* __restrict__ C, int ldc,
    int M, int N, int Ktot, int splitk,
    size_t batchA, size_t batchB, size_t batchC, size_t strideS)
{
    extern __shared__ __align__(16) unsigned short smem_bt[];
    const uint32_t sb = (uint32_t)__cvta_generic_to_shared(smem_bt);

    const int tid = threadIdx.x, lane = tid & 31, wid = tid >> 5;
    const int wm = (wid & 1) << 6;    // 0/64
    const int wn = (wid >> 1) << 5;   // 0/32/64/96
    const int row0 = blockIdx.y * 128;
    const int col0 = blockIdx.x * 128;

    const int z = blockIdx.z;
    const int bb = z / splitk;
    const int s  = z - bb * splitk;
    const unsigned short* Ah = Ahi + (size_t)bb * batchA;
    const unsigned short* Al = Alo + (size_t)bb * batchA;
    const unsigned short* Bh = Bhi + (size_t)bb * batchB;
    const unsigned short* Bl = Blo + (size_t)bb * batchB;
    float* Cb = C + (size_t)bb * batchC + (size_t)s * strideS;

    const int Kc = Ktot / splitk;
    const int kbeg = s * Kc;
    const int nch = Kc / 32;

    float acc[4][4][4];
#pragma unroll
    for (int i = 0; i < 4; i++)
#pragma unroll
        for (int j = 0; j < 4; j++)
#pragma unroll
            for (int q = 0; q < 4; q++) acc[i][j][q] = 0.f;

#define BT_LOAD(CC, BUF)                                                        \
    {                                                                           \
        const int kc0 = kbeg + (CC) * 32;                                       \
        const uint32_t st = sb + (BUF) * BT_STAGEB;                             \
        _Pragma("unroll")                                                       \
        for (int p = 0; p < 2; p++) {                                           \
            int idx = tid + p * 256;                                            \
            int row = idx >> 2, ch = idx & 3;                                   \
            uint32_t doff = (uint32_t)(row * 80 + ch * 16);                     \
            int ga = row0 + row;                                                \
            if (ga < M) {                                                       \
                size_t ao = (size_t)ga * Ktot + kc0 + ch * 8;                   \
                cpa16(st + doff,          Ah + ao);                             \
                cpa16(st + BT_PLB + doff, Al + ao);                             \
            }                                                                   \
            int gb = col0 + row;                                                \
            if (gb < N) {                                                       \
                size_t bo = (size_t)gb * Ktot + kc0 + ch * 8;                   \
                cpa16(st + 2 * BT_PLB + doff, Bh + bo);                         \
                cpa16(st + 3 * BT_PLB + doff, Bl + bo);                         \
            }                                                                   \
        }                                                                       \
        asm volatile("cp.async.commit_group;" ::: "memory");                    \
    }

#define BT_COMPUTE(BUF)                                                         \
    {                                                                           \
        const uint32_t pa_hi = sb + (BUF) * BT_STAGEB;                          \
        const uint32_t pa_lo = pa_hi + BT_PLB;                                  \
        const uint32_t pb_hi = pa_hi + 2 * BT_PLB;                              \
        const uint32_t pb_lo = pa_hi + 3 * BT_PLB;                              \
        const int lr = lane & 15, lc = (lane >> 4) << 3;                        \
        _Pragma("unroll")                                                       \
        for (int sub = 0; sub < 2; sub++) {                                     \
            const int kk0 = sub * 16;                                           \
            uint32_t ah[4][4], al[4][4], bh[2][4], bl[2][4];                    \
            _Pragma("unroll")                                                   \
            for (int i = 0; i < 4; i++) {                                       \
                uint32_t off = (uint32_t)(((wm + i * 16 + lr) * 40 + kk0 + lc) * 2); \
                ldsm_x4(ah[i], pa_hi + off);                                    \
                ldsm_x4(al[i], pa_lo + off);                                    \
            }                                                                   \
            _Pragma("unroll")                                                   \
            for (int g = 0; g < 2; g++) {                                       \
                uint32_t off = (uint32_t)(((wn + g * 16 + lr) * 40 + kk0 + lc) * 2); \
                ldsm_x4(bh[g], pb_hi + off);                                    \
                ldsm_x4(bl[g], pb_lo + off);                                    \
            }                                                                   \
            _Pragma("unroll")                                                   \
            for (int i = 0; i < 4; i++)                                         \
                _Pragma("unroll")                                               \
                for (int j = 0; j < 4; j++) {                                   \
                    const int g = j >> 1, o = j & 1;                            \
                    mma_bf16(acc[i][j], ah[i], bh[g][o], bh[g][o + 2]);         \
                    mma_bf16(acc[i][j], ah[i], bl[g][o], bl[g][o + 2]);         \
                    mma_bf16(acc[i][j], al[i], bh[g][o], bh[g][o + 2]);         \
                }                                                               \
        }                                                                       \
    }

    BT_LOAD(0, 0);
    int buf = 0;
    for (int c = 0; c < nch; c++) {
        const bool more = (c + 1) < nch;
        if (more) { BT_LOAD(c + 1, buf ^ 1); }
        if (more) asm volatile("cp.async.wait_group 1;" ::: "memory");
        else      asm volatile("cp.async.wait_group 0;" ::: "memory");
        __syncthreads();
        BT_COMPUTE(buf);
        __syncthreads();
        buf ^= 1;
    }

    const int er = lane >> 2;
    const int ec = (lane & 3) * 2;
#pragma unroll
    for (int i = 0; i < 4; i++) {
#pragma unroll
        for (int j = 0; j < 4; j++) {
            int gm0 = row0 + wm + i * 16 + er;
            int gn  = col0 + wn + j * 8 + ec;
            if (gn >= N) continue;
            if (gm0 < M) {
                Cb[(size_t)gm0 * ldc + gn] = acc[i][j][0];
                if (gn + 1 < N) Cb[(size_t)gm0 * ldc + gn + 1] = acc[i][j][1];
            }
            int gm1 = gm0 + 8;
            if (gm1 < M) {
                Cb[(size_t)gm1 * ldc + gn] = acc[i][j][2];
                if (gn + 1 < N) Cb[(size_t)gm1 * ldc + gn + 1] = acc[i][j][3];
            }
        }
    }
#undef BT_LOAD
#undef BT_COMPUTE
}

// ---------------- split prepasses ----------------
template<bool SILU>
__global__ void split_rm_kernel(const float* __restrict__ x, const float* __restrict__ z,
                                int Kd, int ldz,
                                unsigned short* __restrict__ hi,
                                unsigned short* __restrict__ lo, int total)
{
    int i = blockIdx.x * blockDim.x + threadIdx.x;
    if (i >= total) return;
    float v = x[i];
    if (SILU) {
        int row = i / Kd, col = i - row * Kd;
        v *= siluf(z[(size_t)row * ldz + col]);
    }
    __nv_bfloat16 h, l;
    split_bf(v, h, l);
    hi[i] = __bfloat16_as_ushort(h);
    lo[i] = __bfloat16_as_ushort(l);
}

// W[K,N] fp32 -> Whi/Wlo [N,K] bf16 planes
__global__ void tsplit_kernel(const float* __restrict__ w,
                              unsigned short* __restrict__ hi,
                              unsigned short* __restrict__ lo, int Kd, int Nd)
{
    __shared__ float t[32][33];
    int n0 = blockIdx.x * 32, k0 = blockIdx.y * 32;
    int tx = threadIdx.x, ty = threadIdx.y;
#pragma unroll
    for (int i = 0; i < 32; i += 8)
        t[ty + i][tx] = w[(size_t)(k0 + ty + i) * Nd + n0 + tx];
    __syncthreads();
#pragma unroll
    for (int i = 0; i < 32; i += 8) {
        int n = n0 + ty + i, k = k0 + tx;
        float v = t[tx][ty + i];
        __nv_bfloat16 h, l;
        split_bf(v, h, l);
        hi[(size_t)n * Kd + k] = __bfloat16_as_ushort(h);
        lo[(size_t)n * Kd + k] = __bfloat16_as_ushort(l);
    }
}

// ================= HMMA GEMM with inline split (small GEMMs) =================
static constexpr int SA_STAGE = 128 * 40;
static constexpr int SB_STAGE = 32 * 136;
static constexpr int TC_AHI = 0;
static constexpr int TC_ALO = 2 * SA_STAGE;
static constexpr int TC_BHI = 4 * SA_STAGE;
static constexpr int TC_BLO = TC_BHI + 2 * SB_STAGE;
static constexpr int TC_SMEM_ELEMS = TC_BLO + 2 * SB_STAGE;
static constexpr int TC_SMEM_BYTES = TC_SMEM_ELEMS * 2;

template<int AMODE, bool EPI, bool VECA, bool VECB>
__global__ __launch_bounds__(256, 1) void gemm_tc(
    const float* __restrict__ A, int lda,
    const float* __restrict__ Bp, int ldb,
    float* __restrict__ C, int ldc,
    int M, int N, int Ktot, int splitk,
    size_t batchA, size_t batchB, size_t batchC, size_t strideS,
    const float* __restrict__ Zp, int ldz,
    const float* __restrict__ bias)
{
    extern __shared__ __align__(16) __nv_bfloat16 smem_tc[];

    const int tid  = threadIdx.x;
    const int lane = tid & 31;
    const int wid  = tid >> 5;
    const int wm   = (wid & 1) << 6;
    const int wn   = (wid >> 1) << 5;
    const int row0 = blockIdx.y * 128;
    const int col0 = blockIdx.x * 128;

    const int z = blockIdx.z;
    const int bb = z / splitk;
    const int s  = z - bb * splitk;
    const float* Ab = A + (size_t)bb * batchA;
    const float* Bb = Bp + (size_t)bb * batchB;
    float*       Cb = C + (size_t)bb * batchC + (size_t)s * strideS;
    const int kchunk = Ktot / splitk;
    const int kbeg = s * kchunk;
    const int kend = (s == splitk - 1) ? Ktot : kbeg + kchunk;

    const uint32_t sbase = (uint32_t)__cvta_generic_to_shared(smem_tc);

    const int ar = lane & 15;
    const int ac = (lane >> 4) << 3;
    const int br = (lane & 7) + ((lane >> 3) & 1) * 8;
    const int bc = (lane >> 4) << 3;

    float acc[4][4][4];
#pragma unroll
    for (int i = 0; i < 4; i++)
#pragma unroll
        for (int j = 0; j < 4; j++)
#pragma unroll
            for (int q = 0; q < 4; q++) acc[i][j][q] = 0.f;

    float4 ra4[4], rb4[4];

#define TC_LOADG(K0)                                                             \
    _Pragma("unroll")                                                            \
    for (int p = 0; p < 4; p++) {                                                \
        int idx = tid + p * 256;                                                 \
        float4 v = make_float4(0.f, 0.f, 0.f, 0.f);                              \
        {                                                                        \
            int am = idx >> 3, ak4 = (idx & 7) * 4;                              \
            int gm = row0 + am, gk = (K0) + ak4;                                 \
            if (gm < M) {                                                        \
                size_t aoff = (size_t)gm * lda + gk;                             \
                if (VECA && gk + 3 < kend) {                                     \
                    v = *(const float4*)(Ab + aoff);                             \
                } else {                                                         \
                    if (gk     < kend) v.x = Ab[aoff];                           \
                    if (gk + 1 < kend) v.y = Ab[aoff + 1];                       \
                    if (gk + 2 < kend) v.z = Ab[aoff + 2];                       \
                    if (gk + 3 < kend) v.w = Ab[aoff + 3];                       \
                }                                                                \
                if (AMODE == 1) {                                                \
                    size_t zoff = (size_t)gm * ldz + gk;                         \
                    float4 zv = make_float4(0.f, 0.f, 0.f, 0.f);                 \
                    if (VECA && gk + 3 < kend) {                                 \
                        zv = *(const float4*)(Zp + zoff);                        \
                    } else {                                                     \
                        if (gk     < kend) zv.x = Zp[zoff];                      \
                        if (gk + 1 < kend) zv.y = Zp[zoff + 1];                  \
                        if (gk + 2 < kend) zv.z = Zp[zoff + 2];                  \
                        if (gk + 3 < kend) zv.w = Zp[zoff + 3];                  \
                    }                                                            \
                    v.x *= siluf(zv.x); v.y *= siluf(zv.y);                      \
                    v.z *= siluf(zv.z); v.w *= siluf(zv.w);                      \
                }                                                                \
            }                                                                    \
        }                                                                        \
        ra4[p] = v;                                                              \
        int bk = idx >> 5, bn4 = (idx & 31) * 4;                                 \
        int gk2 = (K0) + bk, gn = col0 + bn4;                                    \
        float4 w = make_float4(0.f, 0.f, 0.f, 0.f);                             \
        if (gk2 < kend) {                                                        \
            size_t boff = (size_t)gk2 * ldb + gn;                                \
            if (VECB && gn + 3 < N) {                                            \
                w = *(const float4*)(Bb + boff);                                 \
            } else {                                                             \
                if (gn     < N) w.x = Bb[boff];                                  \
                if (gn + 1 < N) w.y = Bb[boff + 1];                              \
                if (gn + 2 < N) w.z = Bb[boff + 2];                              \
                if (gn + 3 < N) w.w = Bb[boff + 3];                              \
            }                                                                    \
        }                                                                        \
        rb4[p] = w;                                                              \
    }

#define TC_STORES(BUF)                                                           \
    _Pragma("unroll")                                                            \
    for (int p = 0; p < 4; p++) {                                                \
        int idx = tid + p * 256;                                                 \
        __nv_bfloat16 h0, h1, h2, h3, l0, l1, l2, l3;                            \
        split_bf(ra4[p].x, h0, l0); split_bf(ra4[p].y, h1, l1);                  \
        split_bf(ra4[p].z, h2, l2); split_bf(ra4[p].w, h3, l3);                  \
        {                                                                        \
            int am = idx >> 3, ak4 = (idx & 7) * 4;                              \
            int o = (BUF) * SA_STAGE + am * 40 + ak4;                            \
            __nv_bfloat162 t;                                                    \
            t.x = h0; t.y = h1;                                                  \
            *(__nv_bfloat162*)&smem_tc[TC_AHI + o] = t;                          \
            t.x = h2; t.y = h3;                                                  \
            *(__nv_bfloat162*)&smem_tc[TC_AHI + o + 2] = t;                      \
            t.x = l0; t.y = l1;                                                  \
            *(__nv_bfloat162*)&smem_tc[TC_ALO + o] = t;                          \
            t.x = l2; t.y = l3;                                                  \
            *(__nv_bfloat162*)&smem_tc[TC_ALO + o + 2] = t;                      \
        }                                                                        \
        split_bf(rb4[p].x, h0, l0); split_bf(rb4[p].y, h1, l1);                  \
        split_bf(rb4[p].z, h2, l2); split_bf(rb4[p].w, h3, l3);                  \
        int bk = idx >> 5, bn4 = (idx & 31) * 4;                                 \
        int ob = (BUF) * SB_STAGE + bk * 136 + bn4;                              \
        __nv_bfloat162 u;                                                        \
        u.x = h0; u.y = h1;                                                      \
        *(__nv_bfloat162*)&smem_tc[TC_BHI + ob] = u;                             \
        u.x = h2; u.y = h3;                                                      \
        *(__nv_bfloat162*)&smem_tc[TC_BHI + ob + 2] = u;                         \
        u.x = l0; u.y = l1;                                                      \
        *(__nv_bfloat162*)&smem_tc[TC_BLO + ob] = u;                             \
        u.x = l2; u.y = l3;                                                      \
        *(__nv_bfloat162*)&smem_tc[TC_BLO + ob + 2] = u;                         \
    }

    TC_LOADG(kbeg);
    TC_STORES(0);
    __syncthreads();

    int buf = 0;
    for (int k0 = kbeg; k0 < kend; k0 += 32) {
        const bool more = (k0 + 32) < kend;
        if (more) { TC_LOADG(k0 + 32); }

        const uint32_t sa_hi = sbase + (TC_AHI + buf * SA_STAGE) * 2;
        const uint32_t sa_lo = sbase + (TC_ALO + buf * SA_STAGE) * 2;
        const uint32_t sb_hi = sbase + (TC_BHI + buf * SB_STAGE) * 2;
        const uint32_t sb_lo = sbase + (TC_BLO + buf * SB_STAGE) * 2;

#pragma unroll
        for (int sub = 0; sub < 2; sub++) {
            const int kk0 = sub * 16;
            uint32_t ah[4][4], al[4][4], bh[2][4], bl[2][4];
#pragma unroll
            for (int i = 0; i < 4; i++) {
                uint32_t off = ((wm + i * 16 + ar) * 40 + kk0 + ac) * 2;
                ldsm_x4(ah[i], sa_hi + off);
                ldsm_x4(al[i], sa_lo + off);
            }
#pragma unroll
            for (int g = 0; g < 2; g++) {
                uint32_t off = ((kk0 + br) * 136 + wn + g * 16 + bc) * 2;
                ldsm_x4_t(bh[g], sb_hi + off);
                ldsm_x4_t(bl[g], sb_lo + off);
            }
#pragma unroll
            for (int i = 0; i < 4; i++)
#pragma unroll
                for (int j = 0; j < 4; j++) {
                    const int g = j >> 1, t = (j & 1) * 2;
                    mma_bf16(acc[i][j], ah[i], bh[g][t], bh[g][t + 1]);
                    mma_bf16(acc[i][j], ah[i], bl[g][t], bl[g][t + 1]);
                    mma_bf16(acc[i][j], al[i], bh[g][t], bh[g][t + 1]);
                }
        }

        if (more) { TC_STORES(buf ^ 1); }
        __syncthreads();
        buf ^= 1;
    }

    const int er = lane >> 2;
    const int ec = (lane & 3) * 2;
#pragma unroll
    for (int i = 0; i < 4; i++) {
#pragma unroll
        for (int j = 0; j < 4; j++) {
            int gm0 = row0 + wm + i * 16 + er;
            int gn  = col0 + wn + j * 8 + ec;
            if (gn >= N) continue;
            float v0 = acc[i][j][0], v1 = acc[i][j][1];
            float v2 = acc[i][j][2], v3 = acc[i][j][3];
            if (EPI) {
                float b0 = bias[gn];
                float b1 = (gn + 1 < N) ? bias[gn + 1] : 0.f;
                v0 = softplusf(v0 + b0); v1 = softplusf(v1 + b1);
                v2 = softplusf(v2 + b0); v3 = softplusf(v3 + b1);
            }
            if (gm0 < M) {
                Cb[(size_t)gm0 * ldc + gn] = v0;
                if (gn + 1 < N) Cb[(size_t)gm0 * ldc + gn + 1] = v1;
            }
            int gm1 = gm0 + 8;
            if (gm1 < M) {
                Cb[(size_t)gm1 * ldc + gn] = v2;
                if (gn + 1 < N) Cb[(size_t)gm1 * ldc + gn + 1] = v3;
            }
        }
    }
#undef TC_LOADG
#undef TC_STORES
}

// ---------------- fixed-order split-K reduction ----------------
__global__ void reduce_sum_kernel(const float* __restrict__ part, float* __restrict__ out,
                                  int total, size_t stride, int ns)
{
    int i = blockIdx.x * blockDim.x + threadIdx.x;
    if (i >= total) return;
    float a = 0.f;
    for (int s = 0; s < ns; s++) a += part[(size_t)s * stride + i];
    out[i] = a;
}

// ---------------- depthwise causal conv (k=4) + silu ----------------
__global__ void conv_silu_kernel(const float* __restrict__ xz, int ldxz,
                                 const float* __restrict__ w, const float* __restrict__ bias,
                                 float* __restrict__ xi, int Bn, int L, int dinner)
{
    int idx = blockIdx.x * blockDim.x + threadIdx.x;
    int total = Bn * L * dinner;
    if (idx >= total) return;
    int ch = idx % dinner;
    int l  = (idx / dinner) % L;
    int b  = idx / (dinner * L);
    const float* x0 = xz + (size_t)(b * L) * ldxz + ch;
    float acc = bias[ch];
    float w0 = w[ch * 4 + 0], w1 = w[ch * 4 + 1], w2 = w[ch * 4 + 2], w3 = w[ch * 4 + 3];
    if (l >= 3) acc = fmaf(w0, x0[(size_t)(l - 3) * ldxz], acc);
    if (l >= 2) acc = fmaf(w1, x0[(size_t)(l - 2) * ldxz], acc);
    if (l >= 1) acc = fmaf(w2, x0[(size_t)(l - 1) * ldxz], acc);
    acc = fmaf(w3, x0[(size_t)l * ldxz], acc);
    xi[idx] = siluf(acc);
}

// ---------------- selective scan ----------------
template<int TCH>
__global__ void scan_kernel(const float* __restrict__ u, const float* __restrict__ dt,
                            const float* __restrict__ xdbl, int ld_dbl, int boff, int coff,
                            const float* __restrict__ A_log, const float* __restrict__ Dp,
                            float* __restrict__ y, int Bn, int L, int dinner)
{
    int gwarp = (blockIdx.x * blockDim.x + threadIdx.x) >> 5;
    int lane  = threadIdx.x & 31;
    int half  = lane >> 4;
    int n     = lane & 15;
    int gd    = gwarp * 2 + half;
    if (gd >= Bn * dinner) return;
    int b   = gd / dinner;
    int dch = gd - b * dinner;

    float a  = -__expf(A_log[dch * NS + n]);
    float Dv = Dp[dch];
    float h  = 0.f;

    const float* urow  = u    + (size_t)b * L * dinner + dch;
    const float* dtrow = dt   + (size_t)b * L * dinner + dch;
    const float* brow  = xdbl + (size_t)b * L * ld_dbl + boff + n;
    const float* crow  = xdbl + (size_t)b * L * ld_dbl + coff + n;
    float*       yrow  = y    + (size_t)b * L * dinner + dch;

    float vdt[2][TCH], vu[2][TCH], vB[2][TCH], vC[2][TCH];

#define SCAN_LOAD(BUF, T0)                                                      \
    _Pragma("unroll")                                                           \
    for (int tt = 0; tt < TCH; tt++) {                                          \
        size_t t = (size_t)((T0) + tt);                                         \
        vdt[BUF][tt] = dtrow[t * dinner];                                       \
        vu[BUF][tt]  = urow[t * dinner];                                        \
        vB[BUF][tt]  = brow[t * ld_dbl];                                        \
        vC[BUF][tt]  = crow[t * ld_dbl];                                        \
    }

#define SCAN_COMPUTE(BUF, T0)                                                   \
    {                                                                           \
        float p[TCH];                                                           \
        _Pragma("unroll")                                                       \
        for (int tt = 0; tt < TCH; tt++) {                                      \
            float dA = __expf(vdt[BUF][tt] * a);                                \
            h = fmaf(dA, h, vdt[BUF][tt] * vB[BUF][tt] * vu[BUF][tt]);          \
            p[tt] = h * vC[BUF][tt] + ((n == 0) ? vu[BUF][tt] * Dv : 0.f);      \
        }                                                                       \
        _Pragma("unroll")                                                       \
        for (int tt = 0; tt < TCH; tt++) p[tt] += __shfl_xor_sync(0xffffffffu, p[tt], 8); \
        _Pragma("unroll")                                                       \
        for (int tt = 0; tt < TCH; tt++) p[tt] += __shfl_xor_sync(0xffffffffu, p[tt], 4); \
        _Pragma("unroll")                                                       \
        for (int tt = 0; tt < TCH; tt++) p[tt] += __shfl_xor_sync(0xffffffffu, p[tt], 2); \
        _Pragma("unroll")                                                       \
        for (int tt = 0; tt < TCH; tt++) p[tt] += __shfl_xor_sync(0xffffffffu, p[tt], 1); \
        _Pragma("unroll")                                                       \
        for (int tt = 0; tt < TCH; tt++)                                        \
            if (n == tt) yrow[(size_t)((T0) + tt) * dinner] = p[tt];            \
    }

    const int nch = L / TCH;
    SCAN_LOAD(0, 0);
    for (int c = 0; c < nch; c += 2) {
        if (c + 1 < nch) SCAN_LOAD(1, (c + 1) * TCH);
        SCAN_COMPUTE(0, c * TCH);
        if (c + 1 < nch) {
            if (c + 2 < nch) SCAN_LOAD(0, (c + 2) * TCH);
            SCAN_COMPUTE(1, (c + 1) * TCH);
        }
    }
#undef SCAN_LOAD
#undef SCAN_COMPUTE
}

// ---------------- mean over N_ : one warp per row ----------------
__global__ void mean_kernel(const float* __restrict__ sc2, float* __restrict__ sbuf)
{
    int gw = (blockIdx.x * blockDim.x + threadIdx.x) >> 5;
    int lane = threadIdx.x & 31;
    if (gw >= B_ * K_) return;
    const float* row = sc2 + (size_t)gw * N_;
    float a = 0.f;
    for (int i = lane; i < N_; i += 32) a += row[i];
#pragma unroll
    for (int o = 16; o; o >>= 1) a += __shfl_xor_sync(0xffffffffu, a, o);
    if (lane == 0) sbuf[gw] = a / (float)N_;
}

// ---------------- softmax over K_ per batch ----------------
__global__ void softmax_kernel(float* __restrict__ s)
{
    __shared__ float red[32];
    int b = blockIdx.x, tid = threadIdx.x;
    int lane = tid & 31, w = tid >> 5;
    float v = s[(size_t)b * K_ + tid];
    float m = v;
#pragma unroll
    for (int o = 16; o; o >>= 1) m = fmaxf(m, __shfl_xor_sync(0xffffffffu, m, o));
    if (lane == 0) red[w] = m;
    __syncthreads();
    if (tid < 32) {
        float t = red[tid];
#pragma unroll
        for (int o = 16; o; o >>= 1) t = fmaxf(t, __shfl_xor_sync(0xffffffffu, t, o));
        if (tid == 0) red[0] = t;
    }
    __syncthreads();
    m = red[0];
    __syncthreads();
    float e = __expf(v - m);
    float sum = e;
#pragma unroll
    for (int o = 16; o; o >>= 1) sum += __shfl_xor_sync(0xffffffffu, sum, o);
    if (lane == 0) red[w] = sum;
    __syncthreads();
    if (tid < 32) {
        float t = red[tid];
#pragma unroll
        for (int o = 16; o; o >>= 1) t += __shfl_xor_sync(0xffffffffu, t, o);
        if (tid == 0) red[0] = t;
    }
    __syncthreads();
    s[(size_t)b * K_ + tid] = e / red[0];
}

// ---------------- top-k(98 of 1024) bitonic ----------------
__global__ void topk_kernel(const float* __restrict__ s, int* __restrict__ ind,
                            float* __restrict__ vtop)
{
    __shared__ float sv[K_];
    __shared__ int   si[K_];
    int b = blockIdx.x, tid = threadIdx.x;
    for (int i = tid; i < K_; i += 256) { sv[i] = s[(size_t)b * K_ + i]; si[i] = i; }
    __syncthreads();
    for (int k = 2; k <= K_; k <<= 1) {
        for (int j = k >> 1; j > 0; j >>= 1) {
            for (int i = tid; i < K_; i += 256) {
                int ixj = i ^ j;
                if (ixj > i) {
                    float v1 = sv[i], v2 = sv[ixj];
                    int   i1 = si[i], i2 = si[ixj];
                    bool lt_ji = (v2 > v1) || (v2 == v1 && i2 < i1);
                    bool lt_ij = (v1 > v2) || (v1 == v2 && i1 < i2);
                    bool asc = ((i & k) == 0);
                    if (asc ? lt_ji : lt_ij) {
                        sv[i] = v2; sv[ixj] = v1;
                        si[i] = i2; si[ixj] = i1;
                    }
                }
            }
            __syncthreads();
        }
    }
    for (int i = tid; i < N_; i += 256) {
        ind[b * N_ + i]  = si[i];
        vtop[b * N_ + i] = sv[i];
    }
}

// ---------------- h = imageFeature + gather(kf, ind) * vtop ----------------
__global__ void build_h_kernel(const float* __restrict__ imf, const float* __restrict__ kf,
                               const int* __restrict__ ind, const float* __restrict__ vtop,
                               float* __restrict__ h)
{
    int idx = blockIdx.x * blockDim.x + threadIdx.x;
    int total = B_ * LC * DM_;
    if (idx >= total) return;
    int d = idx % DM_;
    int j = (idx / DM_) % LC;
    int b = idx / (DM_ * LC);
    int r = ind[b * N_ + j];
    h[idx] = imf[(size_t)j * DM_ + d] +
             kf[((size_t)b * DM_ + d) * K_ + r] * vtop[b * N_ + j];
}

// ---------------- host ----------------
extern "C" void kernel_launch(void* const* d_in, const int* in_sizes, int n_in,
                              void* d_out, int out_size)
{
    const float* imf      = (const float*)d_in[0];
    const float* kf       = (const float*)d_in[1];
    const float* a_in_w   = (const float*)d_in[2];
    const float* a_conv_w = (const float*)d_in[3];
    const float* a_conv_b = (const float*)d_in[4];
    const float* a_xproj_w= (const float*)d_in[5];
    const float* a_dt_w   = (const float*)d_in[6];
    const float* a_dt_b   = (const float*)d_in[7];
    const float* a_A_log  = (const float*)d_in[8];
    const float* a_D      = (const float*)d_in[9];
    const float* a_out_w  = (const float*)d_in[10];
    const float* c_in_w   = (const float*)d_in[11];
    const float* c_conv_w = (const float*)d_in[12];
    const float* c_conv_b = (const float*)d_in[13];
    const float* c_xproj_w= (const float*)d_in[14];
    const float* c_dt_w   = (const float*)d_in[15];
    const float* c_dt_b   = (const float*)d_in[16];
    const float* c_A_log  = (const float*)d_in[17];
    const float* c_D      = (const float*)d_in[18];
    const float* c_out_w  = (const float*)d_in[19];
    float* out = (float*)d_out;

    cudaFuncSetAttribute((const void*)gemm_bt, cudaFuncAttributeMaxDynamicSharedMemorySize, BT_SMEM);
    cudaFuncSetAttribute((const void*)gemm_tc<0, false, false, true >, cudaFuncAttributeMaxDynamicSharedMemorySize, TC_SMEM_BYTES);
    cudaFuncSetAttribute((const void*)gemm_tc<0, false, true,  false>, cudaFuncAttributeMaxDynamicSharedMemorySize, TC_SMEM_BYTES);
    cudaFuncSetAttribute((const void*)gemm_tc<0, true,  false, true >, cudaFuncAttributeMaxDynamicSharedMemorySize, TC_SMEM_BYTES);
    cudaFuncSetAttribute((const void*)gemm_tc<1, false, true,  false>, cudaFuncAttributeMaxDynamicSharedMemorySize, TC_SMEM_BYTES);
    cudaFuncSetAttribute((const void*)gemm_tc<0, false, true,  true >, cudaFuncAttributeMaxDynamicSharedMemorySize, TC_SMEM_BYTES);
    cudaFuncSetAttribute((const void*)gemm_tc<0, true,  true,  true >, cudaFuncAttributeMaxDynamicSharedMemorySize, TC_SMEM_BYTES);

    float* sc = nullptr;
    cudaGetSymbolAddress((void**)&sc, g_scratch);
    unsigned short* bf = nullptr;
    cudaGetSymbolAddress((void**)&bf, g_bf);
    int*   p_ind  = nullptr;
    float* p_vtop = nullptr;
    cudaGetSymbolAddress((void**)&p_ind, g_ind);
    cudaGetSymbolAddress((void**)&p_vtop, g_vtop);

    float* scp    = sc + OFF_SCP;
    float* scorev = sc + OFF_SC;
    float* xza    = sc + OFF_XZA;
    float* xia    = sc + OFF_XIA;
    float* xdbla  = sc + OFF_XDBLA;
    float* dta    = sc + OFF_DTA;
    float* ya     = sc + OFF_YA;
    float* sc2    = sc + OFF_SC2;
    float* sbuf   = sc + OFF_S;
    float* hbuf   = sc + OFF_H;
    float* xzc    = sc + OFF_XZC;
    float* xic    = sc + OFF_XIC;
    float* xdblc  = sc + OFF_XDBLC;
    float* xpcp   = sc + OFF_XPCP;
    float* dtc    = sc + OFF_DTC;
    float* yc     = sc + OFF_YC;
    float* outp   = sc + OFF_OUTP;

    const int Ma = B_ * K_;   // 8192
    const int Mc = B_ * LC;   // 784

    // -- prepasses: weight + input splits (transpose to [N][K] K-contig planes) --
    tsplit_kernel<<<dim3((2 * DIC) / 32, DM_ / 32), dim3(32, 8)>>>(
        c_in_w, bf + BO_CINW_HI, bf + BO_CINW_LO, DM_, 2 * DIC);
    tsplit_kernel<<<dim3(DM_ / 32, DIC / 32), dim3(32, 8)>>>(
        c_out_w, bf + BO_COUTW_HI, bf + BO_COUTW_LO, DIC, DM_);
    for (int b = 0; b < B_; b++)
        tsplit_kernel<<<dim3(K_ / 32, DM_ / 32), dim3(32, 8)>>>(
            kf + (size_t)b * DM_ * K_,
            bf + BO_KFT_HI + (size_t)b * K_ * DM_,
            bf + BO_KFT_LO + (size_t)b * K_ * DM_, DM_, K_);
    split_rm_kernel<false><<<ceil_div((int)BSZ_IMF, 256), 256>>>(
        imf, nullptr, DM_, 0, bf + BO_IMF_HI, bf + BO_IMF_LO, (int)BSZ_IMF);

    // 0: score[b][l][n] = kfT[b] @ imf^T  (plane GEMM, batched, split-K=2)
    gemm_bt<<<dim3(1, K_ / 128, B_ * SPLITK_SC), 256, BT_SMEM>>>(
        bf + BO_KFT_HI, bf + BO_KFT_LO, bf + BO_IMF_HI, bf + BO_IMF_LO,
        scp, N_, K_, N_, DM_, SPLITK_SC,
        (size_t)K_ * DM_, 0, (size_t)K_ * N_, SZ_SC1);
    reduce_sum_kernel<<<ceil_div((int)SZ_SC1, 256), 256>>>(
        scp, scorev, (int)SZ_SC1, SZ_SC1, SPLITK_SC);

    // 1: xza = score @ a_in_w  (lda=98 -> scalar A)
    gemm_tc<0, false, false, true><<<dim3(ceil_div(2 * DIA, 128), Ma / 128, 1), 256, TC_SMEM_BYTES>>>(
        scorev, N_, a_in_w, 2 * DIA, xza, 2 * DIA, Ma, 2 * DIA, N_, 1,
        0, 0, 0, 0, nullptr, 0, nullptr);

    // 2: conv + silu (a)
    conv_silu_kernel<<<ceil_div(B_ * LA * DIA, 256), 256>>>(
        xza, 2 * DIA, a_conv_w, a_conv_b, xia, B_, LA, DIA);

    // 3: x_dbl = xi @ a_xproj_w
    gemm_tc<0, false, true, false><<<dim3(1, Ma / 128, 1), 256, TC_SMEM_BYTES>>>(
        xia, DIA, a_xproj_w, LDBA, xdbla, LDBA, Ma, LDBA, DIA, 1,
        0, 0, 0, 0, nullptr, 0, nullptr);

    // 4: dt = softplus(xdbl[:, :7] @ a_dt_w + b)
    gemm_tc<0, true, false, true><<<dim3(ceil_div(DIA, 128), Ma / 128, 1), 256, TC_SMEM_BYTES>>>(
        xdbla, LDBA, a_dt_w, DIA, dta, DIA, Ma, DIA, DRA, 1,
        0, 0, 0, 0, nullptr, 0, a_dt_b);

    // 5: selective scan (a)
    scan_kernel<8><<<(B_ * DIA / 2 * 32) / 256, 256>>>(
        xia, dta, xdbla, LDBA, DRA, DRA + NS, a_A_log, a_D, ya, B_, LA, DIA);

    // 6: sc2 = (y * silu(z)) @ a_out_w
    gemm_tc<1, false, true, false><<<dim3(1, Ma / 128, 1), 256, TC_SMEM_BYTES>>>(
        ya, DIA, a_out_w, N_, sc2, N_, Ma, N_, DIA, 1,
        0, 0, 0, 0, xza + DIA, 2 * DIA, nullptr);

    // 7-10: mean / softmax / topk / gather
    mean_kernel<<<(B_ * K_ * 32) / 256, 256>>>(sc2, sbuf);
    softmax_kernel<<<B_, K_>>>(sbuf);
    topk_kernel<<<B_, 256>>>(sbuf, p_ind, p_vtop);
    build_h_kernel<<<ceil_div(B_ * LC * DM_, 256), 256>>>(imf, kf, p_ind, p_vtop, hbuf);

    // 11: xzc = h @ c_in_w  (plane GEMM)
    split_rm_kernel<false><<<ceil_div(Mc * DM_, 256), 256>>>(
        hbuf, nullptr, DM_, 0, bf + BO_H_HI, bf + BO_H_LO, Mc * DM_);
    gemm_bt<<<dim3((2 * DIC) / 128, ceil_div(Mc, 128), 1), 256, BT_SMEM>>>(
        bf + BO_H_HI, bf + BO_H_LO, bf + BO_CINW_HI, bf + BO_CINW_LO,
        xzc, 2 * DIC, Mc, 2 * DIC, DM_, 1, 0, 0, 0, 0);

    // 12: conv + silu (c)
    conv_silu_kernel<<<ceil_div(B_ * LC * DIC, 256), 256>>>(
        xzc, 2 * DIC, c_conv_w, c_conv_b, xic, B_, LC, DIC);

    // 13: x_dbl partials = xi @ c_xproj_w (split-K=8, HMMA)
    gemm_tc<0, false, true, true><<<dim3(ceil_div(LDBC, 128), ceil_div(Mc, 128), SPLITK_XPC), 256, TC_SMEM_BYTES>>>(
        xic, DIC, c_xproj_w, LDBC, xpcp, LDBC, Mc, LDBC, DIC, SPLITK_XPC,
        0, 0, 0, (size_t)Mc * LDBC, nullptr, 0, nullptr);
    reduce_sum_kernel<<<ceil_div(Mc * LDBC, 256), 256>>>(
        xpcp, xdblc, Mc * LDBC, (size_t)Mc * LDBC, SPLITK_XPC);

    // 14: dt = softplus(xdbl[:, :128] @ c_dt_w + b)
    gemm_tc<0, true, true, true><<<dim3(DIC / 128, ceil_div(Mc, 128), 1), 256, TC_SMEM_BYTES>>>(
        xdblc, LDBC, c_dt_w, DIC, dtc, DIC, Mc, DIC, DRC, 1,
        0, 0, 0, 0, nullptr, 0, c_dt_b);

    // 15: selective scan (c)
    scan_kernel<7><<<(B_ * DIC / 2 * 32) / 256, 256>>>(
        xic, dtc, xdblc, LDBC, DRC, DRC + NS, c_A_log, c_D, yc, B_, LC, DIC);

    // 16: out partials = (y * silu(z)) @ c_out_w  (plane GEMM, split-K=2)
    split_rm_kernel<true><<<ceil_div(Mc * DIC, 256), 256>>>(
        yc, xzc + DIC, DIC, 2 * DIC, bf + BO_Y_HI, bf + BO_Y_LO, Mc * DIC);
    gemm_bt<<<dim3(DM_ / 128, ceil_div(Mc, 128), SPLITK_COUT), 256, BT_SMEM>>>(
        bf + BO_Y_HI, bf + BO_Y_LO, bf + BO_COUTW_HI, bf + BO_COUTW_LO,
        outp, DM_, Mc, DM_, DIC, SPLITK_COUT, 0, 0, 0, (size_t)Mc * DM_);

    // 17: reduce -> out
    reduce_sum_kernel<<<ceil_div(Mc * DM_, 256), 256>>>(
        outp, out, Mc * DM_, (size_t)Mc * DM_, SPLITK_COUT);
}

// round 10
// speedup vs baseline: 2.9920x; 1.0971x over previous
#include <cuda_runtime.h>
#include <cuda_bf16.h>
#include <math.h>
#include <stdint.h>

// ---------------- problem constants ----------------
static constexpr int B_  = 8;
static constexpr int K_  = 1024;
static constexpr int N_  = 98;
static constexpr int DM_ = 2048;
static constexpr int DIA = 196;
static constexpr int DRA = 7;
static constexpr int DIC = 4096;
static constexpr int DRC = 128;
static constexpr int NS  = 16;
static constexpr int LA  = 1024;
static constexpr int LC  = 98;
static constexpr int LDBA = DRA + 2 * NS;   // 39
static constexpr int LDBC = DRC + 2 * NS;   // 160

static constexpr int SPLITK_SC   = 4;
static constexpr int SPLITK_XPC  = 8;
static constexpr int SPLITK_COUT = 2;

// ---------------- fp32 scratch arena ----------------
static constexpr size_t SZ_SC1   = (size_t)B_ * K_ * N_;
static constexpr size_t SZ_SCP   = (size_t)SPLITK_SC * SZ_SC1;
static constexpr size_t SZ_XZA   = (size_t)B_ * K_ * 2 * DIA;
static constexpr size_t SZ_XIA   = (size_t)B_ * K_ * DIA;
static constexpr size_t SZ_XDBLA = (size_t)B_ * K_ * LDBA;
static constexpr size_t SZ_DTA   = (size_t)B_ * K_ * DIA;
static constexpr size_t SZ_YA    = (size_t)B_ * K_ * DIA;
static constexpr size_t SZ_SC2   = (size_t)B_ * K_ * N_;
static constexpr size_t SZ_S     = (size_t)B_ * K_;
static constexpr size_t SZ_XZC   = (size_t)B_ * LC * 2 * DIC;
static constexpr size_t SZ_XIC   = (size_t)B_ * LC * DIC;
static constexpr size_t SZ_XDBLC = (size_t)B_ * LC * LDBC;
static constexpr size_t SZ_XPCP  = (size_t)SPLITK_XPC * B_ * LC * LDBC;
static constexpr size_t SZ_DTC   = (size_t)B_ * LC * DIC;
static constexpr size_t SZ_YC    = (size_t)B_ * LC * DIC;
static constexpr size_t SZ_OUTP  = (size_t)SPLITK_COUT * B_ * LC * DM_;

static constexpr size_t OFF_SCP   = 0;
static constexpr size_t OFF_SC    = OFF_SCP + SZ_SCP;
static constexpr size_t OFF_XZA   = OFF_SC + SZ_SC1;
static constexpr size_t OFF_XIA   = OFF_XZA + SZ_XZA;
static constexpr size_t OFF_XDBLA = OFF_XIA + SZ_XIA;
static constexpr size_t OFF_DTA   = OFF_XDBLA + SZ_XDBLA;
static constexpr size_t OFF_YA    = OFF_DTA + SZ_DTA;
static constexpr size_t OFF_SC2   = OFF_YA + SZ_YA;
static constexpr size_t OFF_S     = OFF_SC2 + SZ_SC2;
static constexpr size_t OFF_XZC   = OFF_S + SZ_S;
static constexpr size_t OFF_XIC   = OFF_XZC + SZ_XZC;
static constexpr size_t OFF_XDBLC = OFF_XIC + SZ_XIC;
static constexpr size_t OFF_XPCP  = OFF_XDBLC + SZ_XDBLC;
static constexpr size_t OFF_DTC   = OFF_XPCP + SZ_XPCP;
static constexpr size_t OFF_YC    = OFF_DTC + SZ_DTC;
static constexpr size_t OFF_OUTP  = OFF_YC + SZ_YC;
static constexpr size_t SCRATCH_TOTAL = OFF_OUTP + SZ_OUTP;

__device__ float g_scratch[SCRATCH_TOTAL];
__device__ int   g_ind[B_ * N_];
__device__ float g_vtop[B_ * N_];

// ---------------- bf16 hi/lo plane arena (u16) ----------------
static constexpr size_t BSZ_KFT   = (size_t)B_ * K_ * DM_;
static constexpr size_t BSZ_IMF   = (size_t)N_ * DM_;
static constexpr size_t BSZ_CINW  = (size_t)(2 * DIC) * DM_;
static constexpr size_t BSZ_COUTW = (size_t)DM_ * DIC;
static constexpr size_t BSZ_H     = (size_t)B_ * LC * DM_;
static constexpr size_t BSZ_Y     = (size_t)B_ * LC * DIC;

static constexpr size_t BO_KFT_HI   = 0;
static constexpr size_t BO_KFT_LO   = BO_KFT_HI + BSZ_KFT;
static constexpr size_t BO_IMF_HI   = BO_KFT_LO + BSZ_KFT;
static constexpr size_t BO_IMF_LO   = BO_IMF_HI + BSZ_IMF;
static constexpr size_t BO_CINW_HI  = BO_IMF_LO + BSZ_IMF;
static constexpr size_t BO_CINW_LO  = BO_CINW_HI + BSZ_CINW;
static constexpr size_t BO_COUTW_HI = BO_CINW_LO + BSZ_CINW;
static constexpr size_t BO_COUTW_LO = BO_COUTW_HI + BSZ_COUTW;
static constexpr size_t BO_H_HI     = BO_COUTW_LO + BSZ_COUTW;
static constexpr size_t BO_H_LO     = BO_H_HI + BSZ_H;
static constexpr size_t BO_Y_HI     = BO_H_LO + BSZ_H;
static constexpr size_t BO_Y_LO     = BO_Y_HI + BSZ_Y;
static constexpr size_t BF_TOTAL    = BO_Y_LO + BSZ_Y;

__device__ unsigned short g_bf[BF_TOTAL];

// ---------------- helpers ----------------
__device__ __forceinline__ float siluf(float x) { return x / (1.f + __expf(-x)); }
__device__ __forceinline__ float softplusf(float x) {
    return x > 20.f ? x : log1pf(__expf(x));
}
static inline int ceil_div(int a, int b) { return (a + b - 1) / b; }

__device__ __forceinline__ void ldsm_x4(uint32_t (&r)[4], uint32_t addr) {
    asm volatile("ldmatrix.sync.aligned.m8n8.x4.shared.b16 {%0,%1,%2,%3}, [%4];"
                 : "=r"(r[0]), "=r"(r[1]), "=r"(r[2]), "=r"(r[3]) : "r"(addr));
}
__device__ __forceinline__ void ldsm_x4_t(uint32_t (&r)[4], uint32_t addr) {
    asm volatile("ldmatrix.sync.aligned.m8n8.x4.trans.shared.b16 {%0,%1,%2,%3}, [%4];"
                 : "=r"(r[0]), "=r"(r[1]), "=r"(r[2]), "=r"(r[3]) : "r"(addr));
}
__device__ __forceinline__ void mma_bf16(float (&d)[4], const uint32_t (&a)[4],
                                         uint32_t b0, uint32_t b1) {
    asm volatile("mma.sync.aligned.m16n8k16.row.col.f32.bf16.bf16.f32 "
                 "{%0,%1,%2,%3}, {%4,%5,%6,%7}, {%8,%9}, {%0,%1,%2,%3};"
                 : "+f"(d[0]), "+f"(d[1]), "+f"(d[2]), "+f"(d[3])
                 : "r"(a[0]), "r"(a[1]), "r"(a[2]), "r"(a[3]), "r"(b0), "r"(b1));
}
__device__ __forceinline__ void split_bf(float v, __nv_bfloat16& h, __nv_bfloat16& l) {
    h = __float2bfloat16(v);
    l = __float2bfloat16(v - __bfloat162float(h));
}
__device__ __forceinline__ void cpa16(uint32_t dst, const void* src) {
    asm volatile("cp.async.cg.shared.global [%0], [%1], 16;" :: "r"(dst), "l"(src));
}

// ================================================================
//  gemm_bt:  C[M,N] = A[M,K] @ B[N,K]^T   (pre-split bf16 planes)
//  128x128 tile, K-chunks of 32, cp.async double buffer, 256 thr,
//  2 CTAs/SM (register-bounded). Inner loop: cp.async+ldsm+mma only.
// ================================================================
static constexpr int BT_PL     = 128 * 40;
static constexpr int BT_PLB    = BT_PL * 2;           // 10240 B
static constexpr int BT_STAGEB = 4 * BT_PLB;          // 40960 B
static constexpr int BT_SMEM   = 2 * BT_STAGEB;       // 81920 B

__global__ __launch_bounds__(256, 2) void gemm_bt(
    const unsigned short* __restrict__ Ahi, const unsigned short* __restrict__ Alo,
    const unsigned short* __restrict__ Bhi, const unsigned short* __restrict__ Blo,
    float* __restrict__ C, int ldc,
    int M, int N, int Ktot, int splitk,
    size_t batchA, size_t batchB, size_t batchC, size_t strideS)
{
    extern __shared__ __align__(16) unsigned short smem_bt[];
    const uint32_t sb = (uint32_t)__cvta_generic_to_shared(smem_bt);

    const int tid = threadIdx.x, lane = tid & 31, wid = tid >> 5;
    const int wm = (wid & 1) << 6;
    const int wn = (wid >> 1) << 5;
    const int row0 = blockIdx.y * 128;
    const int col0 = blockIdx.x * 128;

    const int z = blockIdx.z;
    const int bb = z / splitk;
    const int s  = z - bb * splitk;
    const unsigned short* Ah = Ahi + (size_t)bb * batchA;
    const unsigned short* Al = Alo + (size_t)bb * batchA;
    const unsigned short* Bh = Bhi + (size_t)bb * batchB;
    const unsigned short* Bl = Blo + (size_t)bb * batchB;
    float* Cb = C + (size_t)bb * batchC + (size_t)s * strideS;

    const int Kc = Ktot / splitk;
    const int kbeg = s * Kc;
    const int nch = Kc / 32;

    float acc[4][4][4];
#pragma unroll
    for (int i = 0; i < 4; i++)
#pragma unroll
        for (int j = 0; j < 4; j++)
#pragma unroll
            for (int q = 0; q < 4; q++) acc[i][j][q] = 0.f;

#define BT_LOAD(CC, BUF)                                                        \
    {                                                                           \
        const int kc0 = kbeg + (CC) * 32;                                       \
        const uint32_t st = sb + (BUF) * BT_STAGEB;                             \
        _Pragma("unroll")                                                       \
        for (int p = 0; p < 2; p++) {                                           \
            int idx = tid + p * 256;                                            \
            int row = idx >> 2, ch = idx & 3;                                   \
            uint32_t doff = (uint32_t)(row * 80 + ch * 16);                     \
            int ga = row0 + row;                                                \
            if (ga < M) {                                                       \
                size_t ao = (size_t)ga * Ktot + kc0 + ch * 8;                   \
                cpa16(st + doff,          Ah + ao);                             \
                cpa16(st + BT_PLB + doff, Al + ao);                             \
            }                                                                   \
            int gb = col0 + row;                                                \
            if (gb < N) {                                                       \
                size_t bo = (size_t)gb * Ktot + kc0 + ch * 8;                   \
                cpa16(st + 2 * BT_PLB + doff, Bh + bo);                         \
                cpa16(st + 3 * BT_PLB + doff, Bl + bo);                         \
            }                                                                   \
        }                                                                       \
        asm volatile("cp.async.commit_group;" ::: "memory");                    \
    }

#define BT_COMPUTE(BUF)                                                         \
    {                                                                           \
        const uint32_t pa_hi = sb + (BUF) * BT_STAGEB;                          \
        const uint32_t pa_lo = pa_hi + BT_PLB;                                  \
        const uint32_t pb_hi = pa_hi + 2 * BT_PLB;                              \
        const uint32_t pb_lo = pa_hi + 3 * BT_PLB;                              \
        const int lr = lane & 15, lc = (lane >> 4) << 3;                        \
        _Pragma("unroll")                                                       \
        for (int sub = 0; sub < 2; sub++) {                                     \
            const int kk0 = sub * 16;                                           \
            uint32_t bh[2][4], bl[2][4];                                        \
            _Pragma("unroll")                                                   \
            for (int g = 0; g < 2; g++) {                                       \
                uint32_t off = (uint32_t)(((wn + g * 16 + lr) * 40 + kk0 + lc) * 2); \
                ldsm_x4(bh[g], pb_hi + off);                                    \
                ldsm_x4(bl[g], pb_lo + off);                                    \
            }                                                                   \
            _Pragma("unroll")                                                   \
            for (int i = 0; i < 4; i++) {                                       \
                uint32_t ah[4], al[4];                                          \
                uint32_t offa = (uint32_t)(((wm + i * 16 + lr) * 40 + kk0 + lc) * 2); \
                ldsm_x4(ah, pa_hi + offa);                                      \
                ldsm_x4(al, pa_lo + offa);                                      \
                _Pragma("unroll")                                               \
                for (int j = 0; j < 4; j++) {                                   \
                    const int g = j >> 1, o = j & 1;                            \
                    mma_bf16(acc[i][j], ah, bh[g][o], bh[g][o + 2]);            \
                    mma_bf16(acc[i][j], ah, bl[g][o], bl[g][o + 2]);            \
                    mma_bf16(acc[i][j], al, bh[g][o], bh[g][o + 2]);            \
                }                                                               \
            }                                                                   \
        }                                                                       \
    }

    BT_LOAD(0, 0);
    int buf = 0;
    for (int c = 0; c < nch; c++) {
        const bool more = (c + 1) < nch;
        if (more) { BT_LOAD(c + 1, buf ^ 1); }
        if (more) asm volatile("cp.async.wait_group 1;" ::: "memory");
        else      asm volatile("cp.async.wait_group 0;" ::: "memory");
        __syncthreads();
        BT_COMPUTE(buf);
        __syncthreads();
        buf ^= 1;
    }

    const int er = lane >> 2;
    const int ec = (lane & 3) * 2;
#pragma unroll
    for (int i = 0; i < 4; i++) {
#pragma unroll
        for (int j = 0; j < 4; j++) {
            int gm0 = row0 + wm + i * 16 + er;
            int gn  = col0 + wn + j * 8 + ec;
            if (gn >= N) continue;
            if (gm0 < M) {
                Cb[(size_t)gm0 * ldc + gn] = acc[i][j][0];
                if (gn + 1 < N) Cb[(size_t)gm0 * ldc + gn + 1] = acc[i][j][1];
            }
            int gm1 = gm0 + 8;
            if (gm1 < M) {
                Cb[(size_t)gm1 * ldc + gn] = acc[i][j][2];
                if (gn + 1 < N) Cb[(size_t)gm1 * ldc + gn + 1] = acc[i][j][3];
            }
        }
    }
#undef BT_LOAD
#undef BT_COMPUTE
}

// ---------------- split prepasses (vectorized) ----------------
template<bool SILU>
__global__ void split_rm_kernel(const float* __restrict__ x, const float* __restrict__ z,
                                int Kd, int ldz,
                                unsigned short* __restrict__ hi,
                                unsigned short* __restrict__ lo, int total4)
{
    int t = blockIdx.x * blockDim.x + threadIdx.x;
    if (t >= total4) return;
    int i = t * 4;
    float4 v = *(const float4*)(x + i);
    if (SILU) {
        int row = i / Kd, col = i - row * Kd;
        float4 zv = *(const float4*)(z + (size_t)row * ldz + col);
        v.x *= siluf(zv.x); v.y *= siluf(zv.y);
        v.z *= siluf(zv.z); v.w *= siluf(zv.w);
    }
    __nv_bfloat16 h0, h1, h2, h3, l0, l1, l2, l3;
    split_bf(v.x, h0, l0); split_bf(v.y, h1, l1);
    split_bf(v.z, h2, l2); split_bf(v.w, h3, l3);
    __nv_bfloat162 a, b;
    a.x = h0; a.y = h1; b.x = h2; b.y = h3;
    *(__nv_bfloat162*)(hi + i)     = a;
    *(__nv_bfloat162*)(hi + i + 2) = b;
    a.x = l0; a.y = l1; b.x = l2; b.y = l3;
    *(__nv_bfloat162*)(lo + i)     = a;
    *(__nv_bfloat162*)(lo + i + 2) = b;
}

// W[Kd,Nd] fp32 -> Whi/Wlo [Nd,Kd] bf16 planes (batched over z)
__global__ void tsplit_kernel(const float* __restrict__ w,
                              unsigned short* __restrict__ hi,
                              unsigned short* __restrict__ lo, int Kd, int Nd,
                              size_t wBatch, size_t oBatch)
{
    __shared__ float t[32][33];
    int n0 = blockIdx.x * 32, k0 = blockIdx.y * 32;
    const float* wb = w + (size_t)blockIdx.z * wBatch;
    unsigned short* hib = hi + (size_t)blockIdx.z * oBatch;
    unsigned short* lob = lo + (size_t)blockIdx.z * oBatch;
    int tx = threadIdx.x & 31, ty = threadIdx.x >> 5;   // 256 threads = 32x8
#pragma unroll
    for (int i = 0; i < 32; i += 8)
        t[ty + i][tx] = wb[(size_t)(k0 + ty + i) * Nd + n0 + tx];
    __syncthreads();
#pragma unroll
    for (int p = 0; p < 2; p++) {
        int q = threadIdx.x + p * 256;     // 0..511
        int n = q >> 4;                    // 0..31
        int kp = q & 15;                   // 0..15
        float v0 = t[2 * kp][n], v1 = t[2 * kp + 1][n];
        __nv_bfloat16 h0, l0, h1, l1;
        split_bf(v0, h0, l0); split_bf(v1, h1, l1);
        size_t off = (size_t)(n0 + n) * Kd + k0 + 2 * kp;
        __nv_bfloat162 hh; hh.x = h0; hh.y = h1;
        *(__nv_bfloat162*)(hib + off) = hh;
        __nv_bfloat162 ll; ll.x = l0; ll.y = l1;
        *(__nv_bfloat162*)(lob + off) = ll;
    }
}

// ================= HMMA GEMM with inline split (small GEMMs) =================
static constexpr int SA_STAGE = 128 * 40;
static constexpr int SB_STAGE = 32 * 136;
static constexpr int TC_AHI = 0;
static constexpr int TC_ALO = 2 * SA_STAGE;
static constexpr int TC_BHI = 4 * SA_STAGE;
static constexpr int TC_BLO = TC_BHI + 2 * SB_STAGE;
static constexpr int TC_SMEM_ELEMS = TC_BLO + 2 * SB_STAGE;
static constexpr int TC_SMEM_BYTES = TC_SMEM_ELEMS * 2;

template<int AMODE, bool EPI, bool VECA, bool VECB>
__global__ __launch_bounds__(256, 1) void gemm_tc(
    const float* __restrict__ A, int lda,
    const float* __restrict__ Bp, int ldb,
    float* __restrict__ C, int ldc,
    int M, int N, int Ktot, int splitk,
    size_t batchA, size_t batchB, size_t batchC, size_t strideS,
    const float* __restrict__ Zp, int ldz,
    const float* __restrict__ bias)
{
    extern __shared__ __align__(16) __nv_bfloat16 smem_tc[];

    const int tid  = threadIdx.x;
    const int lane = tid & 31;
    const int wid  = tid >> 5;
    const int wm   = (wid & 1) << 6;
    const int wn   = (wid >> 1) << 5;
    const int row0 = blockIdx.y * 128;
    const int col0 = blockIdx.x * 128;

    const int z = blockIdx.z;
    const int bb = z / splitk;
    const int s  = z - bb * splitk;
    const float* Ab = A + (size_t)bb * batchA;
    const float* Bb = Bp + (size_t)bb * batchB;
    float*       Cb = C + (size_t)bb * batchC + (size_t)s * strideS;
    const int kchunk = Ktot / splitk;
    const int kbeg = s * kchunk;
    const int kend = (s == splitk - 1) ? Ktot : kbeg + kchunk;

    const uint32_t sbase = (uint32_t)__cvta_generic_to_shared(smem_tc);

    const int ar = lane & 15;
    const int ac = (lane >> 4) << 3;
    const int br = (lane & 7) + ((lane >> 3) & 1) * 8;
    const int bc = (lane >> 4) << 3;

    float acc[4][4][4];
#pragma unroll
    for (int i = 0; i < 4; i++)
#pragma unroll
        for (int j = 0; j < 4; j++)
#pragma unroll
            for (int q = 0; q < 4; q++) acc[i][j][q] = 0.f;

    float4 ra4[4], rb4[4];

#define TC_LOADG(K0)                                                             \
    _Pragma("unroll")                                                            \
    for (int p = 0; p < 4; p++) {                                                \
        int idx = tid + p * 256;                                                 \
        float4 v = make_float4(0.f, 0.f, 0.f, 0.f);                              \
        {                                                                        \
            int am = idx >> 3, ak4 = (idx & 7) * 4;                              \
            int gm = row0 + am, gk = (K0) + ak4;                                 \
            if (gm < M) {                                                        \
                size_t aoff = (size_t)gm * lda + gk;                             \
                if (VECA && gk + 3 < kend) {                                     \
                    v = *(const float4*)(Ab + aoff);                             \
                } else {                                                         \
                    if (gk     < kend) v.x = Ab[aoff];                           \
                    if (gk + 1 < kend) v.y = Ab[aoff + 1];                       \
                    if (gk + 2 < kend) v.z = Ab[aoff + 2];                       \
                    if (gk + 3 < kend) v.w = Ab[aoff + 3];                       \
                }                                                                \
                if (AMODE == 1) {                                                \
                    size_t zoff = (size_t)gm * ldz + gk;                         \
                    float4 zv = make_float4(0.f, 0.f, 0.f, 0.f);                 \
                    if (VECA && gk + 3 < kend) {                                 \
                        zv = *(const float4*)(Zp + zoff);                        \
                    } else {                                                     \
                        if (gk     < kend) zv.x = Zp[zoff];                      \
                        if (gk + 1 < kend) zv.y = Zp[zoff + 1];                  \
                        if (gk + 2 < kend) zv.z = Zp[zoff + 2];                  \
                        if (gk + 3 < kend) zv.w = Zp[zoff + 3];                  \
                    }                                                            \
                    v.x *= siluf(zv.x); v.y *= siluf(zv.y);                      \
                    v.z *= siluf(zv.z); v.w *= siluf(zv.w);                      \
                }                                                                \
            }                                                                    \
        }                                                                        \
        ra4[p] = v;                                                              \
        int bk = idx >> 5, bn4 = (idx & 31) * 4;                                 \
        int gk2 = (K0) + bk, gn = col0 + bn4;                                    \
        float4 w = make_float4(0.f, 0.f, 0.f, 0.f);                             \
        if (gk2 < kend) {                                                        \
            size_t boff = (size_t)gk2 * ldb + gn;                                \
            if (VECB && gn + 3 < N) {                                            \
                w = *(const float4*)(Bb + boff);                                 \
            } else {                                                             \
                if (gn     < N) w.x = Bb[boff];                                  \
                if (gn + 1 < N) w.y = Bb[boff + 1];                              \
                if (gn + 2 < N) w.z = Bb[boff + 2];                              \
                if (gn + 3 < N) w.w = Bb[boff + 3];                              \
            }                                                                    \
        }                                                                        \
        rb4[p] = w;                                                              \
    }

#define TC_STORES(BUF)                                                           \
    _Pragma("unroll")                                                            \
    for (int p = 0; p < 4; p++) {                                                \
        int idx = tid + p * 256;                                                 \
        __nv_bfloat16 h0, h1, h2, h3, l0, l1, l2, l3;                            \
        split_bf(ra4[p].x, h0, l0); split_bf(ra4[p].y, h1, l1);                  \
        split_bf(ra4[p].z, h2, l2); split_bf(ra4[p].w, h3, l3);                  \
        {                                                                        \
            int am = idx >> 3, ak4 = (idx & 7) * 4;                              \
            int o = (BUF) * SA_STAGE + am * 40 + ak4;                            \
            __nv_bfloat162 t;                                                    \
            t.x = h0; t.y = h1;                                                  \
            *(__nv_bfloat162*)&smem_tc[TC_AHI + o] = t;                          \
            t.x = h2; t.y = h3;                                                  \
            *(__nv_bfloat162*)&smem_tc[TC_AHI + o + 2] = t;                      \
            t.x = l0; t.y = l1;                                                  \
            *(__nv_bfloat162*)&smem_tc[TC_ALO + o] = t;                          \
            t.x = l2; t.y = l3;                                                  \
            *(__nv_bfloat162*)&smem_tc[TC_ALO + o + 2] = t;                      \
        }                                                                        \
        split_bf(rb4[p].x, h0, l0); split_bf(rb4[p].y, h1, l1);                  \
        split_bf(rb4[p].z, h2, l2); split_bf(rb4[p].w, h3, l3);                  \
        int bk = idx >> 5, bn4 = (idx & 31) * 4;                                 \
        int ob = (BUF) * SB_STAGE + bk * 136 + bn4;                              \
        __nv_bfloat162 u;                                                        \
        u.x = h0; u.y = h1;                                                      \
        *(__nv_bfloat162*)&smem_tc[TC_BHI + ob] = u;                             \
        u.x = h2; u.y = h3;                                                      \
        *(__nv_bfloat162*)&smem_tc[TC_BHI + ob + 2] = u;                         \
        u.x = l0; u.y = l1;                                                      \
        *(__nv_bfloat162*)&smem_tc[TC_BLO + ob] = u;                             \
        u.x = l2; u.y = l3;                                                      \
        *(__nv_bfloat162*)&smem_tc[TC_BLO + ob + 2] = u;                         \
    }

    TC_LOADG(kbeg);
    TC_STORES(0);
    __syncthreads();

    int buf = 0;
    for (int k0 = kbeg; k0 < kend; k0 += 32) {
        const bool more = (k0 + 32) < kend;
        if (more) { TC_LOADG(k0 + 32); }

        const uint32_t sa_hi = sbase + (TC_AHI + buf * SA_STAGE) * 2;
        const uint32_t sa_lo = sbase + (TC_ALO + buf * SA_STAGE) * 2;
        const uint32_t sb_hi = sbase + (TC_BHI + buf * SB_STAGE) * 2;
        const uint32_t sb_lo = sbase + (TC_BLO + buf * SB_STAGE) * 2;

#pragma unroll
        for (int sub = 0; sub < 2; sub++) {
            const int kk0 = sub * 16;
            uint32_t ah[4][4], al[4][4], bh[2][4], bl[2][4];
#pragma unroll
            for (int i = 0; i < 4; i++) {
                uint32_t off = ((wm + i * 16 + ar) * 40 + kk0 + ac) * 2;
                ldsm_x4(ah[i], sa_hi + off);
                ldsm_x4(al[i], sa_lo + off);
            }
#pragma unroll
            for (int g = 0; g < 2; g++) {
                uint32_t off = ((kk0 + br) * 136 + wn + g * 16 + bc) * 2;
                ldsm_x4_t(bh[g], sb_hi + off);
                ldsm_x4_t(bl[g], sb_lo + off);
            }
#pragma unroll
            for (int i = 0; i < 4; i++)
#pragma unroll
                for (int j = 0; j < 4; j++) {
                    const int g = j >> 1, t = (j & 1) * 2;
                    mma_bf16(acc[i][j], ah[i], bh[g][t], bh[g][t + 1]);
                    mma_bf16(acc[i][j], ah[i], bl[g][t], bl[g][t + 1]);
                    mma_bf16(acc[i][j], al[i], bh[g][t], bh[g][t + 1]);
                }
        }

        if (more) { TC_STORES(buf ^ 1); }
        __syncthreads();
        buf ^= 1;
    }

    const int er = lane >> 2;
    const int ec = (lane & 3) * 2;
#pragma unroll
    for (int i = 0; i < 4; i++) {
#pragma unroll
        for (int j = 0; j < 4; j++) {
            int gm0 = row0 + wm + i * 16 + er;
            int gn  = col0 + wn + j * 8 + ec;
            if (gn >= N) continue;
            float v0 = acc[i][j][0], v1 = acc[i][j][1];
            float v2 = acc[i][j][2], v3 = acc[i][j][3];
            if (EPI) {
                float b0 = bias[gn];
                float b1 = (gn + 1 < N) ? bias[gn + 1] : 0.f;
                v0 = softplusf(v0 + b0); v1 = softplusf(v1 + b1);
                v2 = softplusf(v2 + b0); v3 = softplusf(v3 + b1);
            }
            if (gm0 < M) {
                Cb[(size_t)gm0 * ldc + gn] = v0;
                if (gn + 1 < N) Cb[(size_t)gm0 * ldc + gn + 1] = v1;
            }
            int gm1 = gm0 + 8;
            if (gm1 < M) {
                Cb[(size_t)gm1 * ldc + gn] = v2;
                if (gn + 1 < N) Cb[(size_t)gm1 * ldc + gn + 1] = v3;
            }
        }
    }
#undef TC_LOADG
#undef TC_STORES
}

// ---------------- fixed-order split-K reduction ----------------
__global__ void reduce_sum_kernel(const float* __restrict__ part, float* __restrict__ out,
                                  int total, size_t stride, int ns)
{
    int i = blockIdx.x * blockDim.x + threadIdx.x;
    if (i >= total) return;
    float a = 0.f;
    for (int s = 0; s < ns; s++) a += part[(size_t)s * stride + i];
    out[i] = a;
}

// ---------------- depthwise causal conv (k=4) + silu, x4 vectorized ----------------
__global__ void conv_silu_kernel(const float* __restrict__ xz, int ldxz,
                                 const float* __restrict__ w, const float* __restrict__ bias,
                                 float* __restrict__ xi, int Bn, int L, int dinner)
{
    int t = blockIdx.x * blockDim.x + threadIdx.x;
    int total4 = (Bn * L * dinner) >> 2;
    if (t >= total4) return;
    int i4 = t * 4;
    int ch = i4 % dinner;
    int l  = (i4 / dinner) % L;
    int b  = i4 / (dinner * L);
    const float* x0 = xz + (size_t)(b * L) * ldxz + ch;

    float4 acc = *(const float4*)(bias + ch);
    float4 w0 = *(const float4*)(w + (ch + 0) * 4);
    float4 w1 = *(const float4*)(w + (ch + 1) * 4);
    float4 w2 = *(const float4*)(w + (ch + 2) * 4);
    float4 w3 = *(const float4*)(w + (ch + 3) * 4);

    float4 xx = *(const float4*)(x0 + (size_t)l * ldxz);
    acc.x = fmaf(w0.w, xx.x, acc.x);
    acc.y = fmaf(w1.w, xx.y, acc.y);
    acc.z = fmaf(w2.w, xx.z, acc.z);
    acc.w = fmaf(w3.w, xx.w, acc.w);
    if (l >= 1) {
        float4 xm = *(const float4*)(x0 + (size_t)(l - 1) * ldxz);
        acc.x = fmaf(w0.z, xm.x, acc.x);
        acc.y = fmaf(w1.z, xm.y, acc.y);
        acc.z = fmaf(w2.z, xm.z, acc.z);
        acc.w = fmaf(w3.z, xm.w, acc.w);
    }
    if (l >= 2) {
        float4 xm = *(const float4*)(x0 + (size_t)(l - 2) * ldxz);
        acc.x = fmaf(w0.y, xm.x, acc.x);
        acc.y = fmaf(w1.y, xm.y, acc.y);
        acc.z = fmaf(w2.y, xm.z, acc.z);
        acc.w = fmaf(w3.y, xm.w, acc.w);
    }
    if (l >= 3) {
        float4 xm = *(const float4*)(x0 + (size_t)(l - 3) * ldxz);
        acc.x = fmaf(w0.x, xm.x, acc.x);
        acc.y = fmaf(w1.x, xm.y, acc.y);
        acc.z = fmaf(w2.x, xm.z, acc.z);
        acc.w = fmaf(w3.x, xm.w, acc.w);
    }
    acc.x = siluf(acc.x); acc.y = siluf(acc.y);
    acc.z = siluf(acc.z); acc.w = siluf(acc.w);
    *(float4*)(xi + i4) = acc;
}

// ---------------- selective scan ----------------
template<int TCH>
__global__ void scan_kernel(const float* __restrict__ u, const float* __restrict__ dt,
                            const float* __restrict__ xdbl, int ld_dbl, int boff, int coff,
                            const float* __restrict__ A_log, const float* __restrict__ Dp,
                            float* __restrict__ y, int Bn, int L, int dinner)
{
    int gwarp = (blockIdx.x * blockDim.x + threadIdx.x) >> 5;
    int lane  = threadIdx.x & 31;
    int half  = lane >> 4;
    int n     = lane & 15;
    int gd    = gwarp * 2 + half;
    if (gd >= Bn * dinner) return;
    int b   = gd / dinner;
    int dch = gd - b * dinner;

    float a  = -__expf(A_log[dch * NS + n]);
    float Dv = Dp[dch];
    float h  = 0.f;

    const float* urow  = u    + (size_t)b * L * dinner + dch;
    const float* dtrow = dt   + (size_t)b * L * dinner + dch;
    const float* brow  = xdbl + (size_t)b * L * ld_dbl + boff + n;
    const float* crow  = xdbl + (size_t)b * L * ld_dbl + coff + n;
    float*       yrow  = y    + (size_t)b * L * dinner + dch;

    float vdt[2][TCH], vu[2][TCH], vB[2][TCH], vC[2][TCH];

#define SCAN_LOAD(BUF, T0)                                                      \
    _Pragma("unroll")                                                           \
    for (int tt = 0; tt < TCH; tt++) {                                          \
        size_t t = (size_t)((T0) + tt);                                         \
        vdt[BUF][tt] = dtrow[t * dinner];                                       \
        vu[BUF][tt]  = urow[t * dinner];                                        \
        vB[BUF][tt]  = brow[t * ld_dbl];                                        \
        vC[BUF][tt]  = crow[t * ld_dbl];                                        \
    }

#define SCAN_COMPUTE(BUF, T0)                                                   \
    {                                                                           \
        float p[TCH];                                                           \
        _Pragma("unroll")                                                       \
        for (int tt = 0; tt < TCH; tt++) {                                      \
            float dA = __expf(vdt[BUF][tt] * a);                                \
            h = fmaf(dA, h, vdt[BUF][tt] * vB[BUF][tt] * vu[BUF][tt]);          \
            p[tt] = h * vC[BUF][tt] + ((n == 0) ? vu[BUF][tt] * Dv : 0.f);      \
        }                                                                       \
        _Pragma("unroll")                                                       \
        for (int tt = 0; tt < TCH; tt++) p[tt] += __shfl_xor_sync(0xffffffffu, p[tt], 8); \
        _Pragma("unroll")                                                       \
        for (int tt = 0; tt < TCH; tt++) p[tt] += __shfl_xor_sync(0xffffffffu, p[tt], 4); \
        _Pragma("unroll")                                                       \
        for (int tt = 0; tt < TCH; tt++) p[tt] += __shfl_xor_sync(0xffffffffu, p[tt], 2); \
        _Pragma("unroll")                                                       \
        for (int tt = 0; tt < TCH; tt++) p[tt] += __shfl_xor_sync(0xffffffffu, p[tt], 1); \
        _Pragma("unroll")                                                       \
        for (int tt = 0; tt < TCH; tt++)                                        \
            if (n == tt) yrow[(size_t)((T0) + tt) * dinner] = p[tt];            \
    }

    const int nch = L / TCH;
    SCAN_LOAD(0, 0);
    for (int c = 0; c < nch; c += 2) {
        if (c + 1 < nch) SCAN_LOAD(1, (c + 1) * TCH);
        SCAN_COMPUTE(0, c * TCH);
        if (c + 1 < nch) {
            if (c + 2 < nch) SCAN_LOAD(0, (c + 2) * TCH);
            SCAN_COMPUTE(1, (c + 1) * TCH);
        }
    }
#undef SCAN_LOAD
#undef SCAN_COMPUTE
}

// ---------------- mean over N_ : one warp per row ----------------
__global__ void mean_kernel(const float* __restrict__ sc2, float* __restrict__ sbuf)
{
    int gw = (blockIdx.x * blockDim.x + threadIdx.x) >> 5;
    int lane = threadIdx.x & 31;
    if (gw >= B_ * K_) return;
    const float* row = sc2 + (size_t)gw * N_;
    float a = 0.f;
    for (int i = lane; i < N_; i += 32) a += row[i];
#pragma unroll
    for (int o = 16; o; o >>= 1) a += __shfl_xor_sync(0xffffffffu, a, o);
    if (lane == 0) sbuf[gw] = a / (float)N_;
}

// ---------------- softmax over K_ per batch ----------------
__global__ void softmax_kernel(float* __restrict__ s)
{
    __shared__ float red[32];
    int b = blockIdx.x, tid = threadIdx.x;
    int lane = tid & 31, w = tid >> 5;
    float v = s[(size_t)b * K_ + tid];
    float m = v;
#pragma unroll
    for (int o = 16; o; o >>= 1) m = fmaxf(m, __shfl_xor_sync(0xffffffffu, m, o));
    if (lane == 0) red[w] = m;
    __syncthreads();
    if (tid < 32) {
        float t = red[tid];
#pragma unroll
        for (int o = 16; o; o >>= 1) t = fmaxf(t, __shfl_xor_sync(0xffffffffu, t, o));
        if (tid == 0) red[0] = t;
    }
    __syncthreads();
    m = red[0];
    __syncthreads();
    float e = __expf(v - m);
    float sum = e;
#pragma unroll
    for (int o = 16; o; o >>= 1) sum += __shfl_xor_sync(0xffffffffu, sum, o);
    if (lane == 0) red[w] = sum;
    __syncthreads();
    if (tid < 32) {
        float t = red[tid];
#pragma unroll
        for (int o = 16; o; o >>= 1) t += __shfl_xor_sync(0xffffffffu, t, o);
        if (tid == 0) red[0] = t;
    }
    __syncthreads();
    s[(size_t)b * K_ + tid] = e / red[0];
}

// ---------------- top-k(98 of 1024) bitonic ----------------
__global__ void topk_kernel(const float* __restrict__ s, int* __restrict__ ind,
                            float* __restrict__ vtop)
{
    __shared__ float sv[K_];
    __shared__ int   si[K_];
    int b = blockIdx.x, tid = threadIdx.x;
    for (int i = tid; i < K_; i += 256) { sv[i] = s[(size_t)b * K_ + i]; si[i] = i; }
    __syncthreads();
    for (int k = 2; k <= K_; k <<= 1) {
        for (int j = k >> 1; j > 0; j >>= 1) {
            for (int i = tid; i < K_; i += 256) {
                int ixj = i ^ j;
                if (ixj > i) {
                    float v1 = sv[i], v2 = sv[ixj];
                    int   i1 = si[i], i2 = si[ixj];
                    bool lt_ji = (v2 > v1) || (v2 == v1 && i2 < i1);
                    bool lt_ij = (v1 > v2) || (v1 == v2 && i1 < i2);
                    bool asc = ((i & k) == 0);
                    if (asc ? lt_ji : lt_ij) {
                        sv[i] = v2; sv[ixj] = v1;
                        si[i] = i2; si[ixj] = i1;
                    }
                }
            }
            __syncthreads();
        }
    }
    for (int i = tid; i < N_; i += 256) {
        ind[b * N_ + i]  = si[i];
        vtop[b * N_ + i] = sv[i];
    }
}

// ---------------- h planes = split(imageFeature + gather(kf) * vtop) ----------------
__global__ void build_h_kernel(const float* __restrict__ imf, const float* __restrict__ kf,
                               const int* __restrict__ ind, const float* __restrict__ vtop,
                               unsigned short* __restrict__ hhi,
                               unsigned short* __restrict__ hlo)
{
    int idx = blockIdx.x * blockDim.x + threadIdx.x;
    int total = B_ * LC * DM_;
    if (idx >= total) return;
    int d = idx % DM_;
    int j = (idx / DM_) % LC;
    int b = idx / (DM_ * LC);
    int r = ind[b * N_ + j];
    float v = imf[(size_t)j * DM_ + d] +
              kf[((size_t)b * DM_ + d) * K_ + r] * vtop[b * N_ + j];
    __nv_bfloat16 h, l;
    split_bf(v, h, l);
    hhi[idx] = __bfloat16_as_ushort(h);
    hlo[idx] = __bfloat16_as_ushort(l);
}

// ---------------- host ----------------
extern "C" void kernel_launch(void* const* d_in, const int* in_sizes, int n_in,
                              void* d_out, int out_size)
{
    const float* imf      = (const float*)d_in[0];
    const float* kf       = (const float*)d_in[1];
    const float* a_in_w   = (const float*)d_in[2];
    const float* a_conv_w = (const float*)d_in[3];
    const float* a_conv_b = (const float*)d_in[4];
    const float* a_xproj_w= (const float*)d_in[5];
    const float* a_dt_w   = (const float*)d_in[6];
    const float* a_dt_b   = (const float*)d_in[7];
    const float* a_A_log  = (const float*)d_in[8];
    const float* a_D      = (const float*)d_in[9];
    const float* a_out_w  = (const float*)d_in[10];
    const float* c_in_w   = (const float*)d_in[11];
    const float* c_conv_w = (const float*)d_in[12];
    const float* c_conv_b = (const float*)d_in[13];
    const float* c_xproj_w= (const float*)d_in[14];
    const float* c_dt_w   = (const float*)d_in[15];
    const float* c_dt_b   = (const float*)d_in[16];
    const float* c_A_log  = (const float*)d_in[17];
    const float* c_D      = (const float*)d_in[18];
    const float* c_out_w  = (const float*)d_in[19];
    float* out = (float*)d_out;

    cudaFuncSetAttribute((const void*)gemm_bt, cudaFuncAttributeMaxDynamicSharedMemorySize, BT_SMEM);
    cudaFuncSetAttribute((const void*)gemm_tc<0, false, false, true >, cudaFuncAttributeMaxDynamicSharedMemorySize, TC_SMEM_BYTES);
    cudaFuncSetAttribute((const void*)gemm_tc<0, false, true,  false>, cudaFuncAttributeMaxDynamicSharedMemorySize, TC_SMEM_BYTES);
    cudaFuncSetAttribute((const void*)gemm_tc<0, true,  false, true >, cudaFuncAttributeMaxDynamicSharedMemorySize, TC_SMEM_BYTES);
    cudaFuncSetAttribute((const void*)gemm_tc<1, false, true,  false>, cudaFuncAttributeMaxDynamicSharedMemorySize, TC_SMEM_BYTES);
    cudaFuncSetAttribute((const void*)gemm_tc<0, false, true,  true >, cudaFuncAttributeMaxDynamicSharedMemorySize, TC_SMEM_BYTES);
    cudaFuncSetAttribute((const void*)gemm_tc<0, true,  true,  true >, cudaFuncAttributeMaxDynamicSharedMemorySize, TC_SMEM_BYTES);

    float* sc = nullptr;
    cudaGetSymbolAddress((void**)&sc, g_scratch);
    unsigned short* bf = nullptr;
    cudaGetSymbolAddress((void**)&bf, g_bf);
    int*   p_ind  = nullptr;
    float* p_vtop = nullptr;
    cudaGetSymbolAddress((void**)&p_ind, g_ind);
    cudaGetSymbolAddress((void**)&p_vtop, g_vtop);

    float* scp    = sc + OFF_SCP;
    float* scorev = sc + OFF_SC;
    float* xza    = sc + OFF_XZA;
    float* xia    = sc + OFF_XIA;
    float* xdbla  = sc + OFF_XDBLA;
    float* dta    = sc + OFF_DTA;
    float* ya     = sc + OFF_YA;
    float* sc2    = sc + OFF_SC2;
    float* sbuf   = sc + OFF_S;
    float* xzc    = sc + OFF_XZC;
    float* xic    = sc + OFF_XIC;
    float* xdblc  = sc + OFF_XDBLC;
    float* xpcp   = sc + OFF_XPCP;
    float* dtc    = sc + OFF_DTC;
    float* yc     = sc + OFF_YC;
    float* outp   = sc + OFF_OUTP;

    const int Ma = B_ * K_;   // 8192
    const int Mc = B_ * LC;   // 784

    // -- prepasses: weight + input splits (transpose to [N][K] K-contig planes) --
    tsplit_kernel<<<dim3((2 * DIC) / 32, DM_ / 32, 1), 256>>>(
        c_in_w, bf + BO_CINW_HI, bf + BO_CINW_LO, DM_, 2 * DIC, 0, 0);
    tsplit_kernel<<<dim3(DM_ / 32, DIC / 32, 1), 256>>>(
        c_out_w, bf + BO_COUTW_HI, bf + BO_COUTW_LO, DIC, DM_, 0, 0);
    tsplit_kernel<<<dim3(K_ / 32, DM_ / 32, B_), 256>>>(
        kf, bf + BO_KFT_HI, bf + BO_KFT_LO, DM_, K_,
        (size_t)DM_ * K_, (size_t)K_ * DM_);
    split_rm_kernel<false><<<ceil_div((int)(BSZ_IMF / 4), 256), 256>>>(
        imf, nullptr, DM_, 0, bf + BO_IMF_HI, bf + BO_IMF_LO, (int)(BSZ_IMF / 4));

    // 0: score[b][l][n] = kfT[b] @ imf^T  (plane GEMM, batched, split-K=4)
    gemm_bt<<<dim3(1, K_ / 128, B_ * SPLITK_SC), 256, BT_SMEM>>>(
        bf + BO_KFT_HI, bf + BO_KFT_LO, bf + BO_IMF_HI, bf + BO_IMF_LO,
        scp, N_, K_, N_, DM_, SPLITK_SC,
        (size_t)K_ * DM_, 0, (size_t)K_ * N_, SZ_SC1);
    reduce_sum_kernel<<<ceil_div((int)SZ_SC1, 256), 256>>>(
        scp, scorev, (int)SZ_SC1, SZ_SC1, SPLITK_SC);

    // 1: xza = score @ a_in_w
    gemm_tc<0, false, false, true><<<dim3(ceil_div(2 * DIA, 128), Ma / 128, 1), 256, TC_SMEM_BYTES>>>(
        scorev, N_, a_in_w, 2 * DIA, xza, 2 * DIA, Ma, 2 * DIA, N_, 1,
        0, 0, 0, 0, nullptr, 0, nullptr);

    // 2: conv + silu (a)
    conv_silu_kernel<<<ceil_div(B_ * LA * DIA / 4, 256), 256>>>(
        xza, 2 * DIA, a_conv_w, a_conv_b, xia, B_, LA, DIA);

    // 3: x_dbl = xi @ a_xproj_w
    gemm_tc<0, false, true, false><<<dim3(1, Ma / 128, 1), 256, TC_SMEM_BYTES>>>(
        xia, DIA, a_xproj_w, LDBA, xdbla, LDBA, Ma, LDBA, DIA, 1,
        0, 0, 0, 0, nullptr, 0, nullptr);

    // 4: dt = softplus(xdbl[:, :7] @ a_dt_w + b)
    gemm_tc<0, true, false, true><<<dim3(ceil_div(DIA, 128), Ma / 128, 1), 256, TC_SMEM_BYTES>>>(
        xdbla, LDBA, a_dt_w, DIA, dta, DIA, Ma, DIA, DRA, 1,
        0, 0, 0, 0, nullptr, 0, a_dt_b);

    // 5: selective scan (a)
    scan_kernel<8><<<(B_ * DIA / 2 * 32) / 256, 256>>>(
        xia, dta, xdbla, LDBA, DRA, DRA + NS, a_A_log, a_D, ya, B_, LA, DIA);

    // 6: sc2 = (y * silu(z)) @ a_out_w
    gemm_tc<1, false, true, false><<<dim3(1, Ma / 128, 1), 256, TC_SMEM_BYTES>>>(
        ya, DIA, a_out_w, N_, sc2, N_, Ma, N_, DIA, 1,
        0, 0, 0, 0, xza + DIA, 2 * DIA, nullptr);

    // 7-10: mean / softmax / topk / gather (fused split)
    mean_kernel<<<(B_ * K_ * 32) / 256, 256>>>(sc2, sbuf);
    softmax_kernel<<<B_, K_>>>(sbuf);
    topk_kernel<<<B_, 256>>>(sbuf, p_ind, p_vtop);
    build_h_kernel<<<ceil_div(B_ * LC * DM_, 256), 256>>>(
        imf, kf, p_ind, p_vtop, bf + BO_H_HI, bf + BO_H_LO);

    // 11: xzc = h @ c_in_w  (plane GEMM)
    gemm_bt<<<dim3((2 * DIC) / 128, ceil_div(Mc, 128), 1), 256, BT_SMEM>>>(
        bf + BO_H_HI, bf + BO_H_LO, bf + BO_CINW_HI, bf + BO_CINW_LO,
        xzc, 2 * DIC, Mc, 2 * DIC, DM_, 1, 0, 0, 0, 0);

    // 12: conv + silu (c)
    conv_silu_kernel<<<ceil_div(B_ * LC * DIC / 4, 256), 256>>>(
        xzc, 2 * DIC, c_conv_w, c_conv_b, xic, B_, LC, DIC);

    // 13: x_dbl partials = xi @ c_xproj_w (split-K=8, HMMA)
    gemm_tc<0, false, true, true><<<dim3(ceil_div(LDBC, 128), ceil_div(Mc, 128), SPLITK_XPC), 256, TC_SMEM_BYTES>>>(
        xic, DIC, c_xproj_w, LDBC, xpcp, LDBC, Mc, LDBC, DIC, SPLITK_XPC,
        0, 0, 0, (size_t)Mc * LDBC, nullptr, 0, nullptr);
    reduce_sum_kernel<<<ceil_div(Mc * LDBC, 256), 256>>>(
        xpcp, xdblc, Mc * LDBC, (size_t)Mc * LDBC, SPLITK_XPC);

    // 14: dt = softplus(xdbl[:, :128] @ c_dt_w + b)
    gemm_tc<0, true, true, true><<<dim3(DIC / 128, ceil_div(Mc, 128), 1), 256, TC_SMEM_BYTES>>>(
        xdblc, LDBC, c_dt_w, DIC, dtc, DIC, Mc, DIC, DRC, 1,
        0, 0, 0, 0, nullptr, 0, c_dt_b);

    // 15: selective scan (c)
    scan_kernel<7><<<(B_ * DIC / 2 * 32) / 256, 256>>>(
        xic, dtc, xdblc, LDBC, DRC, DRC + NS, c_A_log, c_D, yc, B_, LC, DIC);

    // 16: y planes = split(y * silu(z)), then out partials (plane GEMM, split-K=2)
    split_rm_kernel<true><<<ceil_div(Mc * DIC / 4, 256), 256>>>(
        yc, xzc + DIC, DIC, 2 * DIC, bf + BO_Y_HI, bf + BO_Y_LO, Mc * DIC / 4);
    gemm_bt<<<dim3(DM_ / 128, ceil_div(Mc, 128), SPLITK_COUT), 256, BT_SMEM>>>(
        bf + BO_Y_HI, bf + BO_Y_LO, bf + BO_COUTW_HI, bf + BO_COUTW_LO,
        outp, DM_, Mc, DM_, DIC, SPLITK_COUT, 0, 0, 0, (size_t)Mc * DM_);

    // 17: reduce -> out
    reduce_sum_kernel<<<ceil_div(Mc * DM_, 256), 256>>>(
        outp, out, Mc * DM_, (size_t)Mc * DM_, SPLITK_COUT);
}

// round 12
// speedup vs baseline: 3.0145x; 1.0075x over previous
#include <cuda_runtime.h>
#include <cuda_bf16.h>
#include <math.h>
#include <stdint.h>

// ---------------- problem constants ----------------
static constexpr int B_  = 8;
static constexpr int K_  = 1024;
static constexpr int N_  = 98;
static constexpr int DM_ = 2048;
static constexpr int DIA = 196;
static constexpr int DRA = 7;
static constexpr int DIC = 4096;
static constexpr int DRC = 128;
static constexpr int NS  = 16;
static constexpr int LA  = 1024;
static constexpr int LC  = 98;
static constexpr int LDBA = DRA + 2 * NS;   // 39
static constexpr int LDBC = DRC + 2 * NS;   // 160

static constexpr int SPLITK_SC   = 4;
static constexpr int SPLITK_XPC  = 8;
static constexpr int SPLITK_COUT = 2;

// padded K sizes (multiples of 32) for plane GEMMs
static constexpr int KP_SC  = 128;   // 98 -> 128
static constexpr int KP_A   = 224;   // 196 -> 224
static constexpr int KP_DTA = 32;    // 7 -> 32

// ---------------- fp32 scratch arena ----------------
static constexpr size_t SZ_SC1   = (size_t)B_ * K_ * N_;
static constexpr size_t SZ_SCP   = (size_t)SPLITK_SC * SZ_SC1;
static constexpr size_t SZ_XZA   = (size_t)B_ * K_ * 2 * DIA;
static constexpr size_t SZ_XIA   = (size_t)B_ * K_ * DIA;
static constexpr size_t SZ_XDBLA = (size_t)B_ * K_ * LDBA;
static constexpr size_t SZ_DTA   = (size_t)B_ * K_ * DIA;
static constexpr size_t SZ_YA    = (size_t)B_ * K_ * DIA;
static constexpr size_t SZ_SC2   = (size_t)B_ * K_ * N_;
static constexpr size_t SZ_S     = (size_t)B_ * K_;
static constexpr size_t SZ_XZC   = (size_t)B_ * LC * 2 * DIC;
static constexpr size_t SZ_XIC   = (size_t)B_ * LC * DIC;
static constexpr size_t SZ_XDBLC = (size_t)B_ * LC * LDBC;
static constexpr size_t SZ_XPCP  = (size_t)SPLITK_XPC * B_ * LC * LDBC;
static constexpr size_t SZ_DTC   = (size_t)B_ * LC * DIC;
static constexpr size_t SZ_YC    = (size_t)B_ * LC * DIC;
static constexpr size_t SZ_OUTP  = (size_t)SPLITK_COUT * B_ * LC * DM_;

static constexpr size_t OFF_SCP   = 0;
static constexpr size_t OFF_XZA   = OFF_SCP + SZ_SCP;
static constexpr size_t OFF_XIA   = OFF_XZA + SZ_XZA;
static constexpr size_t OFF_XDBLA = OFF_XIA + SZ_XIA;
static constexpr size_t OFF_DTA   = OFF_XDBLA + SZ_XDBLA;
static constexpr size_t OFF_YA    = OFF_DTA + SZ_DTA;
static constexpr size_t OFF_SC2   = OFF_YA + SZ_YA;
static constexpr size_t OFF_S     = OFF_SC2 + SZ_SC2;
static constexpr size_t OFF_XZC   = OFF_S + SZ_S;
static constexpr size_t OFF_XIC   = OFF_XZC + SZ_XZC;
static constexpr size_t OFF_XDBLC = OFF_XIC + SZ_XIC;
static constexpr size_t OFF_XPCP  = OFF_XDBLC + SZ_XDBLC;
static constexpr size_t OFF_DTC   = OFF_XPCP + SZ_XPCP;
static constexpr size_t OFF_YC    = OFF_DTC + SZ_DTC;
static constexpr size_t OFF_OUTP  = OFF_YC + SZ_YC;
static constexpr size_t SCRATCH_TOTAL = OFF_OUTP + SZ_OUTP;

__device__ float g_scratch[SCRATCH_TOTAL];
__device__ int   g_ind[B_ * N_];
__device__ float g_vtop[B_ * N_];

// ---------------- bf16 hi/lo plane arena (u16, 16B-aligned) ----------------
static constexpr size_t BSZ_KFT    = (size_t)B_ * K_ * DM_;       // [b][l][2048]
static constexpr size_t BSZ_IMF    = (size_t)N_ * DM_;            // [98][2048]
static constexpr size_t BSZ_CINW   = (size_t)(2 * DIC) * DM_;     // [8192][2048]
static constexpr size_t BSZ_COUTW  = (size_t)DM_ * DIC;           // [2048][4096]
static constexpr size_t BSZ_H      = (size_t)B_ * LC * DM_;       // [784][2048]
static constexpr size_t BSZ_YC     = (size_t)B_ * LC * DIC;       // [784][4096]
static constexpr size_t BSZ_SCPL   = (size_t)B_ * K_ * KP_SC;     // [8192][128]
static constexpr size_t BSZ_AINW   = (size_t)(2 * DIA) * KP_SC;   // [392][128]
static constexpr size_t BSZ_XIA    = (size_t)B_ * K_ * KP_A;      // [8192][224]
static constexpr size_t BSZ_AXPW   = (size_t)LDBA * KP_A;         // [39][224]
static constexpr size_t BSZ_DTAIN  = (size_t)B_ * K_ * KP_DTA;    // [8192][32]
static constexpr size_t BSZ_ADTW   = (size_t)DIA * KP_DTA;        // [196][32]
static constexpr size_t BSZ_YA     = (size_t)B_ * K_ * KP_A;      // [8192][224]
static constexpr size_t BSZ_AOUTW  = (size_t)N_ * KP_A;           // [98][224]
static constexpr size_t BSZ_XIC    = (size_t)B_ * LC * DIC;       // [784][4096]
static constexpr size_t BSZ_CXPW   = (size_t)LDBC * DIC;          // [160][4096]
static constexpr size_t BSZ_XDBLCP = (size_t)B_ * LC * LDBC;      // [784][160]
static constexpr size_t BSZ_CDTW   = (size_t)DIC * DRC;           // [4096][128]

static constexpr size_t BO_KFT_HI    = 0;
static constexpr size_t BO_KFT_LO    = BO_KFT_HI + BSZ_KFT;
static constexpr size_t BO_IMF_HI    = BO_KFT_LO + BSZ_KFT;
static constexpr size_t BO_IMF_LO    = BO_IMF_HI + BSZ_IMF;
static constexpr size_t BO_CINW_HI   = BO_IMF_LO + BSZ_IMF;
static constexpr size_t BO_CINW_LO   = BO_CINW_HI + BSZ_CINW;
static constexpr size_t BO_COUTW_HI  = BO_CINW_LO + BSZ_CINW;
static constexpr size_t BO_COUTW_LO  = BO_COUTW_HI + BSZ_COUTW;
static constexpr size_t BO_H_HI      = BO_COUTW_LO + BSZ_COUTW;
static constexpr size_t BO_H_LO      = BO_H_HI + BSZ_H;
static constexpr size_t BO_YC_HI     = BO_H_LO + BSZ_H;
static constexpr size_t BO_YC_LO     = BO_YC_HI + BSZ_YC;
static constexpr size_t BO_SCPL_HI   = BO_YC_LO + BSZ_YC;
static constexpr size_t BO_SCPL_LO   = BO_SCPL_HI + BSZ_SCPL;
static constexpr size_t BO_AINW_HI   = BO_SCPL_LO + BSZ_SCPL;
static constexpr size_t BO_AINW_LO   = BO_AINW_HI + BSZ_AINW;
static constexpr size_t BO_XIA_HI    = BO_AINW_LO + BSZ_AINW;
static constexpr size_t BO_XIA_LO    = BO_XIA_HI + BSZ_XIA;
static constexpr size_t BO_AXPW_HI   = BO_XIA_LO + BSZ_XIA;
static constexpr size_t BO_AXPW_LO   = BO_AXPW_HI + BSZ_AXPW;
static constexpr size_t BO_DTAIN_HI  = BO_AXPW_LO + BSZ_AXPW;
static constexpr size_t BO_DTAIN_LO  = BO_DTAIN_HI + BSZ_DTAIN;
static constexpr size_t BO_ADTW_HI   = BO_DTAIN_LO + BSZ_DTAIN;
static constexpr size_t BO_ADTW_LO   = BO_ADTW_HI + BSZ_ADTW;
static constexpr size_t BO_YA_HI     = BO_ADTW_LO + BSZ_ADTW;
static constexpr size_t BO_YA_LO     = BO_YA_HI + BSZ_YA;
static constexpr size_t BO_AOUTW_HI  = BO_YA_LO + BSZ_YA;
static constexpr size_t BO_AOUTW_LO  = BO_AOUTW_HI + BSZ_AOUTW;
static constexpr size_t BO_XIC_HI    = BO_AOUTW_LO + BSZ_AOUTW;
static constexpr size_t BO_XIC_LO    = BO_XIC_HI + BSZ_XIC;
static constexpr size_t BO_CXPW_HI   = BO_XIC_LO + BSZ_XIC;
static constexpr size_t BO_CXPW_LO   = BO_CXPW_HI + BSZ_CXPW;
static constexpr size_t BO_XDBLCP_HI = BO_CXPW_LO + BSZ_CXPW;
static constexpr size_t BO_XDBLCP_LO = BO_XDBLCP_HI + BSZ_XDBLCP;
static constexpr size_t BO_CDTW_HI   = BO_XDBLCP_LO + BSZ_XDBLCP;
static constexpr size_t BO_CDTW_LO   = BO_CDTW_HI + BSZ_CDTW;
static constexpr size_t BF_TOTAL     = BO_CDTW_LO + BSZ_CDTW;

__device__ __align__(16) unsigned short g_bf[BF_TOTAL];

// ---------------- helpers ----------------
__device__ __forceinline__ float siluf(float x) { return x / (1.f + __expf(-x)); }
__device__ __forceinline__ float softplusf(float x) {
    return x > 20.f ? x : log1pf(__expf(x));
}
static inline int ceil_div(int a, int b) { return (a + b - 1) / b; }

__device__ __forceinline__ void ldsm_x4(uint32_t (&r)[4], uint32_t addr) {
    asm volatile("ldmatrix.sync.aligned.m8n8.x4.shared.b16 {%0,%1,%2,%3}, [%4];"
                 : "=r"(r[0]), "=r"(r[1]), "=r"(r[2]), "=r"(r[3]) : "r"(addr));
}
__device__ __forceinline__ void mma_bf16(float (&d)[4], const uint32_t (&a)[4],
                                         uint32_t b0, uint32_t b1) {
    asm volatile("mma.sync.aligned.m16n8k16.row.col.f32.bf16.bf16.f32 "
                 "{%0,%1,%2,%3}, {%4,%5,%6,%7}, {%8,%9}, {%0,%1,%2,%3};"
                 : "+f"(d[0]), "+f"(d[1]), "+f"(d[2]), "+f"(d[3])
                 : "r"(a[0]), "r"(a[1]), "r"(a[2]), "r"(a[3]), "r"(b0), "r"(b1));
}
__device__ __forceinline__ void split_bf(float v, __nv_bfloat16& h, __nv_bfloat16& l) {
    h = __float2bfloat16(v);
    l = __float2bfloat16(v - __bfloat162float(h));
}
__device__ __forceinline__ void cpa16(uint32_t dst, const void* src) {
    asm volatile("cp.async.cg.shared.global [%0], [%1], 16;" :: "r"(dst), "l"(src));
}
__device__ __forceinline__ void store_split4(unsigned short* hi, unsigned short* lo,
                                             size_t i, const float* v) {
    __nv_bfloat16 h0, h1, h2, h3, l0, l1, l2, l3;
    split_bf(v[0], h0, l0); split_bf(v[1], h1, l1);
    split_bf(v[2], h2, l2); split_bf(v[3], h3, l3);
    __nv_bfloat162 a, b;
    a.x = h0; a.y = h1; b.x = h2; b.y = h3;
    *(__nv_bfloat162*)(hi + i)     = a;
    *(__nv_bfloat162*)(hi + i + 2) = b;
    a.x = l0; a.y = l1; b.x = l2; b.y = l3;
    *(__nv_bfloat162*)(lo + i)     = a;
    *(__nv_bfloat162*)(lo + i + 2) = b;
}

// ================================================================
//  gemm_bt:  C[M,N] = A[M,K] @ B[N,K]^T   (pre-split bf16 planes)
//  128x128 tile, K-chunks of 32, cp.async double buffer, 256 thr,
//  2 CTAs/SM. EPI: softplus(acc + bias[n]).
// ================================================================
static constexpr int BT_PL     = 128 * 40;
static constexpr int BT_PLB    = BT_PL * 2;           // 10240 B
static constexpr int BT_STAGEB = 4 * BT_PLB;          // 40960 B
static constexpr int BT_SMEM   = 2 * BT_STAGEB;       // 81920 B

template<bool EPI>
__global__ __launch_bounds__(256, 2) void gemm_bt(
    const unsigned short* __restrict__ Ahi, const unsigned short* __restrict__ Alo,
    const unsigned short* __restrict__ Bhi, const unsigned short* __restrict__ Blo,
    float* __restrict__ C, int ldc,
    int M, int N, int Ktot, int ldA, int ldB, int splitk,
    size_t batchA, size_t batchB, size_t batchC, size_t strideS,
    const float* __restrict__ bias)
{
    extern __shared__ __align__(16) unsigned short smem_bt[];
    const uint32_t sb = (uint32_t)__cvta_generic_to_shared(smem_bt);

    const int tid = threadIdx.x, lane = tid & 31, wid = tid >> 5;
    const int wm = (wid & 1) << 6;
    const int wn = (wid >> 1) << 5;
    const int row0 = blockIdx.y * 128;
    const int col0 = blockIdx.x * 128;

    const int z = blockIdx.z;
    const int bb = z / splitk;
    const int s  = z - bb * splitk;
    const unsigned short* Ah = Ahi + (size_t)bb * batchA;
    const unsigned short* Al = Alo + (size_t)bb * batchA;
    const unsigned short* Bh = Bhi + (size_t)bb * batchB;
    const unsigned short* Bl = Blo + (size_t)bb * batchB;
    float* Cb = C + (size_t)bb * batchC + (size_t)s * strideS;

    const int Kc = Ktot / splitk;
    const int kbeg = s * Kc;
    const int nch = Kc / 32;

    float acc[4][4][4];
#pragma unroll
    for (int i = 0; i < 4; i++)
#pragma unroll
        for (int j = 0; j < 4; j++)
#pragma unroll
            for (int q = 0; q < 4; q++) acc[i][j][q] = 0.f;

#define BT_LOAD(CC, BUF)                                                        \
    {                                                                           \
        const int kc0 = kbeg + (CC) * 32;                                       \
        const uint32_t st = sb + (BUF) * BT_STAGEB;                             \
        _Pragma("unroll")                                                       \
        for (int p = 0; p < 2; p++) {                                           \
            int idx = tid + p * 256;                                            \
            int row = idx >> 2, ch = idx & 3;                                   \
            uint32_t doff = (uint32_t)(row * 80 + ch * 16);                     \
            int ga = row0 + row;                                                \
            if (ga < M) {                                                       \
                size_t ao = (size_t)ga * ldA + kc0 + ch * 8;                    \
                cpa16(st + doff,          Ah + ao);                             \
                cpa16(st + BT_PLB + doff, Al + ao);                             \
            }                                                                   \
            int gb = col0 + row;                                                \
            if (gb < N) {                                                       \
                size_t bo = (size_t)gb * ldB + kc0 + ch * 8;                    \
                cpa16(st + 2 * BT_PLB + doff, Bh + bo);                         \
                cpa16(st + 3 * BT_PLB + doff, Bl + bo);                         \
            }                                                                   \
        }                                                                       \
        asm volatile("cp.async.commit_group;" ::: "memory");                    \
    }

#define BT_COMPUTE(BUF)                                                         \
    {                                                                           \
        const uint32_t pa_hi = sb + (BUF) * BT_STAGEB;                          \
        const uint32_t pa_lo = pa_hi + BT_PLB;                                  \
        const uint32_t pb_hi = pa_hi + 2 * BT_PLB;                              \
        const uint32_t pb_lo = pa_hi + 3 * BT_PLB;                              \
        const int lr = lane & 15, lc = (lane >> 4) << 3;                        \
        _Pragma("unroll")                                                       \
        for (int sub = 0; sub < 2; sub++) {                                     \
            const int kk0 = sub * 16;                                           \
            uint32_t bh[2][4], bl[2][4];                                        \
            _Pragma("unroll")                                                   \
            for (int g = 0; g < 2; g++) {                                       \
                uint32_t off = (uint32_t)(((wn + g * 16 + lr) * 40 + kk0 + lc) * 2); \
                ldsm_x4(bh[g], pb_hi + off);                                    \
                ldsm_x4(bl[g], pb_lo + off);                                    \
            }                                                                   \
            _Pragma("unroll")                                                   \
            for (int i = 0; i < 4; i++) {                                       \
                uint32_t ah[4], al[4];                                          \
                uint32_t offa = (uint32_t)(((wm + i * 16 + lr) * 40 + kk0 + lc) * 2); \
                ldsm_x4(ah, pa_hi + offa);                                      \
                ldsm_x4(al, pa_lo + offa);                                      \
                _Pragma("unroll")                                               \
                for (int j = 0; j < 4; j++) {                                   \
                    const int g = j >> 1, o = j & 1;                            \
                    mma_bf16(acc[i][j], ah, bh[g][o], bh[g][o + 2]);            \
                    mma_bf16(acc[i][j], ah, bl[g][o], bl[g][o + 2]);            \
                    mma_bf16(acc[i][j], al, bh[g][o], bh[g][o + 2]);            \
                }                                                               \
            }                                                                   \
        }                                                                       \
    }

    BT_LOAD(0, 0);
    int buf = 0;
    for (int c = 0; c < nch; c++) {
        const bool more = (c + 1) < nch;
        if (more) { BT_LOAD(c + 1, buf ^ 1); }
        if (more) asm volatile("cp.async.wait_group 1;" ::: "memory");
        else      asm volatile("cp.async.wait_group 0;" ::: "memory");
        __syncthreads();
        BT_COMPUTE(buf);
        __syncthreads();
        buf ^= 1;
    }

    const int er = lane >> 2;
    const int ec = (lane & 3) * 2;
#pragma unroll
    for (int i = 0; i < 4; i++) {
#pragma unroll
        for (int j = 0; j < 4; j++) {
            int gm0 = row0 + wm + i * 16 + er;
            int gn  = col0 + wn + j * 8 + ec;
            if (gn >= N) continue;
            float v0 = acc[i][j][0], v1 = acc[i][j][1];
            float v2 = acc[i][j][2], v3 = acc[i][j][3];
            if (EPI) {
                float b0 = bias[gn];
                float b1 = (gn + 1 < N) ? bias[gn + 1] : 0.f;
                v0 = softplusf(v0 + b0); v1 = softplusf(v1 + b1);
                v2 = softplusf(v2 + b0); v3 = softplusf(v3 + b1);
            }
            if (gm0 < M) {
                Cb[(size_t)gm0 * ldc + gn] = v0;
                if (gn + 1 < N) Cb[(size_t)gm0 * ldc + gn + 1] = v1;
            }
            int gm1 = gm0 + 8;
            if (gm1 < M) {
                Cb[(size_t)gm1 * ldc + gn] = v2;
                if (gn + 1 < N) Cb[(size_t)gm1 * ldc + gn + 1] = v3;
            }
        }
    }
#undef BT_LOAD
#undef BT_COMPUTE
}

// ---------------- guarded transpose-split: W[Ksrc,Nd] -> planes [Nd,Kd] ----------------
__global__ void tsplit_kernel(const float* __restrict__ w,
                              unsigned short* __restrict__ hi,
                              unsigned short* __restrict__ lo,
                              int Ksrc, int Nd, int Kd,
                              size_t wBatch, size_t oBatch)
{
    __shared__ float t[32][33];
    int n0 = blockIdx.x * 32, k0 = blockIdx.y * 32;
    const float* wb = w + (size_t)blockIdx.z * wBatch;
    unsigned short* hib = hi + (size_t)blockIdx.z * oBatch;
    unsigned short* lob = lo + (size_t)blockIdx.z * oBatch;
    int tx = threadIdx.x & 31, ty = threadIdx.x >> 5;
#pragma unroll
    for (int i = 0; i < 32; i += 8) {
        int kk = k0 + ty + i, nn = n0 + tx;
        t[ty + i][tx] = (kk < Ksrc && nn < Nd) ? wb[(size_t)kk * Nd + nn] : 0.f;
    }
    __syncthreads();
#pragma unroll
    for (int p = 0; p < 2; p++) {
        int q = threadIdx.x + p * 256;
        int n = q >> 4;
        int kp = q & 15;
        if (n0 + n >= Nd) continue;
        float v0 = t[2 * kp][n], v1 = t[2 * kp + 1][n];
        __nv_bfloat16 h0, l0, h1, l1;
        split_bf(v0, h0, l0); split_bf(v1, h1, l1);
        size_t off = (size_t)(n0 + n) * Kd + k0 + 2 * kp;
        __nv_bfloat162 hh; hh.x = h0; hh.y = h1;
        *(__nv_bfloat162*)(hib + off) = hh;
        __nv_bfloat162 ll; ll.x = l0; ll.y = l1;
        *(__nv_bfloat162*)(lob + off) = ll;
    }
}

// ---------------- general row split with pad (+optional silu(z)) ----------------
template<bool SILU>
__global__ void split_pad_kernel(const float* __restrict__ x, int ldx, int Ksrc,
                                 const float* __restrict__ z, int ldz,
                                 unsigned short* __restrict__ hi,
                                 unsigned short* __restrict__ lo,
                                 int Kd, int total4)
{
    int t = blockIdx.x * blockDim.x + threadIdx.x;
    if (t >= total4) return;
    size_t i4 = (size_t)t * 4;
    int row = (int)(i4 / Kd), k = (int)(i4 - (size_t)row * Kd);
    float v[4];
#pragma unroll
    for (int e = 0; e < 4; e++) {
        int kk = k + e;
        float val = 0.f;
        if (kk < Ksrc) {
            val = x[(size_t)row * ldx + kk];
            if (SILU) val *= siluf(z[(size_t)row * ldz + kk]);
        }
        v[e] = val;
    }
    store_split4(hi, lo, i4, v);
}

// ---------------- split-K reduce + split (+optional fp32 out) ----------------
__global__ void reduce_split_kernel(const float* __restrict__ part, int ldp, size_t stride,
                                    int ns, float* __restrict__ fout,
                                    unsigned short* __restrict__ hi,
                                    unsigned short* __restrict__ lo,
                                    int Kd, int total4)
{
    int t = blockIdx.x * blockDim.x + threadIdx.x;
    if (t >= total4) return;
    size_t i4 = (size_t)t * 4;
    int row = (int)(i4 / Kd), k = (int)(i4 - (size_t)row * Kd);
    float v[4];
#pragma unroll
    for (int e = 0; e < 4; e++) {
        int kk = k + e;
        float a = 0.f;
        if (kk < ldp) {
            size_t off = (size_t)row * ldp + kk;
            for (int s = 0; s < ns; s++) a += part[(size_t)s * stride + off];
            if (fout) fout[off] = a;
        }
        v[e] = a;
    }
    store_split4(hi, lo, i4, v);
}

// ---------------- plain fixed-order split-K reduction (final out) ----------------
__global__ void reduce_sum_kernel(const float* __restrict__ part, float* __restrict__ out,
                                  int total, size_t stride, int ns)
{
    int i = blockIdx.x * blockDim.x + threadIdx.x;
    if (i >= total) return;
    float a = 0.f;
    for (int s = 0; s < ns; s++) a += part[(size_t)s * stride + i];
    out[i] = a;
}

// ---------------- depthwise causal conv (k=4) + silu -> fp32 + planes ----------------
__global__ void conv_silu_kernel(const float* __restrict__ xz, int ldxz,
                                 const float* __restrict__ w, const float* __restrict__ bias,
                                 float* __restrict__ xi,
                                 unsigned short* __restrict__ hi,
                                 unsigned short* __restrict__ lo,
                                 int Bn, int L, int dinner, int Kd, int total4)
{
    int t = blockIdx.x * blockDim.x + threadIdx.x;
    if (t >= total4) return;
    size_t i4 = (size_t)t * 4;
    int ch = (int)(i4 % Kd);
    int l  = (int)((i4 / Kd) % L);
    int b  = (int)(i4 / ((size_t)Kd * L));
    size_t rowd = (size_t)b * L + l;
    if (ch >= dinner) {
        float zv[4] = {0.f, 0.f, 0.f, 0.f};
        store_split4(hi, lo, rowd * Kd + ch, zv);
        return;
    }
    const float* x0 = xz + rowd * ldxz - (size_t)l * ldxz + (size_t)l * ldxz + ch; // = row base + ch
    const float* xb = xz + ((size_t)b * L) * ldxz + ch;

    float4 acc = *(const float4*)(bias + ch);
    float4 w0 = *(const float4*)(w + (ch + 0) * 4);
    float4 w1 = *(const float4*)(w + (ch + 1) * 4);
    float4 w2 = *(const float4*)(w + (ch + 2) * 4);
    float4 w3 = *(const float4*)(w + (ch + 3) * 4);
    (void)x0;

    float4 xx = *(const float4*)(xb + (size_t)l * ldxz);
    acc.x = fmaf(w0.w, xx.x, acc.x);
    acc.y = fmaf(w1.w, xx.y, acc.y);
    acc.z = fmaf(w2.w, xx.z, acc.z);
    acc.w = fmaf(w3.w, xx.w, acc.w);
    if (l >= 1) {
        float4 xm = *(const float4*)(xb + (size_t)(l - 1) * ldxz);
        acc.x = fmaf(w0.z, xm.x, acc.x);
        acc.y = fmaf(w1.z, xm.y, acc.y);
        acc.z = fmaf(w2.z, xm.z, acc.z);
        acc.w = fmaf(w3.z, xm.w, acc.w);
    }
    if (l >= 2) {
        float4 xm = *(const float4*)(xb + (size_t)(l - 2) * ldxz);
        acc.x = fmaf(w0.y, xm.x, acc.x);
        acc.y = fmaf(w1.y, xm.y, acc.y);
        acc.z = fmaf(w2.y, xm.z, acc.z);
        acc.w = fmaf(w3.y, xm.w, acc.w);
    }
    if (l >= 3) {
        float4 xm = *(const float4*)(xb + (size_t)(l - 3) * ldxz);
        acc.x = fmaf(w0.x, xm.x, acc.x);
        acc.y = fmaf(w1.x, xm.y, acc.y);
        acc.z = fmaf(w2.x, xm.z, acc.z);
        acc.w = fmaf(w3.x, xm.w, acc.w);
    }
    acc.x = siluf(acc.x); acc.y = siluf(acc.y);
    acc.z = siluf(acc.z); acc.w = siluf(acc.w);
    *(float4*)(xi + rowd * dinner + ch) = acc;
    float v[4] = {acc.x, acc.y, acc.z, acc.w};
    store_split4(hi, lo, rowd * Kd + ch, v);
}

// ---------------- selective scan ----------------
template<int TCH>
__global__ void scan_kernel(const float* __restrict__ u, const float* __restrict__ dt,
                            const float* __restrict__ xdbl, int ld_dbl, int boff, int coff,
                            const float* __restrict__ A_log, const float* __restrict__ Dp,
                            float* __restrict__ y, int Bn, int L, int dinner)
{
    int gwarp = (blockIdx.x * blockDim.x + threadIdx.x) >> 5;
    int lane  = threadIdx.x & 31;
    int half  = lane >> 4;
    int n     = lane & 15;
    int gd    = gwarp * 2 + half;
    if (gd >= Bn * dinner) return;
    int b   = gd / dinner;
    int dch = gd - b * dinner;

    float a  = -__expf(A_log[dch * NS + n]);
    float Dv = Dp[dch];
    float h  = 0.f;

    const float* urow  = u    + (size_t)b * L * dinner + dch;
    const float* dtrow = dt   + (size_t)b * L * dinner + dch;
    const float* brow  = xdbl + (size_t)b * L * ld_dbl + boff + n;
    const float* crow  = xdbl + (size_t)b * L * ld_dbl + coff + n;
    float*       yrow  = y    + (size_t)b * L * dinner + dch;

    float vdt[2][TCH], vu[2][TCH], vB[2][TCH], vC[2][TCH];

#define SCAN_LOAD(BUF, T0)                                                      \
    _Pragma("unroll")                                                           \
    for (int tt = 0; tt < TCH; tt++) {                                          \
        size_t t = (size_t)((T0) + tt);                                         \
        vdt[BUF][tt] = dtrow[t * dinner];                                       \
        vu[BUF][tt]  = urow[t * dinner];                                        \
        vB[BUF][tt]  = brow[t * ld_dbl];                                        \
        vC[BUF][tt]  = crow[t * ld_dbl];                                        \
    }

#define SCAN_COMPUTE(BUF, T0)                                                   \
    {                                                                           \
        float p[TCH];                                                           \
        _Pragma("unroll")                                                       \
        for (int tt = 0; tt < TCH; tt++) {                                      \
            float dA = __expf(vdt[BUF][tt] * a);                                \
            h = fmaf(dA, h, vdt[BUF][tt] * vB[BUF][tt] * vu[BUF][tt]);          \
            p[tt] = h * vC[BUF][tt] + ((n == 0) ? vu[BUF][tt] * Dv : 0.f);      \
        }                                                                       \
        _Pragma("unroll")                                                       \
        for (int tt = 0; tt < TCH; tt++) p[tt] += __shfl_xor_sync(0xffffffffu, p[tt], 8); \
        _Pragma("unroll")                                                       \
        for (int tt = 0; tt < TCH; tt++) p[tt] += __shfl_xor_sync(0xffffffffu, p[tt], 4); \
        _Pragma("unroll")                                                       \
        for (int tt = 0; tt < TCH; tt++) p[tt] += __shfl_xor_sync(0xffffffffu, p[tt], 2); \
        _Pragma("unroll")                                                       \
        for (int tt = 0; tt < TCH; tt++) p[tt] += __shfl_xor_sync(0xffffffffu, p[tt], 1); \
        _Pragma("unroll")                                                       \
        for (int tt = 0; tt < TCH; tt++)                                        \
            if (n == tt) yrow[(size_t)((T0) + tt) * dinner] = p[tt];            \
    }

    const int nch = L / TCH;
    SCAN_LOAD(0, 0);
    for (int c = 0; c < nch; c += 2) {
        if (c + 1 < nch) SCAN_LOAD(1, (c + 1) * TCH);
        SCAN_COMPUTE(0, c * TCH);
        if (c + 1 < nch) {
            if (c + 2 < nch) SCAN_LOAD(0, (c + 2) * TCH);
            SCAN_COMPUTE(1, (c + 1) * TCH);
        }
    }
#undef SCAN_LOAD
#undef SCAN_COMPUTE
}

// ---------------- mean over N_ : one warp per row ----------------
__global__ void mean_kernel(const float* __restrict__ sc2, float* __restrict__ sbuf)
{
    int gw = (blockIdx.x * blockDim.x + threadIdx.x) >> 5;
    int lane = threadIdx.x & 31;
    if (gw >= B_ * K_) return;
    const float* row = sc2 + (size_t)gw * N_;
    float a = 0.f;
    for (int i = lane; i < N_; i += 32) a += row[i];
#pragma unroll
    for (int o = 16; o; o >>= 1) a += __shfl_xor_sync(0xffffffffu, a, o);
    if (lane == 0) sbuf[gw] = a / (float)N_;
}

// ---------------- softmax over K_ per batch ----------------
__global__ void softmax_kernel(float* __restrict__ s)
{
    __shared__ float red[32];
    int b = blockIdx.x, tid = threadIdx.x;
    int lane = tid & 31, w = tid >> 5;
    float v = s[(size_t)b * K_ + tid];
    float m = v;
#pragma unroll
    for (int o = 16; o; o >>= 1) m = fmaxf(m, __shfl_xor_sync(0xffffffffu, m, o));
    if (lane == 0) red[w] = m;
    __syncthreads();
    if (tid < 32) {
        float t = red[tid];
#pragma unroll
        for (int o = 16; o; o >>= 1) t = fmaxf(t, __shfl_xor_sync(0xffffffffu, t, o));
        if (tid == 0) red[0] = t;
    }
    __syncthreads();
    m = red[0];
    __syncthreads();
    float e = __expf(v - m);
    float sum = e;
#pragma unroll
    for (int o = 16; o; o >>= 1) sum += __shfl_xor_sync(0xffffffffu, sum, o);
    if (lane == 0) red[w] = sum;
    __syncthreads();
    if (tid < 32) {
        float t = red[tid];
#pragma unroll
        for (int o = 16; o; o >>= 1) t += __shfl_xor_sync(0xffffffffu, t, o);
        if (tid == 0) red[0] = t;
    }
    __syncthreads();
    s[(size_t)b * K_ + tid] = e / red[0];
}

// ---------------- top-k(98 of 1024) bitonic ----------------
__global__ void topk_kernel(const float* __restrict__ s, int* __restrict__ ind,
                            float* __restrict__ vtop)
{
    __shared__ float sv[K_];
    __shared__ int   si[K_];
    int b = blockIdx.x, tid = threadIdx.x;
    for (int i = tid; i < K_; i += 256) { sv[i] = s[(size_t)b * K_ + i]; si[i] = i; }
    __syncthreads();
    for (int k = 2; k <= K_; k <<= 1) {
        for (int j = k >> 1; j > 0; j >>= 1) {
            for (int i = tid; i < K_; i += 256) {
                int ixj = i ^ j;
                if (ixj > i) {
                    float v1 = sv[i], v2 = sv[ixj];
                    int   i1 = si[i], i2 = si[ixj];
                    bool lt_ji = (v2 > v1) || (v2 == v1 && i2 < i1);
                    bool lt_ij = (v1 > v2) || (v1 == v2 && i1 < i2);
                    bool asc = ((i & k) == 0);
                    if (asc ? lt_ji : lt_ij) {
                        sv[i] = v2; sv[ixj] = v1;
                        si[i] = i2; si[ixj] = i1;
                    }
                }
            }
            __syncthreads();
        }
    }
    for (int i = tid; i < N_; i += 256) {
        ind[b * N_ + i]  = si[i];
        vtop[b * N_ + i] = sv[i];
    }
}

// ---------------- h planes = split(imageFeature + gather(kf) * vtop) ----------------
__global__ void build_h_kernel(const float* __restrict__ imf, const float* __restrict__ kf,
                               const int* __restrict__ ind, const float* __restrict__ vtop,
                               unsigned short* __restrict__ hhi,
                               unsigned short* __restrict__ hlo)
{
    int idx = blockIdx.x * blockDim.x + threadIdx.x;
    int total = B_ * LC * DM_;
    if (idx >= total) return;
    int d = idx % DM_;
    int j = (idx / DM_) % LC;
    int b = idx / (DM_ * LC);
    int r = ind[b * N_ + j];
    float v = imf[(size_t)j * DM_ + d] +
              kf[((size_t)b * DM_ + d) * K_ + r] * vtop[b * N_ + j];
    __nv_bfloat16 h, l;
    split_bf(v, h, l);
    hhi[idx] = __bfloat16_as_ushort(h);
    hlo[idx] = __bfloat16_as_ushort(l);
}

// ---------------- host ----------------
extern "C" void kernel_launch(void* const* d_in, const int* in_sizes, int n_in,
                              void* d_out, int out_size)
{
    const float* imf      = (const float*)d_in[0];
    const float* kf       = (const float*)d_in[1];
    const float* a_in_w   = (const float*)d_in[2];
    const float* a_conv_w = (const float*)d_in[3];
    const float* a_conv_b = (const float*)d_in[4];
    const float* a_xproj_w= (const float*)d_in[5];
    const float* a_dt_w   = (const float*)d_in[6];
    const float* a_dt_b   = (const float*)d_in[7];
    const float* a_A_log  = (const float*)d_in[8];
    const float* a_D      = (const float*)d_in[9];
    const float* a_out_w  = (const float*)d_in[10];
    const float* c_in_w   = (const float*)d_in[11];
    const float* c_conv_w = (const float*)d_in[12];
    const float* c_conv_b = (const float*)d_in[13];
    const float* c_xproj_w= (const float*)d_in[14];
    const float* c_dt_w   = (const float*)d_in[15];
    const float* c_dt_b   = (const float*)d_in[16];
    const float* c_A_log  = (const float*)d_in[17];
    const float* c_D      = (const float*)d_in[18];
    const float* c_out_w  = (const float*)d_in[19];
    float* out = (float*)d_out;

    cudaFuncSetAttribute((const void*)gemm_bt<false>, cudaFuncAttributeMaxDynamicSharedMemorySize, BT_SMEM);
    cudaFuncSetAttribute((const void*)gemm_bt<true>,  cudaFuncAttributeMaxDynamicSharedMemorySize, BT_SMEM);

    float* sc = nullptr;
    cudaGetSymbolAddress((void**)&sc, g_scratch);
    unsigned short* bf = nullptr;
    cudaGetSymbolAddress((void**)&bf, g_bf);
    int*   p_ind  = nullptr;
    float* p_vtop = nullptr;
    cudaGetSymbolAddress((void**)&p_ind, g_ind);
    cudaGetSymbolAddress((void**)&p_vtop, g_vtop);

    float* scp    = sc + OFF_SCP;
    float* xza    = sc + OFF_XZA;
    float* xia    = sc + OFF_XIA;
    float* xdbla  = sc + OFF_XDBLA;
    float* dta    = sc + OFF_DTA;
    float* ya     = sc + OFF_YA;
    float* sc2    = sc + OFF_SC2;
    float* sbuf   = sc + OFF_S;
    float* xzc    = sc + OFF_XZC;
    float* xic    = sc + OFF_XIC;
    float* xdblc  = sc + OFF_XDBLC;
    float* xpcp   = sc + OFF_XPCP;
    float* dtc    = sc + OFF_DTC;
    float* yc     = sc + OFF_YC;
    float* outp   = sc + OFF_OUTP;

    const int Ma = B_ * K_;   // 8192
    const int Mc = B_ * LC;   // 784

    // ---- weight/input prepasses (transpose-split to K-contig planes) ----
    tsplit_kernel<<<dim3((2 * DIC) / 32, DM_ / 32, 1), 256>>>(
        c_in_w, bf + BO_CINW_HI, bf + BO_CINW_LO, DM_, 2 * DIC, DM_, 0, 0);
    tsplit_kernel<<<dim3(DM_ / 32, DIC / 32, 1), 256>>>(
        c_out_w, bf + BO_COUTW_HI, bf + BO_COUTW_LO, DIC, DM_, DIC, 0, 0);
    tsplit_kernel<<<dim3(K_ / 32, DM_ / 32, B_), 256>>>(
        kf, bf + BO_KFT_HI, bf + BO_KFT_LO, DM_, K_, DM_,
        (size_t)DM_ * K_, (size_t)K_ * DM_);
    tsplit_kernel<<<dim3(ceil_div(2 * DIA, 32), KP_SC / 32, 1), 256>>>(
        a_in_w, bf + BO_AINW_HI, bf + BO_AINW_LO, N_, 2 * DIA, KP_SC, 0, 0);
    tsplit_kernel<<<dim3(ceil_div(LDBA, 32), KP_A / 32, 1), 256>>>(
        a_xproj_w, bf + BO_AXPW_HI, bf + BO_AXPW_LO, DIA, LDBA, KP_A, 0, 0);
    tsplit_kernel<<<dim3(ceil_div(DIA, 32), KP_DTA / 32, 1), 256>>>(
        a_dt_w, bf + BO_ADTW_HI, bf + BO_ADTW_LO, DRA, DIA, KP_DTA, 0, 0);
    tsplit_kernel<<<dim3(ceil_div(N_, 32), KP_A / 32, 1), 256>>>(
        a_out_w, bf + BO_AOUTW_HI, bf + BO_AOUTW_LO, DIA, N_, KP_A, 0, 0);
    tsplit_kernel<<<dim3(ceil_div(LDBC, 32), DIC / 32, 1), 256>>>(
        c_xproj_w, bf + BO_CXPW_HI, bf + BO_CXPW_LO, DIC, LDBC, DIC, 0, 0);
    tsplit_kernel<<<dim3(DIC / 32, DRC / 32, 1), 256>>>(
        c_dt_w, bf + BO_CDTW_HI, bf + BO_CDTW_LO, DRC, DIC, DRC, 0, 0);
    split_pad_kernel<false><<<ceil_div((int)(BSZ_IMF / 4), 256), 256>>>(
        imf, DM_, DM_, nullptr, 0, bf + BO_IMF_HI, bf + BO_IMF_LO, DM_, (int)(BSZ_IMF / 4));

    // 0: score[b][l][n] = kfT[b] @ imf^T  (split-K=4) -> partials -> planes (98->128 pad)
    gemm_bt<false><<<dim3(1, K_ / 128, B_ * SPLITK_SC), 256, BT_SMEM>>>(
        bf + BO_KFT_HI, bf + BO_KFT_LO, bf + BO_IMF_HI, bf + BO_IMF_LO,
        scp, N_, K_, N_, DM_, DM_, DM_, SPLITK_SC,
        (size_t)K_ * DM_, 0, (size_t)K_ * N_, SZ_SC1, nullptr);
    reduce_split_kernel<<<ceil_div(Ma * KP_SC / 4, 256), 256>>>(
        scp, N_, SZ_SC1, SPLITK_SC, nullptr,
        bf + BO_SCPL_HI, bf + BO_SCPL_LO, KP_SC, Ma * KP_SC / 4);

    // 1: xza = score @ a_in_w   (K=128 padded planes)
    gemm_bt<false><<<dim3(ceil_div(2 * DIA, 128), Ma / 128, 1), 256, BT_SMEM>>>(
        bf + BO_SCPL_HI, bf + BO_SCPL_LO, bf + BO_AINW_HI, bf + BO_AINW_LO,
        xza, 2 * DIA, Ma, 2 * DIA, KP_SC, KP_SC, KP_SC, 1, 0, 0, 0, 0, nullptr);

    // 2: conv + silu (a) -> fp32 xia + planes [8192,224]
    conv_silu_kernel<<<ceil_div(Ma * KP_A / 4, 256), 256>>>(
        xza, 2 * DIA, a_conv_w, a_conv_b, xia,
        bf + BO_XIA_HI, bf + BO_XIA_LO, B_, LA, DIA, KP_A, Ma * KP_A / 4);

    // 3: x_dbl = xi @ a_xproj_w
    gemm_bt<false><<<dim3(1, Ma / 128, 1), 256, BT_SMEM>>>(
        bf + BO_XIA_HI, bf + BO_XIA_LO, bf + BO_AXPW_HI, bf + BO_AXPW_LO,
        xdbla, LDBA, Ma, LDBA, KP_A, KP_A, KP_A, 1, 0, 0, 0, 0, nullptr);

    // 4: dt-in planes = xdbla[:, :7] (pad 32); dt = softplus(dtin @ a_dt_w + b)
    split_pad_kernel<false><<<ceil_div(Ma * KP_DTA / 4, 256), 256>>>(
        xdbla, LDBA, DRA, nullptr, 0,
        bf + BO_DTAIN_HI, bf + BO_DTAIN_LO, KP_DTA, Ma * KP_DTA / 4);
    gemm_bt<true><<<dim3(ceil_div(DIA, 128), Ma / 128, 1), 256, BT_SMEM>>>(
        bf + BO_DTAIN_HI, bf + BO_DTAIN_LO, bf + BO_ADTW_HI, bf + BO_ADTW_LO,
        dta, DIA, Ma, DIA, KP_DTA, KP_DTA, KP_DTA, 1, 0, 0, 0, 0, a_dt_b);

    // 5: selective scan (a)
    scan_kernel<8><<<(B_ * DIA / 2 * 32) / 256, 256>>>(
        xia, dta, xdbla, LDBA, DRA, DRA + NS, a_A_log, a_D, ya, B_, LA, DIA);

    // 6: y planes = split(y * silu(z)); sc2 = y @ a_out_w
    split_pad_kernel<true><<<ceil_div(Ma * KP_A / 4, 256), 256>>>(
        ya, DIA, DIA, xza + DIA, 2 * DIA,
        bf + BO_YA_HI, bf + BO_YA_LO, KP_A, Ma * KP_A / 4);
    gemm_bt<false><<<dim3(1, Ma / 128, 1), 256, BT_SMEM>>>(
        bf + BO_YA_HI, bf + BO_YA_LO, bf + BO_AOUTW_HI, bf + BO_AOUTW_LO,
        sc2, N_, Ma, N_, KP_A, KP_A, KP_A, 1, 0, 0, 0, 0, nullptr);

    // 7-10: mean / softmax / topk / gather (fused split)
    mean_kernel<<<(B_ * K_ * 32) / 256, 256>>>(sc2, sbuf);
    softmax_kernel<<<B_, K_>>>(sbuf);
    topk_kernel<<<B_, 256>>>(sbuf, p_ind, p_vtop);
    build_h_kernel<<<ceil_div(B_ * LC * DM_, 256), 256>>>(
        imf, kf, p_ind, p_vtop, bf + BO_H_HI, bf + BO_H_LO);

    // 11: xzc = h @ c_in_w
    gemm_bt<false><<<dim3((2 * DIC) / 128, ceil_div(Mc, 128), 1), 256, BT_SMEM>>>(
        bf + BO_H_HI, bf + BO_H_LO, bf + BO_CINW_HI, bf + BO_CINW_LO,
        xzc, 2 * DIC, Mc, 2 * DIC, DM_, DM_, DM_, 1, 0, 0, 0, 0, nullptr);

    // 12: conv + silu (c) -> fp32 xic + planes [784,4096]
    conv_silu_kernel<<<ceil_div(Mc * DIC / 4, 256), 256>>>(
        xzc, 2 * DIC, c_conv_w, c_conv_b, xic,
        bf + BO_XIC_HI, bf + BO_XIC_LO, B_, LC, DIC, DIC, Mc * DIC / 4);

    // 13: x_dbl partials = xi @ c_xproj_w (split-K=8) -> reduce+split (fp32 + planes)
    gemm_bt<false><<<dim3(ceil_div(LDBC, 128), ceil_div(Mc, 128), SPLITK_XPC), 256, BT_SMEM>>>(
        bf + BO_XIC_HI, bf + BO_XIC_LO, bf + BO_CXPW_HI, bf + BO_CXPW_LO,
        xpcp, LDBC, Mc, LDBC, DIC, DIC, DIC, SPLITK_XPC,
        0, 0, 0, (size_t)Mc * LDBC, nullptr);
    reduce_split_kernel<<<ceil_div(Mc * LDBC / 4, 256), 256>>>(
        xpcp, LDBC, (size_t)Mc * LDBC, SPLITK_XPC, xdblc,
        bf + BO_XDBLCP_HI, bf + BO_XDBLCP_LO, LDBC, Mc * LDBC / 4);

    // 14: dt = softplus(xdblc[:, :128] @ c_dt_w + b)   (ldA=160, Ktot=128)
    gemm_bt<true><<<dim3(DIC / 128, ceil_div(Mc, 128), 1), 256, BT_SMEM>>>(
        bf + BO_XDBLCP_HI, bf + BO_XDBLCP_LO, bf + BO_CDTW_HI, bf + BO_CDTW_LO,
        dtc, DIC, Mc, DIC, DRC, LDBC, DRC, 1, 0, 0, 0, 0, c_dt_b);

    // 15: selective scan (c)
    scan_kernel<7><<<(B_ * DIC / 2 * 32) / 256, 256>>>(
        xic, dtc, xdblc, LDBC, DRC, DRC + NS, c_A_log, c_D, yc, B_, LC, DIC);

    // 16: y planes = split(y * silu(z)); out partials (split-K=2)
    split_pad_kernel<true><<<ceil_div(Mc * DIC / 4, 256), 256>>>(
        yc, DIC, DIC, xzc + DIC, 2 * DIC,
        bf + BO_YC_HI, bf + BO_YC_LO, DIC, Mc * DIC / 4);
    gemm_bt<false><<<dim3(DM_ / 128, ceil_div(Mc, 128), SPLITK_COUT), 256, BT_SMEM>>>(
        bf + BO_YC_HI, bf + BO_YC_LO, bf + BO_COUTW_HI, bf + BO_COUTW_LO,
        outp, DM_, Mc, DM_, DIC, DIC, DIC, SPLITK_COUT,
        0, 0, 0, (size_t)Mc * DM_, nullptr);

    // 17: reduce -> out
    reduce_sum_kernel<<<ceil_div(Mc * DM_, 256), 256>>>(
        outp, out, Mc * DM_, (size_t)Mc * DM_, SPLITK_COUT);
}

// round 13
// speedup vs baseline: 3.0529x; 1.0127x over previous
#include <cuda_runtime.h>
#include <cuda_bf16.h>
#include <math.h>
#include <stdint.h>

// ---------------- problem constants ----------------
static constexpr int B_  = 8;
static constexpr int K_  = 1024;
static constexpr int N_  = 98;
static constexpr int DM_ = 2048;
static constexpr int DIA = 196;
static constexpr int DRA = 7;
static constexpr int DIC = 4096;
static constexpr int DRC = 128;
static constexpr int NS  = 16;
static constexpr int LA  = 1024;
static constexpr int LC  = 98;
static constexpr int LDBA = DRA + 2 * NS;   // 39
static constexpr int LDBC = DRC + 2 * NS;   // 160

static constexpr int SPLITK_SC   = 4;
static constexpr int SPLITK_XPC  = 8;
static constexpr int SPLITK_COUT = 2;

// padded K sizes (multiples of 32) for plane GEMMs
static constexpr int KP_SC  = 128;   // 98 -> 128
static constexpr int KP_A   = 224;   // 196 -> 224
static constexpr int KP_DTA = 32;    // 7 -> 32

// ---------------- fp32 scratch arena ----------------
static constexpr size_t SZ_SC1   = (size_t)B_ * K_ * N_;
static constexpr size_t SZ_SCP   = (size_t)SPLITK_SC * SZ_SC1;
static constexpr size_t SZ_XZA   = (size_t)B_ * K_ * 2 * DIA;
static constexpr size_t SZ_XIA   = (size_t)B_ * K_ * DIA;
static constexpr size_t SZ_XDBLA = (size_t)B_ * K_ * LDBA;
static constexpr size_t SZ_DTA   = (size_t)B_ * K_ * DIA;
static constexpr size_t SZ_YA    = (size_t)B_ * K_ * DIA;
static constexpr size_t SZ_SC2   = (size_t)B_ * K_ * N_;
static constexpr size_t SZ_S     = (size_t)B_ * K_;
static constexpr size_t SZ_XZC   = (size_t)B_ * LC * 2 * DIC;
static constexpr size_t SZ_XIC   = (size_t)B_ * LC * DIC;
static constexpr size_t SZ_XDBLC = (size_t)B_ * LC * LDBC;
static constexpr size_t SZ_XPCP  = (size_t)SPLITK_XPC * B_ * LC * LDBC;
static constexpr size_t SZ_DTC   = (size_t)B_ * LC * DIC;
static constexpr size_t SZ_YC    = (size_t)B_ * LC * DIC;
static constexpr size_t SZ_OUTP  = (size_t)SPLITK_COUT * B_ * LC * DM_;

static constexpr size_t OFF_SCP   = 0;
static constexpr size_t OFF_XZA   = OFF_SCP + SZ_SCP;
static constexpr size_t OFF_XIA   = OFF_XZA + SZ_XZA;
static constexpr size_t OFF_XDBLA = OFF_XIA + SZ_XIA;
static constexpr size_t OFF_DTA   = OFF_XDBLA + SZ_XDBLA;
static constexpr size_t OFF_YA    = OFF_DTA + SZ_DTA;
static constexpr size_t OFF_SC2   = OFF_YA + SZ_YA;
static constexpr size_t OFF_S     = OFF_SC2 + SZ_SC2;
static constexpr size_t OFF_XZC   = OFF_S + SZ_S;
static constexpr size_t OFF_XIC   = OFF_XZC + SZ_XZC;
static constexpr size_t OFF_XDBLC = OFF_XIC + SZ_XIC;
static constexpr size_t OFF_XPCP  = OFF_XDBLC + SZ_XDBLC;
static constexpr size_t OFF_DTC   = OFF_XPCP + SZ_XPCP;
static constexpr size_t OFF_YC    = OFF_DTC + SZ_DTC;
static constexpr size_t OFF_OUTP  = OFF_YC + SZ_YC;
static constexpr size_t SCRATCH_TOTAL = OFF_OUTP + SZ_OUTP;

__device__ float g_scratch[SCRATCH_TOTAL];
__device__ int   g_ind[B_ * N_];
__device__ float g_vtop[B_ * N_];

// ---------------- bf16 hi/lo plane arena (u16, 16B-aligned) ----------------
static constexpr size_t BSZ_KFT    = (size_t)B_ * K_ * DM_;
static constexpr size_t BSZ_IMF    = (size_t)N_ * DM_;
static constexpr size_t BSZ_CINW   = (size_t)(2 * DIC) * DM_;
static constexpr size_t BSZ_COUTW  = (size_t)DM_ * DIC;
static constexpr size_t BSZ_H      = (size_t)B_ * LC * DM_;
static constexpr size_t BSZ_YC     = (size_t)B_ * LC * DIC;
static constexpr size_t BSZ_SCPL   = (size_t)B_ * K_ * KP_SC;
static constexpr size_t BSZ_AINW   = (size_t)(2 * DIA) * KP_SC;
static constexpr size_t BSZ_XIA    = (size_t)B_ * K_ * KP_A;
static constexpr size_t BSZ_AXPW   = (size_t)LDBA * KP_A;
static constexpr size_t BSZ_DTAIN  = (size_t)B_ * K_ * KP_DTA;
static constexpr size_t BSZ_ADTW   = (size_t)DIA * KP_DTA;
static constexpr size_t BSZ_YA     = (size_t)B_ * K_ * KP_A;
static constexpr size_t BSZ_AOUTW  = (size_t)N_ * KP_A;
static constexpr size_t BSZ_XIC    = (size_t)B_ * LC * DIC;
static constexpr size_t BSZ_CXPW   = (size_t)LDBC * DIC;
static constexpr size_t BSZ_XDBLCP = (size_t)B_ * LC * LDBC;
static constexpr size_t BSZ_CDTW   = (size_t)DIC * DRC;

static constexpr size_t BO_KFT_HI    = 0;
static constexpr size_t BO_KFT_LO    = BO_KFT_HI + BSZ_KFT;
static constexpr size_t BO_IMF_HI    = BO_KFT_LO + BSZ_KFT;
static constexpr size_t BO_IMF_LO    = BO_IMF_HI + BSZ_IMF;
static constexpr size_t BO_CINW_HI   = BO_IMF_LO + BSZ_IMF;
static constexpr size_t BO_CINW_LO   = BO_CINW_HI + BSZ_CINW;
static constexpr size_t BO_COUTW_HI  = BO_CINW_LO + BSZ_CINW;
static constexpr size_t BO_COUTW_LO  = BO_COUTW_HI + BSZ_COUTW;
static constexpr size_t BO_H_HI      = BO_COUTW_LO + BSZ_COUTW;
static constexpr size_t BO_H_LO      = BO_H_HI + BSZ_H;
static constexpr size_t BO_YC_HI     = BO_H_LO + BSZ_H;
static constexpr size_t BO_YC_LO     = BO_YC_HI + BSZ_YC;
static constexpr size_t BO_SCPL_HI   = BO_YC_LO + BSZ_YC;
static constexpr size_t BO_SCPL_LO   = BO_SCPL_HI + BSZ_SCPL;
static constexpr size_t BO_AINW_HI   = BO_SCPL_LO + BSZ_SCPL;
static constexpr size_t BO_AINW_LO   = BO_AINW_HI + BSZ_AINW;
static constexpr size_t BO_XIA_HI    = BO_AINW_LO + BSZ_AINW;
static constexpr size_t BO_XIA_LO    = BO_XIA_HI + BSZ_XIA;
static constexpr size_t BO_AXPW_HI   = BO_XIA_LO + BSZ_XIA;
static constexpr size_t BO_AXPW_LO   = BO_AXPW_HI + BSZ_AXPW;
static constexpr size_t BO_DTAIN_HI  = BO_AXPW_LO + BSZ_AXPW;
static constexpr size_t BO_DTAIN_LO  = BO_DTAIN_HI + BSZ_DTAIN;
static constexpr size_t BO_ADTW_HI   = BO_DTAIN_LO + BSZ_DTAIN;
static constexpr size_t BO_ADTW_LO   = BO_ADTW_HI + BSZ_ADTW;
static constexpr size_t BO_YA_HI     = BO_ADTW_LO + BSZ_ADTW;
static constexpr size_t BO_YA_LO     = BO_YA_HI + BSZ_YA;
static constexpr size_t BO_AOUTW_HI  = BO_YA_LO + BSZ_YA;
static constexpr size_t BO_AOUTW_LO  = BO_AOUTW_HI + BSZ_AOUTW;
static constexpr size_t BO_XIC_HI    = BO_AOUTW_LO + BSZ_AOUTW;
static constexpr size_t BO_XIC_LO    = BO_XIC_HI + BSZ_XIC;
static constexpr size_t BO_CXPW_HI   = BO_XIC_LO + BSZ_XIC;
static constexpr size_t BO_CXPW_LO   = BO_CXPW_HI + BSZ_CXPW;
static constexpr size_t BO_XDBLCP_HI = BO_CXPW_LO + BSZ_CXPW;
static constexpr size_t BO_XDBLCP_LO = BO_XDBLCP_HI + BSZ_XDBLCP;
static constexpr size_t BO_CDTW_HI   = BO_XDBLCP_LO + BSZ_XDBLCP;
static constexpr size_t BO_CDTW_LO   = BO_CDTW_HI + BSZ_CDTW;
static constexpr size_t BF_TOTAL     = BO_CDTW_LO + BSZ_CDTW;

__device__ __align__(16) unsigned short g_bf[BF_TOTAL];

// ---------------- helpers ----------------
__device__ __forceinline__ float siluf(float x) { return x / (1.f + __expf(-x)); }
__device__ __forceinline__ float softplusf(float x) {
    return x > 20.f ? x : log1pf(__expf(x));
}
static inline int ceil_div(int a, int b) { return (a + b - 1) / b; }

__device__ __forceinline__ void ldsm_x4(uint32_t (&r)[4], uint32_t addr) {
    asm volatile("ldmatrix.sync.aligned.m8n8.x4.shared.b16 {%0,%1,%2,%3}, [%4];"
                 : "=r"(r[0]), "=r"(r[1]), "=r"(r[2]), "=r"(r[3]) : "r"(addr));
}
__device__ __forceinline__ void mma_bf16(float (&d)[4], const uint32_t (&a)[4],
                                         uint32_t b0, uint32_t b1) {
    asm volatile("mma.sync.aligned.m16n8k16.row.col.f32.bf16.bf16.f32 "
                 "{%0,%1,%2,%3}, {%4,%5,%6,%7}, {%8,%9}, {%0,%1,%2,%3};"
                 : "+f"(d[0]), "+f"(d[1]), "+f"(d[2]), "+f"(d[3])
                 : "r"(a[0]), "r"(a[1]), "r"(a[2]), "r"(a[3]), "r"(b0), "r"(b1));
}
__device__ __forceinline__ void split_bf(float v, __nv_bfloat16& h, __nv_bfloat16& l) {
    h = __float2bfloat16(v);
    l = __float2bfloat16(v - __bfloat162float(h));
}
__device__ __forceinline__ void cpa16(uint32_t dst, const void* src) {
    asm volatile("cp.async.cg.shared.global [%0], [%1], 16;" :: "r"(dst), "l"(src));
}
__device__ __forceinline__ void store_split4(unsigned short* hi, unsigned short* lo,
                                             size_t i, const float* v) {
    __nv_bfloat16 h0, h1, h2, h3, l0, l1, l2, l3;
    split_bf(v[0], h0, l0); split_bf(v[1], h1, l1);
    split_bf(v[2], h2, l2); split_bf(v[3], h3, l3);
    __nv_bfloat162 a, b;
    a.x = h0; a.y = h1; b.x = h2; b.y = h3;
    *(__nv_bfloat162*)(hi + i)     = a;
    *(__nv_bfloat162*)(hi + i + 2) = b;
    a.x = l0; a.y = l1; b.x = l2; b.y = l3;
    *(__nv_bfloat162*)(lo + i)     = a;
    *(__nv_bfloat162*)(lo + i + 2) = b;
}

// ================================================================
//  gemm_bt:  C[M,N] = A[M,K] @ B[N,K]^T   (pre-split bf16 planes)
// ================================================================
static constexpr int BT_PL     = 128 * 40;
static constexpr int BT_PLB    = BT_PL * 2;           // 10240 B
static constexpr int BT_STAGEB = 4 * BT_PLB;          // 40960 B
static constexpr int BT_SMEM   = 2 * BT_STAGEB;       // 81920 B

template<bool EPI>
__global__ __launch_bounds__(256, 2) void gemm_bt(
    const unsigned short* __restrict__ Ahi, const unsigned short* __restrict__ Alo,
    const unsigned short* __restrict__ Bhi, const unsigned short* __restrict__ Blo,
    float* __restrict__ C, int ldc,
    int M, int N, int Ktot, int ldA, int ldB, int splitk,
    size_t batchA, size_t batchB, size_t batchC, size_t strideS,
    const float* __restrict__ bias)
{
    extern __shared__ __align__(16) unsigned short smem_bt[];
    const uint32_t sb = (uint32_t)__cvta_generic_to_shared(smem_bt);

    const int tid = threadIdx.x, lane = tid & 31, wid = tid >> 5;
    const int wm = (wid & 1) << 6;
    const int wn = (wid >> 1) << 5;
    const int row0 = blockIdx.y * 128;
    const int col0 = blockIdx.x * 128;

    const int z = blockIdx.z;
    const int bb = z / splitk;
    const int s  = z - bb * splitk;
    const unsigned short* Ah = Ahi + (size_t)bb * batchA;
    const unsigned short* Al = Alo + (size_t)bb * batchA;
    const unsigned short* Bh = Bhi + (size_t)bb * batchB;
    const unsigned short* Bl = Blo + (size_t)bb * batchB;
    float* Cb = C + (size_t)bb * batchC + (size_t)s * strideS;

    const int Kc = Ktot / splitk;
    const int kbeg = s * Kc;
    const int nch = Kc / 32;

    float acc[4][4][4];
#pragma unroll
    for (int i = 0; i < 4; i++)
#pragma unroll
        for (int j = 0; j < 4; j++)
#pragma unroll
            for (int q = 0; q < 4; q++) acc[i][j][q] = 0.f;

#define BT_LOAD(CC, BUF)                                                        \
    {                                                                           \
        const int kc0 = kbeg + (CC) * 32;                                       \
        const uint32_t st = sb + (BUF) * BT_STAGEB;                             \
        _Pragma("unroll")                                                       \
        for (int p = 0; p < 2; p++) {                                           \
            int idx = tid + p * 256;                                            \
            int row = idx >> 2, ch = idx & 3;                                   \
            uint32_t doff = (uint32_t)(row * 80 + ch * 16);                     \
            int ga = row0 + row;                                                \
            if (ga < M) {                                                       \
                size_t ao = (size_t)ga * ldA + kc0 + ch * 8;                    \
                cpa16(st + doff,          Ah + ao);                             \
                cpa16(st + BT_PLB + doff, Al + ao);                             \
            }                                                                   \
            int gb = col0 + row;                                                \
            if (gb < N) {                                                       \
                size_t bo = (size_t)gb * ldB + kc0 + ch * 8;                    \
                cpa16(st + 2 * BT_PLB + doff, Bh + bo);                         \
                cpa16(st + 3 * BT_PLB + doff, Bl + bo);                         \
            }                                                                   \
        }                                                                       \
        asm volatile("cp.async.commit_group;" ::: "memory");                    \
    }

#define BT_COMPUTE(BUF)                                                         \
    {                                                                           \
        const uint32_t pa_hi = sb + (BUF) * BT_STAGEB;                          \
        const uint32_t pa_lo = pa_hi + BT_PLB;                                  \
        const uint32_t pb_hi = pa_hi + 2 * BT_PLB;                              \
        const uint32_t pb_lo = pa_hi + 3 * BT_PLB;                              \
        const int lr = lane & 15, lc = (lane >> 4) << 3;                        \
        _Pragma("unroll")                                                       \
        for (int sub = 0; sub < 2; sub++) {                                     \
            const int kk0 = sub * 16;                                           \
            uint32_t bh[2][4], bl[2][4];                                        \
            _Pragma("unroll")                                                   \
            for (int g = 0; g < 2; g++) {                                       \
                uint32_t off = (uint32_t)(((wn + g * 16 + lr) * 40 + kk0 + lc) * 2); \
                ldsm_x4(bh[g], pb_hi + off);                                    \
                ldsm_x4(bl[g], pb_lo + off);                                    \
            }                                                                   \
            _Pragma("unroll")                                                   \
            for (int i = 0; i < 4; i++) {                                       \
                uint32_t ah[4], al[4];                                          \
                uint32_t offa = (uint32_t)(((wm + i * 16 + lr) * 40 + kk0 + lc) * 2); \
                ldsm_x4(ah, pa_hi + offa);                                      \
                ldsm_x4(al, pa_lo + offa);                                      \
                _Pragma("unroll")                                               \
                for (int j = 0; j < 4; j++) {                                   \
                    const int g = j >> 1, o = j & 1;                            \
                    mma_bf16(acc[i][j], ah, bh[g][o], bh[g][o + 2]);            \
                    mma_bf16(acc[i][j], ah, bl[g][o], bl[g][o + 2]);            \
                    mma_bf16(acc[i][j], al, bh[g][o], bh[g][o + 2]);            \
                }                                                               \
            }                                                                   \
        }                                                                       \
    }

    BT_LOAD(0, 0);
    int buf = 0;
    for (int c = 0; c < nch; c++) {
        const bool more = (c + 1) < nch;
        if (more) { BT_LOAD(c + 1, buf ^ 1); }
        if (more) asm volatile("cp.async.wait_group 1;" ::: "memory");
        else      asm volatile("cp.async.wait_group 0;" ::: "memory");
        __syncthreads();
        BT_COMPUTE(buf);
        __syncthreads();
        buf ^= 1;
    }

    const int er = lane >> 2;
    const int ec = (lane & 3) * 2;
#pragma unroll
    for (int i = 0; i < 4; i++) {
#pragma unroll
        for (int j = 0; j < 4; j++) {
            int gm0 = row0 + wm + i * 16 + er;
            int gn  = col0 + wn + j * 8 + ec;
            if (gn >= N) continue;
            float v0 = acc[i][j][0], v1 = acc[i][j][1];
            float v2 = acc[i][j][2], v3 = acc[i][j][3];
            if (EPI) {
                float b0 = bias[gn];
                float b1 = (gn + 1 < N) ? bias[gn + 1] : 0.f;
                v0 = softplusf(v0 + b0); v1 = softplusf(v1 + b1);
                v2 = softplusf(v2 + b0); v3 = softplusf(v3 + b1);
            }
            if (gm0 < M) {
                Cb[(size_t)gm0 * ldc + gn] = v0;
                if (gn + 1 < N) Cb[(size_t)gm0 * ldc + gn + 1] = v1;
            }
            int gm1 = gm0 + 8;
            if (gm1 < M) {
                Cb[(size_t)gm1 * ldc + gn] = v2;
                if (gn + 1 < N) Cb[(size_t)gm1 * ldc + gn + 1] = v3;
            }
        }
    }
#undef BT_LOAD
#undef BT_COMPUTE
}

// ---------------- guarded transpose-split: W[Ksrc,Nd] -> planes [Nd,Kd] ----------------
__global__ void tsplit_kernel(const float* __restrict__ w,
                              unsigned short* __restrict__ hi,
                              unsigned short* __restrict__ lo,
                              int Ksrc, int Nd, int Kd,
                              size_t wBatch, size_t oBatch)
{
    __shared__ float t[32][33];
    int n0 = blockIdx.x * 32, k0 = blockIdx.y * 32;
    const float* wb = w + (size_t)blockIdx.z * wBatch;
    unsigned short* hib = hi + (size_t)blockIdx.z * oBatch;
    unsigned short* lob = lo + (size_t)blockIdx.z * oBatch;
    int tx = threadIdx.x & 31, ty = threadIdx.x >> 5;
#pragma unroll
    for (int i = 0; i < 32; i += 8) {
        int kk = k0 + ty + i, nn = n0 + tx;
        t[ty + i][tx] = (kk < Ksrc && nn < Nd) ? wb[(size_t)kk * Nd + nn] : 0.f;
    }
    __syncthreads();
#pragma unroll
    for (int p = 0; p < 2; p++) {
        int q = threadIdx.x + p * 256;
        int n = q >> 4;
        int kp = q & 15;
        if (n0 + n >= Nd) continue;
        float v0 = t[2 * kp][n], v1 = t[2 * kp + 1][n];
        __nv_bfloat16 h0, l0, h1, l1;
        split_bf(v0, h0, l0); split_bf(v1, h1, l1);
        size_t off = (size_t)(n0 + n) * Kd + k0 + 2 * kp;
        __nv_bfloat162 hh; hh.x = h0; hh.y = h1;
        *(__nv_bfloat162*)(hib + off) = hh;
        __nv_bfloat162 ll; ll.x = l0; ll.y = l1;
        *(__nv_bfloat162*)(lob + off) = ll;
    }
}

// ---------------- general row split with pad (+optional silu(z)) ----------------
template<bool SILU>
__global__ void split_pad_kernel(const float* __restrict__ x, int ldx, int Ksrc,
                                 const float* __restrict__ z, int ldz,
                                 unsigned short* __restrict__ hi,
                                 unsigned short* __restrict__ lo,
                                 int Kd, int total4)
{
    int t = blockIdx.x * blockDim.x + threadIdx.x;
    if (t >= total4) return;
    size_t i4 = (size_t)t * 4;
    int row = (int)(i4 / Kd), k = (int)(i4 - (size_t)row * Kd);
    float v[4];
#pragma unroll
    for (int e = 0; e < 4; e++) {
        int kk = k + e;
        float val = 0.f;
        if (kk < Ksrc) {
            val = x[(size_t)row * ldx + kk];
            if (SILU) val *= siluf(z[(size_t)row * ldz + kk]);
        }
        v[e] = val;
    }
    store_split4(hi, lo, i4, v);
}

// ---------------- split-K reduce + split (+optional fp32 out) ----------------
__global__ void reduce_split_kernel(const float* __restrict__ part, int ldp, size_t stride,
                                    int ns, float* __restrict__ fout,
                                    unsigned short* __restrict__ hi,
                                    unsigned short* __restrict__ lo,
                                    int Kd, int total4)
{
    int t = blockIdx.x * blockDim.x + threadIdx.x;
    if (t >= total4) return;
    size_t i4 = (size_t)t * 4;
    int row = (int)(i4 / Kd), k = (int)(i4 - (size_t)row * Kd);
    float v[4];
#pragma unroll
    for (int e = 0; e < 4; e++) {
        int kk = k + e;
        float a = 0.f;
        if (kk < ldp) {
            size_t off = (size_t)row * ldp + kk;
            for (int s = 0; s < ns; s++) a += part[(size_t)s * stride + off];
            if (fout) fout[off] = a;
        }
        v[e] = a;
    }
    store_split4(hi, lo, i4, v);
}

// ---------------- plain fixed-order split-K reduction (final out) ----------------
__global__ void reduce_sum_kernel(const float* __restrict__ part, float* __restrict__ out,
                                  int total, size_t stride, int ns)
{
    int i = blockIdx.x * blockDim.x + threadIdx.x;
    if (i >= total) return;
    float a = 0.f;
    for (int s = 0; s < ns; s++) a += part[(size_t)s * stride + i];
    out[i] = a;
}

// ---------------- depthwise causal conv (k=4) + silu -> fp32 + planes ----------------
__global__ void conv_silu_kernel(const float* __restrict__ xz, int ldxz,
                                 const float* __restrict__ w, const float* __restrict__ bias,
                                 float* __restrict__ xi,
                                 unsigned short* __restrict__ hi,
                                 unsigned short* __restrict__ lo,
                                 int Bn, int L, int dinner, int Kd, int total4)
{
    int t = blockIdx.x * blockDim.x + threadIdx.x;
    if (t >= total4) return;
    size_t i4 = (size_t)t * 4;
    int ch = (int)(i4 % Kd);
    int l  = (int)((i4 / Kd) % L);
    int b  = (int)(i4 / ((size_t)Kd * L));
    size_t rowd = (size_t)b * L + l;
    if (ch >= dinner) {
        float zv[4] = {0.f, 0.f, 0.f, 0.f};
        store_split4(hi, lo, rowd * Kd + ch, zv);
        return;
    }
    const float* xb = xz + ((size_t)b * L) * ldxz + ch;

    float4 acc = *(const float4*)(bias + ch);
    float4 w0 = *(const float4*)(w + (ch + 0) * 4);
    float4 w1 = *(const float4*)(w + (ch + 1) * 4);
    float4 w2 = *(const float4*)(w + (ch + 2) * 4);
    float4 w3 = *(const float4*)(w + (ch + 3) * 4);

    float4 xx = *(const float4*)(xb + (size_t)l * ldxz);
    acc.x = fmaf(w0.w, xx.x, acc.x);
    acc.y = fmaf(w1.w, xx.y, acc.y);
    acc.z = fmaf(w2.w, xx.z, acc.z);
    acc.w = fmaf(w3.w, xx.w, acc.w);
    if (l >= 1) {
        float4 xm = *(const float4*)(xb + (size_t)(l - 1) * ldxz);
        acc.x = fmaf(w0.z, xm.x, acc.x);
        acc.y = fmaf(w1.z, xm.y, acc.y);
        acc.z = fmaf(w2.z, xm.z, acc.z);
        acc.w = fmaf(w3.z, xm.w, acc.w);
    }
    if (l >= 2) {
        float4 xm = *(const float4*)(xb + (size_t)(l - 2) * ldxz);
        acc.x = fmaf(w0.y, xm.x, acc.x);
        acc.y = fmaf(w1.y, xm.y, acc.y);
        acc.z = fmaf(w2.y, xm.z, acc.z);
        acc.w = fmaf(w3.y, xm.w, acc.w);
    }
    if (l >= 3) {
        float4 xm = *(const float4*)(xb + (size_t)(l - 3) * ldxz);
        acc.x = fmaf(w0.x, xm.x, acc.x);
        acc.y = fmaf(w1.x, xm.y, acc.y);
        acc.z = fmaf(w2.x, xm.z, acc.z);
        acc.w = fmaf(w3.x, xm.w, acc.w);
    }
    acc.x = siluf(acc.x); acc.y = siluf(acc.y);
    acc.z = siluf(acc.z); acc.w = siluf(acc.w);
    *(float4*)(xi + rowd * dinner + ch) = acc;
    float v[4] = {acc.x, acc.y, acc.z, acc.w};
    store_split4(hi, lo, rowd * Kd + ch, v);
}

// ---------------- selective scan ----------------
template<int TCH>
__global__ void scan_kernel(const float* __restrict__ u, const float* __restrict__ dt,
                            const float* __restrict__ xdbl, int ld_dbl, int boff, int coff,
                            const float* __restrict__ A_log, const float* __restrict__ Dp,
                            float* __restrict__ y, int Bn, int L, int dinner)
{
    int gwarp = (blockIdx.x * blockDim.x + threadIdx.x) >> 5;
    int lane  = threadIdx.x & 31;
    int half  = lane >> 4;
    int n     = lane & 15;
    int gd    = gwarp * 2 + half;
    if (gd >= Bn * dinner) return;
    int b   = gd / dinner;
    int dch = gd - b * dinner;

    float a  = -__expf(A_log[dch * NS + n]);
    float Dv = Dp[dch];
    float h  = 0.f;

    const float* urow  = u    + (size_t)b * L * dinner + dch;
    const float* dtrow = dt   + (size_t)b * L * dinner + dch;
    const float* brow  = xdbl + (size_t)b * L * ld_dbl + boff + n;
    const float* crow  = xdbl + (size_t)b * L * ld_dbl + coff + n;
    float*       yrow  = y    + (size_t)b * L * dinner + dch;

    float vdt[2][TCH], vu[2][TCH], vB[2][TCH], vC[2][TCH];

#define SCAN_LOAD(BUF, T0)                                                      \
    _Pragma("unroll")                                                           \
    for (int tt = 0; tt < TCH; tt++) {                                          \
        size_t t = (size_t)((T0) + tt);                                         \
        vdt[BUF][tt] = dtrow[t * dinner];                                       \
        vu[BUF][tt]  = urow[t * dinner];                                        \
        vB[BUF][tt]  = brow[t * ld_dbl];                                        \
        vC[BUF][tt]  = crow[t * ld_dbl];                                        \
    }

#define SCAN_COMPUTE(BUF, T0)                                                   \
    {                                                                           \
        float p[TCH];                                                           \
        _Pragma("unroll")                                                       \
        for (int tt = 0; tt < TCH; tt++) {                                      \
            float dA = __expf(vdt[BUF][tt] * a);                                \
            h = fmaf(dA, h, vdt[BUF][tt] * vB[BUF][tt] * vu[BUF][tt]);          \
            p[tt] = h * vC[BUF][tt] + ((n == 0) ? vu[BUF][tt] * Dv : 0.f);      \
        }                                                                       \
        _Pragma("unroll")                                                       \
        for (int tt = 0; tt < TCH; tt++) p[tt] += __shfl_xor_sync(0xffffffffu, p[tt], 8); \
        _Pragma("unroll")                                                       \
        for (int tt = 0; tt < TCH; tt++) p[tt] += __shfl_xor_sync(0xffffffffu, p[tt], 4); \
        _Pragma("unroll")                                                       \
        for (int tt = 0; tt < TCH; tt++) p[tt] += __shfl_xor_sync(0xffffffffu, p[tt], 2); \
        _Pragma("unroll")                                                       \
        for (int tt = 0; tt < TCH; tt++) p[tt] += __shfl_xor_sync(0xffffffffu, p[tt], 1); \
        _Pragma("unroll")                                                       \
        for (int tt = 0; tt < TCH; tt++)                                        \
            if (n == tt) yrow[(size_t)((T0) + tt) * dinner] = p[tt];            \
    }

    const int nch = L / TCH;
    SCAN_LOAD(0, 0);
    for (int c = 0; c < nch; c += 2) {
        if (c + 1 < nch) SCAN_LOAD(1, (c + 1) * TCH);
        SCAN_COMPUTE(0, c * TCH);
        if (c + 1 < nch) {
            if (c + 2 < nch) SCAN_LOAD(0, (c + 2) * TCH);
            SCAN_COMPUTE(1, (c + 1) * TCH);
        }
    }
#undef SCAN_LOAD
#undef SCAN_COMPUTE
}

// ---------------- mean over N_ : one warp per row ----------------
__global__ void mean_kernel(const float* __restrict__ sc2, float* __restrict__ sbuf)
{
    int gw = (blockIdx.x * blockDim.x + threadIdx.x) >> 5;
    int lane = threadIdx.x & 31;
    if (gw >= B_ * K_) return;
    const float* row = sc2 + (size_t)gw * N_;
    float a = 0.f;
    for (int i = lane; i < N_; i += 32) a += row[i];
#pragma unroll
    for (int o = 16; o; o >>= 1) a += __shfl_xor_sync(0xffffffffu, a, o);
    if (lane == 0) sbuf[gw] = a / (float)N_;
}

// ---------------- softmax over K_ per batch ----------------
__global__ void softmax_kernel(float* __restrict__ s)
{
    __shared__ float red[32];
    int b = blockIdx.x, tid = threadIdx.x;
    int lane = tid & 31, w = tid >> 5;
    float v = s[(size_t)b * K_ + tid];
    float m = v;
#pragma unroll
    for (int o = 16; o; o >>= 1) m = fmaxf(m, __shfl_xor_sync(0xffffffffu, m, o));
    if (lane == 0) red[w] = m;
    __syncthreads();
    if (tid < 32) {
        float t = red[tid];
#pragma unroll
        for (int o = 16; o; o >>= 1) t = fmaxf(t, __shfl_xor_sync(0xffffffffu, t, o));
        if (tid == 0) red[0] = t;
    }
    __syncthreads();
    m = red[0];
    __syncthreads();
    float e = __expf(v - m);
    float sum = e;
#pragma unroll
    for (int o = 16; o; o >>= 1) sum += __shfl_xor_sync(0xffffffffu, sum, o);
    if (lane == 0) red[w] = sum;
    __syncthreads();
    if (tid < 32) {
        float t = red[tid];
#pragma unroll
        for (int o = 16; o; o >>= 1) t += __shfl_xor_sync(0xffffffffu, t, o);
        if (tid == 0) red[0] = t;
    }
    __syncthreads();
    s[(size_t)b * K_ + tid] = e / red[0];
}

// ---------------- top-k(98 of 1024) bitonic ----------------
__global__ void topk_kernel(const float* __restrict__ s, int* __restrict__ ind,
                            float* __restrict__ vtop)
{
    __shared__ float sv[K_];
    __shared__ int   si[K_];
    int b = blockIdx.x, tid = threadIdx.x;
    for (int i = tid; i < K_; i += 256) { sv[i] = s[(size_t)b * K_ + i]; si[i] = i; }
    __syncthreads();
    for (int k = 2; k <= K_; k <<= 1) {
        for (int j = k >> 1; j > 0; j >>= 1) {
            for (int i = tid; i < K_; i += 256) {
                int ixj = i ^ j;
                if (ixj > i) {
                    float v1 = sv[i], v2 = sv[ixj];
                    int   i1 = si[i], i2 = si[ixj];
                    bool lt_ji = (v2 > v1) || (v2 == v1 && i2 < i1);
                    bool lt_ij = (v1 > v2) || (v1 == v2 && i1 < i2);
                    bool asc = ((i & k) == 0);
                    if (asc ? lt_ji : lt_ij) {
                        sv[i] = v2; sv[ixj] = v1;
                        si[i] = i2; si[ixj] = i1;
                    }
                }
            }
            __syncthreads();
        }
    }
    for (int i = tid; i < N_; i += 256) {
        ind[b * N_ + i]  = si[i];
        vtop[b * N_ + i] = sv[i];
    }
}

// ---------------- h planes = split(imageFeature + gather(kf) * vtop) ----------------
__global__ void build_h_kernel(const float* __restrict__ imf, const float* __restrict__ kf,
                               const int* __restrict__ ind, const float* __restrict__ vtop,
                               unsigned short* __restrict__ hhi,
                               unsigned short* __restrict__ hlo)
{
    int idx = blockIdx.x * blockDim.x + threadIdx.x;
    int total = B_ * LC * DM_;
    if (idx >= total) return;
    int d = idx % DM_;
    int j = (idx / DM_) % LC;
    int b = idx / (DM_ * LC);
    int r = ind[b * N_ + j];
    float v = imf[(size_t)j * DM_ + d] +
              kf[((size_t)b * DM_ + d) * K_ + r] * vtop[b * N_ + j];
    __nv_bfloat16 h, l;
    split_bf(v, h, l);
    hhi[idx] = __bfloat16_as_ushort(h);
    hlo[idx] = __bfloat16_as_ushort(l);
}

// ---------------- host ----------------
extern "C" void kernel_launch(void* const* d_in, const int* in_sizes, int n_in,
                              void* d_out, int out_size)
{
    const float* imf      = (const float*)d_in[0];
    const float* kf       = (const float*)d_in[1];
    const float* a_in_w   = (const float*)d_in[2];
    const float* a_conv_w = (const float*)d_in[3];
    const float* a_conv_b = (const float*)d_in[4];
    const float* a_xproj_w= (const float*)d_in[5];
    const float* a_dt_w   = (const float*)d_in[6];
    const float* a_dt_b   = (const float*)d_in[7];
    const float* a_A_log  = (const float*)d_in[8];
    const float* a_D      = (const float*)d_in[9];
    const float* a_out_w  = (const float*)d_in[10];
    const float* c_in_w   = (const float*)d_in[11];
    const float* c_conv_w = (const float*)d_in[12];
    const float* c_conv_b = (const float*)d_in[13];
    const float* c_xproj_w= (const float*)d_in[14];
    const float* c_dt_w   = (const float*)d_in[15];
    const float* c_dt_b   = (const float*)d_in[16];
    const float* c_A_log  = (const float*)d_in[17];
    const float* c_D      = (const float*)d_in[18];
    const float* c_out_w  = (const float*)d_in[19];
    float* out = (float*)d_out;

    cudaFuncSetAttribute((const void*)gemm_bt<false>, cudaFuncAttributeMaxDynamicSharedMemorySize, BT_SMEM);
    cudaFuncSetAttribute((const void*)gemm_bt<true>,  cudaFuncAttributeMaxDynamicSharedMemorySize, BT_SMEM);

    // side stream for weight prepasses (created once, outside capture on first call)
    static cudaStream_t s2 = nullptr;
    static cudaEvent_t evF = nullptr, evJ = nullptr;
    if (s2 == nullptr) {
        cudaStreamCreateWithFlags(&s2, cudaStreamNonBlocking);
        cudaEventCreateWithFlags(&evF, cudaEventDisableTiming);
        cudaEventCreateWithFlags(&evJ, cudaEventDisableTiming);
    }

    float* sc = nullptr;
    cudaGetSymbolAddress((void**)&sc, g_scratch);
    unsigned short* bf = nullptr;
    cudaGetSymbolAddress((void**)&bf, g_bf);
    int*   p_ind  = nullptr;
    float* p_vtop = nullptr;
    cudaGetSymbolAddress((void**)&p_ind, g_ind);
    cudaGetSymbolAddress((void**)&p_vtop, g_vtop);

    float* scp    = sc + OFF_SCP;
    float* xza    = sc + OFF_XZA;
    float* xia    = sc + OFF_XIA;
    float* xdbla  = sc + OFF_XDBLA;
    float* dta    = sc + OFF_DTA;
    float* ya     = sc + OFF_YA;
    float* sc2    = sc + OFF_SC2;
    float* sbuf   = sc + OFF_S;
    float* xzc    = sc + OFF_XZC;
    float* xic    = sc + OFF_XIC;
    float* xdblc  = sc + OFF_XDBLC;
    float* xpcp   = sc + OFF_XPCP;
    float* dtc    = sc + OFF_DTC;
    float* yc     = sc + OFF_YC;
    float* outp   = sc + OFF_OUTP;

    const int Ma = B_ * K_;   // 8192
    const int Mc = B_ * LC;   // 784

    // ---- fork: all weight splits run on s2, overlapped with score chain ----
    cudaEventRecord(evF, 0);
    cudaStreamWaitEvent(s2, evF, 0);

    tsplit_kernel<<<dim3((2 * DIC) / 32, DM_ / 32, 1), 256, 0, s2>>>(
        c_in_w, bf + BO_CINW_HI, bf + BO_CINW_LO, DM_, 2 * DIC, DM_, 0, 0);
    tsplit_kernel<<<dim3(DM_ / 32, DIC / 32, 1), 256, 0, s2>>>(
        c_out_w, bf + BO_COUTW_HI, bf + BO_COUTW_LO, DIC, DM_, DIC, 0, 0);
    tsplit_kernel<<<dim3(ceil_div(2 * DIA, 32), KP_SC / 32, 1), 256, 0, s2>>>(
        a_in_w, bf + BO_AINW_HI, bf + BO_AINW_LO, N_, 2 * DIA, KP_SC, 0, 0);
    tsplit_kernel<<<dim3(ceil_div(LDBA, 32), KP_A / 32, 1), 256, 0, s2>>>(
        a_xproj_w, bf + BO_AXPW_HI, bf + BO_AXPW_LO, DIA, LDBA, KP_A, 0, 0);
    tsplit_kernel<<<dim3(ceil_div(DIA, 32), KP_DTA / 32, 1), 256, 0, s2>>>(
        a_dt_w, bf + BO_ADTW_HI, bf + BO_ADTW_LO, DRA, DIA, KP_DTA, 0, 0);
    tsplit_kernel<<<dim3(ceil_div(N_, 32), KP_A / 32, 1), 256, 0, s2>>>(
        a_out_w, bf + BO_AOUTW_HI, bf + BO_AOUTW_LO, DIA, N_, KP_A, 0, 0);
    tsplit_kernel<<<dim3(ceil_div(LDBC, 32), DIC / 32, 1), 256, 0, s2>>>(
        c_xproj_w, bf + BO_CXPW_HI, bf + BO_CXPW_LO, DIC, LDBC, DIC, 0, 0);
    tsplit_kernel<<<dim3(DIC / 32, DRC / 32, 1), 256, 0, s2>>>(
        c_dt_w, bf + BO_CDTW_HI, bf + BO_CDTW_LO, DRC, DIC, DRC, 0, 0);
    cudaEventRecord(evJ, s2);

    // ---- main stream: kf/imf splits (needed by score) ----
    tsplit_kernel<<<dim3(K_ / 32, DM_ / 32, B_), 256>>>(
        kf, bf + BO_KFT_HI, bf + BO_KFT_LO, DM_, K_, DM_,
        (size_t)DM_ * K_, (size_t)K_ * DM_);
    split_pad_kernel<false><<<ceil_div((int)(BSZ_IMF / 4), 256), 256>>>(
        imf, DM_, DM_, nullptr, 0, bf + BO_IMF_HI, bf + BO_IMF_LO, DM_, (int)(BSZ_IMF / 4));

    // 0: score[b][l][n] = kfT[b] @ imf^T  (split-K=4) -> partials -> planes (98->128 pad)
    gemm_bt<false><<<dim3(1, K_ / 128, B_ * SPLITK_SC), 256, BT_SMEM>>>(
        bf + BO_KFT_HI, bf + BO_KFT_LO, bf + BO_IMF_HI, bf + BO_IMF_LO,
        scp, N_, K_, N_, DM_, DM_, DM_, SPLITK_SC,
        (size_t)K_ * DM_, 0, (size_t)K_ * N_, SZ_SC1, nullptr);
    reduce_split_kernel<<<ceil_div(Ma * KP_SC / 4, 256), 256>>>(
        scp, N_, SZ_SC1, SPLITK_SC, nullptr,
        bf + BO_SCPL_HI, bf + BO_SCPL_LO, KP_SC, Ma * KP_SC / 4);

    // ---- join: weights ready before first consumer ----
    cudaStreamWaitEvent(0, evJ, 0);

    // 1: xza = score @ a_in_w
    gemm_bt<false><<<dim3(ceil_div(2 * DIA, 128), Ma / 128, 1), 256, BT_SMEM>>>(
        bf + BO_SCPL_HI, bf + BO_SCPL_LO, bf + BO_AINW_HI, bf + BO_AINW_LO,
        xza, 2 * DIA, Ma, 2 * DIA, KP_SC, KP_SC, KP_SC, 1, 0, 0, 0, 0, nullptr);

    // 2: conv + silu (a) -> fp32 xia + planes
    conv_silu_kernel<<<ceil_div(Ma * KP_A / 4, 256), 256>>>(
        xza, 2 * DIA, a_conv_w, a_conv_b, xia,
        bf + BO_XIA_HI, bf + BO_XIA_LO, B_, LA, DIA, KP_A, Ma * KP_A / 4);

    // 3: x_dbl = xi @ a_xproj_w
    gemm_bt<false><<<dim3(1, Ma / 128, 1), 256, BT_SMEM>>>(
        bf + BO_XIA_HI, bf + BO_XIA_LO, bf + BO_AXPW_HI, bf + BO_AXPW_LO,
        xdbla, LDBA, Ma, LDBA, KP_A, KP_A, KP_A, 1, 0, 0, 0, 0, nullptr);

    // 4: dt-in planes; dt = softplus(dtin @ a_dt_w + b)
    split_pad_kernel<false><<<ceil_div(Ma * KP_DTA / 4, 256), 256>>>(
        xdbla, LDBA, DRA, nullptr, 0,
        bf + BO_DTAIN_HI, bf + BO_DTAIN_LO, KP_DTA, Ma * KP_DTA / 4);
    gemm_bt<true><<<dim3(ceil_div(DIA, 128), Ma / 128, 1), 256, BT_SMEM>>>(
        bf + BO_DTAIN_HI, bf + BO_DTAIN_LO, bf + BO_ADTW_HI, bf + BO_ADTW_LO,
        dta, DIA, Ma, DIA, KP_DTA, KP_DTA, KP_DTA, 1, 0, 0, 0, 0, a_dt_b);

    // 5: selective scan (a)
    scan_kernel<8><<<(B_ * DIA / 2 * 32) / 256, 256>>>(
        xia, dta, xdbla, LDBA, DRA, DRA + NS, a_A_log, a_D, ya, B_, LA, DIA);

    // 6: y planes = split(y * silu(z)); sc2 = y @ a_out_w
    split_pad_kernel<true><<<ceil_div(Ma * KP_A / 4, 256), 256>>>(
        ya, DIA, DIA, xza + DIA, 2 * DIA,
        bf + BO_YA_HI, bf + BO_YA_LO, KP_A, Ma * KP_A / 4);
    gemm_bt<false><<<dim3(1, Ma / 128, 1), 256, BT_SMEM>>>(
        bf + BO_YA_HI, bf + BO_YA_LO, bf + BO_AOUTW_HI, bf + BO_AOUTW_LO,
        sc2, N_, Ma, N_, KP_A, KP_A, KP_A, 1, 0, 0, 0, 0, nullptr);

    // 7-10: mean / softmax / topk / gather (fused split)
    mean_kernel<<<(B_ * K_ * 32) / 256, 256>>>(sc2, sbuf);
    softmax_kernel<<<B_, K_>>>(sbuf);
    topk_kernel<<<B_, 256>>>(sbuf, p_ind, p_vtop);
    build_h_kernel<<<ceil_div(B_ * LC * DM_, 256), 256>>>(
        imf, kf, p_ind, p_vtop, bf + BO_H_HI, bf + BO_H_LO);

    // 11: xzc = h @ c_in_w
    gemm_bt<false><<<dim3((2 * DIC) / 128, ceil_div(Mc, 128), 1), 256, BT_SMEM>>>(
        bf + BO_H_HI, bf + BO_H_LO, bf + BO_CINW_HI, bf + BO_CINW_LO,
        xzc, 2 * DIC, Mc, 2 * DIC, DM_, DM_, DM_, 1, 0, 0, 0, 0, nullptr);

    // 12: conv + silu (c) -> fp32 xic + planes
    conv_silu_kernel<<<ceil_div(Mc * DIC / 4, 256), 256>>>(
        xzc, 2 * DIC, c_conv_w, c_conv_b, xic,
        bf + BO_XIC_HI, bf + BO_XIC_LO, B_, LC, DIC, DIC, Mc * DIC / 4);

    // 13: x_dbl partials = xi @ c_xproj_w (split-K=8) -> reduce+split
    gemm_bt<false><<<dim3(ceil_div(LDBC, 128), ceil_div(Mc, 128), SPLITK_XPC), 256, BT_SMEM>>>(
        bf + BO_XIC_HI, bf + BO_XIC_LO, bf + BO_CXPW_HI, bf + BO_CXPW_LO,
        xpcp, LDBC, Mc, LDBC, DIC, DIC, DIC, SPLITK_XPC,
        0, 0, 0, (size_t)Mc * LDBC, nullptr);
    reduce_split_kernel<<<ceil_div(Mc * LDBC / 4, 256), 256>>>(
        xpcp, LDBC, (size_t)Mc * LDBC, SPLITK_XPC, xdblc,
        bf + BO_XDBLCP_HI, bf + BO_XDBLCP_LO, LDBC, Mc * LDBC / 4);

    // 14: dt = softplus(xdblc[:, :128] @ c_dt_w + b)
    gemm_bt<true><<<dim3(DIC / 128, ceil_div(Mc, 128), 1), 256, BT_SMEM>>>(
        bf + BO_XDBLCP_HI, bf + BO_XDBLCP_LO, bf + BO_CDTW_HI, bf + BO_CDTW_LO,
        dtc, DIC, Mc, DIC, DRC, LDBC, DRC, 1, 0, 0, 0, 0, c_dt_b);

    // 15: selective scan (c)
    scan_kernel<7><<<(B_ * DIC / 2 * 32) / 256, 256>>>(
        xic, dtc, xdblc, LDBC, DRC, DRC + NS, c_A_log, c_D, yc, B_, LC, DIC);

    // 16: y planes = split(y * silu(z)); out partials (split-K=2)
    split_pad_kernel<true><<<ceil_div(Mc * DIC / 4, 256), 256>>>(
        yc, DIC, DIC, xzc + DIC, 2 * DIC,
        bf + BO_YC_HI, bf + BO_YC_LO, DIC, Mc * DIC / 4);
    gemm_bt<false><<<dim3(DM_ / 128, ceil_div(Mc, 128), SPLITK_COUT), 256, BT_SMEM>>>(
        bf + BO_YC_HI, bf + BO_YC_LO, bf + BO_COUTW_HI, bf + BO_COUTW_LO,
        outp, DM_, Mc, DM_, DIC, DIC, DIC, SPLITK_COUT,
        0, 0, 0, (size_t)Mc * DM_, nullptr);

    // 17: reduce -> out
    reduce_sum_kernel<<<ceil_div(Mc * DM_, 256), 256>>>(
        outp, out, Mc * DM_, (size_t)Mc * DM_, SPLITK_COUT);
}

// round 17
// speedup vs baseline: 3.0797x; 1.0088x over previous
#include <cuda_runtime.h>
#include <cuda_bf16.h>
#include <math.h>
#include <stdint.h>

// ---------------- problem constants ----------------
static constexpr int B_  = 8;
static constexpr int K_  = 1024;
static constexpr int N_  = 98;
static constexpr int DM_ = 2048;
static constexpr int DIA = 196;
static constexpr int DRA = 7;
static constexpr int DIC = 4096;
static constexpr int DRC = 128;
static constexpr int NS  = 16;
static constexpr int LA  = 1024;
static constexpr int LC  = 98;
static constexpr int LDBA = DRA + 2 * NS;   // 39
static constexpr int LDBC = DRC + 2 * NS;   // 160

static constexpr int SPLITK_SC   = 4;
static constexpr int SPLITK_XPC  = 8;
static constexpr int SPLITK_COUT = 2;

// padded K sizes (multiples of 32) for plane GEMMs
static constexpr int KP_SC  = 128;   // 98 -> 128
static constexpr int KP_A   = 224;   // 196 -> 224
static constexpr int KP_DTA = 32;    // 7 -> 32

// ---------------- fp32 scratch arena ----------------
static constexpr size_t SZ_SC1   = (size_t)B_ * K_ * N_;
static constexpr size_t SZ_SCP   = (size_t)SPLITK_SC * SZ_SC1;
static constexpr size_t SZ_XZA   = (size_t)B_ * K_ * 2 * DIA;
static constexpr size_t SZ_XIA   = (size_t)B_ * K_ * DIA;
static constexpr size_t SZ_XDBLA = (size_t)B_ * K_ * LDBA;
static constexpr size_t SZ_DTA   = (size_t)B_ * K_ * DIA;
static constexpr size_t SZ_YA    = (size_t)B_ * K_ * DIA;
static constexpr size_t SZ_S     = (size_t)B_ * K_;
static constexpr size_t SZ_XZC   = (size_t)B_ * LC * 2 * DIC;
static constexpr size_t SZ_XIC   = (size_t)B_ * LC * DIC;
static constexpr size_t SZ_XDBLC = (size_t)B_ * LC * LDBC;
static constexpr size_t SZ_XPCP  = (size_t)SPLITK_XPC * B_ * LC * LDBC;
static constexpr size_t SZ_DTC   = (size_t)B_ * LC * DIC;
static constexpr size_t SZ_YC    = (size_t)B_ * LC * DIC;
static constexpr size_t SZ_OUTP  = (size_t)SPLITK_COUT * B_ * LC * DM_;

static constexpr size_t OFF_SCP   = 0;
static constexpr size_t OFF_XZA   = OFF_SCP + SZ_SCP;
static constexpr size_t OFF_XIA   = OFF_XZA + SZ_XZA;
static constexpr size_t OFF_XDBLA = OFF_XIA + SZ_XIA;
static constexpr size_t OFF_DTA   = OFF_XDBLA + SZ_XDBLA;
static constexpr size_t OFF_YA    = OFF_DTA + SZ_DTA;
static constexpr size_t OFF_S     = OFF_YA + SZ_YA;
static constexpr size_t OFF_XZC   = OFF_S + SZ_S;
static constexpr size_t OFF_XIC   = OFF_XZC + SZ_XZC;
static constexpr size_t OFF_XDBLC = OFF_XIC + SZ_XIC;
static constexpr size_t OFF_XPCP  = OFF_XDBLC + SZ_XDBLC;
static constexpr size_t OFF_DTC   = OFF_XPCP + SZ_XPCP;
static constexpr size_t OFF_YC    = OFF_DTC + SZ_DTC;
static constexpr size_t OFF_OUTP  = OFF_YC + SZ_YC;
static constexpr size_t SCRATCH_TOTAL = OFF_OUTP + SZ_OUTP;

__device__ float g_scratch[SCRATCH_TOTAL];
__device__ int   g_ind[B_ * N_];
__device__ float g_vtop[B_ * N_];

// ---------------- bf16 hi/lo plane arena (u16, 16B-aligned) ----------------
static constexpr size_t BSZ_KFT    = (size_t)B_ * K_ * DM_;
static constexpr size_t BSZ_IMF    = (size_t)N_ * DM_;
static constexpr size_t BSZ_CINW   = (size_t)(2 * DIC) * DM_;
static constexpr size_t BSZ_COUTW  = (size_t)DM_ * DIC;
static constexpr size_t BSZ_H      = (size_t)B_ * LC * DM_;
static constexpr size_t BSZ_YC     = (size_t)B_ * LC * DIC;
static constexpr size_t BSZ_SCPL   = (size_t)B_ * K_ * KP_SC;
static constexpr size_t BSZ_AINW   = (size_t)(2 * DIA) * KP_SC;
static constexpr size_t BSZ_XIA    = (size_t)B_ * K_ * KP_A;
static constexpr size_t BSZ_AXPW   = (size_t)LDBA * KP_A;
static constexpr size_t BSZ_DTAIN  = (size_t)B_ * K_ * KP_DTA;
static constexpr size_t BSZ_ADTW   = (size_t)DIA * KP_DTA;
static constexpr size_t BSZ_YA     = (size_t)B_ * K_ * KP_A;
static constexpr size_t BSZ_AOUTW  = (size_t)N_ * KP_A;
static constexpr size_t BSZ_XIC    = (size_t)B_ * LC * DIC;
static constexpr size_t BSZ_CXPW   = (size_t)LDBC * DIC;
static constexpr size_t BSZ_XDBLCP = (size_t)B_ * LC * LDBC;
static constexpr size_t BSZ_CDTW   = (size_t)DIC * DRC;

static constexpr size_t BO_KFT_HI    = 0;
static constexpr size_t BO_KFT_LO    = BO_KFT_HI + BSZ_KFT;
static constexpr size_t BO_IMF_HI    = BO_KFT_LO + BSZ_KFT;
static constexpr size_t BO_IMF_LO    = BO_IMF_HI + BSZ_IMF;
static constexpr size_t BO_CINW_HI   = BO_IMF_LO + BSZ_IMF;
static constexpr size_t BO_CINW_LO   = BO_CINW_HI + BSZ_CINW;
static constexpr size_t BO_COUTW_HI  = BO_CINW_LO + BSZ_CINW;
static constexpr size_t BO_COUTW_LO  = BO_COUTW_HI + BSZ_COUTW;
static constexpr size_t BO_H_HI      = BO_COUTW_LO + BSZ_COUTW;
static constexpr size_t BO_H_LO      = BO_H_HI + BSZ_H;
static constexpr size_t BO_YC_HI     = BO_H_LO + BSZ_H;
static constexpr size_t BO_YC_LO     = BO_YC_HI + BSZ_YC;
static constexpr size_t BO_SCPL_HI   = BO_YC_LO + BSZ_YC;
static constexpr size_t BO_SCPL_LO   = BO_SCPL_HI + BSZ_SCPL;
static constexpr size_t BO_AINW_HI   = BO_SCPL_LO + BSZ_SCPL;
static constexpr size_t BO_AINW_LO   = BO_AINW_HI + BSZ_AINW;
static constexpr size_t BO_XIA_HI    = BO_AINW_LO + BSZ_AINW;
static constexpr size_t BO_XIA_LO    = BO_XIA_HI + BSZ_XIA;
static constexpr size_t BO_AXPW_HI   = BO_XIA_LO + BSZ_XIA;
static constexpr size_t BO_AXPW_LO   = BO_AXPW_HI + BSZ_AXPW;
static constexpr size_t BO_DTAIN_HI  = BO_AXPW_LO + BSZ_AXPW;
static constexpr size_t BO_DTAIN_LO  = BO_DTAIN_HI + BSZ_DTAIN;
static constexpr size_t BO_ADTW_HI   = BO_DTAIN_LO + BSZ_DTAIN;
static constexpr size_t BO_ADTW_LO   = BO_ADTW_HI + BSZ_ADTW;
static constexpr size_t BO_YA_HI     = BO_ADTW_LO + BSZ_ADTW;
static constexpr size_t BO_YA_LO     = BO_YA_HI + BSZ_YA;
static constexpr size_t BO_AOUTW_HI  = BO_YA_LO + BSZ_YA;
static constexpr size_t BO_AOUTW_LO  = BO_AOUTW_HI + BSZ_AOUTW;
static constexpr size_t BO_XIC_HI    = BO_AOUTW_LO + BSZ_AOUTW;
static constexpr size_t BO_XIC_LO    = BO_XIC_HI + BSZ_XIC;
static constexpr size_t BO_CXPW_HI   = BO_XIC_LO + BSZ_XIC;
static constexpr size_t BO_CXPW_LO   = BO_CXPW_HI + BSZ_CXPW;
static constexpr size_t BO_XDBLCP_HI = BO_CXPW_LO + BSZ_CXPW;
static constexpr size_t BO_XDBLCP_LO = BO_XDBLCP_HI + BSZ_XDBLCP;
static constexpr size_t BO_CDTW_HI   = BO_XDBLCP_LO + BSZ_XDBLCP;
static constexpr size_t BO_CDTW_LO   = BO_CDTW_HI + BSZ_CDTW;
static constexpr size_t BF_TOTAL     = BO_CDTW_LO + BSZ_CDTW;

__device__ __align__(16) unsigned short g_bf[BF_TOTAL];

// ---------------- helpers ----------------
__device__ __forceinline__ float siluf(float x) { return x / (1.f + __expf(-x)); }
__device__ __forceinline__ float softplusf(float x) {
    return x > 20.f ? x : log1pf(__expf(x));
}
static inline int ceil_div(int a, int b) { return (a + b - 1) / b; }

__device__ __forceinline__ void ldsm_x4(uint32_t (&r)[4], uint32_t addr) {
    asm volatile("ldmatrix.sync.aligned.m8n8.x4.shared.b16 {%0,%1,%2,%3}, [%4];"
                 : "=r"(r[0]), "=r"(r[1]), "=r"(r[2]), "=r"(r[3]) : "r"(addr));
}
__device__ __forceinline__ void mma_bf16(float (&d)[4], const uint32_t (&a)[4],
                                         uint32_t b0, uint32_t b1) {
    asm volatile("mma.sync.aligned.m16n8k16.row.col.f32.bf16.bf16.f32 "
                 "{%0,%1,%2,%3}, {%4,%5,%6,%7}, {%8,%9}, {%0,%1,%2,%3};"
                 : "+f"(d[0]), "+f"(d[1]), "+f"(d[2]), "+f"(d[3])
                 : "r"(a[0]), "r"(a[1]), "r"(a[2]), "r"(a[3]), "r"(b0), "r"(b1));
}
__device__ __forceinline__ void split_bf(float v, __nv_bfloat16& h, __nv_bfloat16& l) {
    h = __float2bfloat16(v);
    l = __float2bfloat16(v - __bfloat162float(h));
}
__device__ __forceinline__ void cpa16(uint32_t dst, const void* src) {
    asm volatile("cp.async.cg.shared.global [%0], [%1], 16;" :: "r"(dst), "l"(src));
}
__device__ __forceinline__ void store_split4(unsigned short* hi, unsigned short* lo,
                                             size_t i, const float* v) {
    __nv_bfloat16 h0, h1, h2, h3, l0, l1, l2, l3;
    split_bf(v[0], h0, l0); split_bf(v[1], h1, l1);
    split_bf(v[2], h2, l2); split_bf(v[3], h3, l3);
    __nv_bfloat162 a, b;
    a.x = h0; a.y = h1; b.x = h2; b.y = h3;
    *(__nv_bfloat162*)(hi + i)     = a;
    *(__nv_bfloat162*)(hi + i + 2) = b;
    a.x = l0; a.y = l1; b.x = l2; b.y = l3;
    *(__nv_bfloat162*)(lo + i)     = a;
    *(__nv_bfloat162*)(lo + i + 2) = b;
}

// ================================================================
//  gemm_bt:  C[M,N] = A[M,K] @ B[N,K]^T   (pre-split bf16 planes)
//  EMODE: 0 plain; 1 softplus(acc+bias); 2 row-mean -> aux (no C store);
//         3 plain C + dt-in plane write (cols<DRA, pad to KP_DTA)
// ================================================================
static constexpr int BT_PL     = 128 * 40;
static constexpr int BT_PLB    = BT_PL * 2;           // 10240 B
static constexpr int BT_STAGEB = 4 * BT_PLB;          // 40960 B
static constexpr int BT_SMEM   = 2 * BT_STAGEB;       // 81920 B

template<int EMODE>
__global__ __launch_bounds__(256, 2) void gemm_bt(
    const unsigned short* __restrict__ Ahi, const unsigned short* __restrict__ Alo,
    const unsigned short* __restrict__ Bhi, const unsigned short* __restrict__ Blo,
    float* __restrict__ C, int ldc,
    int M, int N, int Ktot, int ldA, int ldB, int splitk,
    size_t batchA, size_t batchB, size_t batchC, size_t strideS,
    const float* __restrict__ bias,
    float* __restrict__ aux,
    unsigned short* __restrict__ phi, unsigned short* __restrict__ plo)
{
    extern __shared__ __align__(16) unsigned short smem_bt[];
    const uint32_t sb = (uint32_t)__cvta_generic_to_shared(smem_bt);

    const int tid = threadIdx.x, lane = tid & 31, wid = tid >> 5;
    const int wm = (wid & 1) << 6;
    const int wn = (wid >> 1) << 5;
    const int row0 = blockIdx.y * 128;
    const int col0 = blockIdx.x * 128;

    const int z = blockIdx.z;
    const int bb = z / splitk;
    const int s  = z - bb * splitk;
    const unsigned short* Ah = Ahi + (size_t)bb * batchA;
    const unsigned short* Al = Alo + (size_t)bb * batchA;
    const unsigned short* Bh = Bhi + (size_t)bb * batchB;
    const unsigned short* Bl = Blo + (size_t)bb * batchB;
    float* Cb = C + (size_t)bb * batchC + (size_t)s * strideS;

    const int Kc = Ktot / splitk;
    const int kbeg = s * Kc;
    const int nch = Kc / 32;

    float acc[4][4][4];
#pragma unroll
    for (int i = 0; i < 4; i++)
#pragma unroll
        for (int j = 0; j < 4; j++)
#pragma unroll
            for (int q = 0; q < 4; q++) acc[i][j][q] = 0.f;

#define BT_LOAD(CC, BUF)                                                        \
    {                                                                           \
        const int kc0 = kbeg + (CC) * 32;                                       \
        const uint32_t st = sb + (BUF) * BT_STAGEB;                             \
        _Pragma("unroll")                                                       \
        for (int p = 0; p < 2; p++) {                                           \
            int idx = tid + p * 256;                                            \
            int row = idx >> 2, ch = idx & 3;                                   \
            uint32_t doff = (uint32_t)(row * 80 + ch * 16);                     \
            int ga = row0 + row;                                                \
            if (ga < M) {                                                       \
                size_t ao = (size_t)ga * ldA + kc0 + ch * 8;                    \
                cpa16(st + doff,          Ah + ao);                             \
                cpa16(st + BT_PLB + doff, Al + ao);                             \
            }                                                                   \
            int gb = col0 + row;                                                \
            if (gb < N) {                                                       \
                size_t bo = (size_t)gb * ldB + kc0 + ch * 8;                    \
                cpa16(st + 2 * BT_PLB + doff, Bh + bo);                         \
                cpa16(st + 3 * BT_PLB + doff, Bl + bo);                         \
            }                                                                   \
        }                                                                       \
        asm volatile("cp.async.commit_group;" ::: "memory");                    \
    }

#define BT_COMPUTE(BUF)                                                         \
    {                                                                           \
        const uint32_t pa_hi = sb + (BUF) * BT_STAGEB;                          \
        const uint32_t pa_lo = pa_hi + BT_PLB;                                  \
        const uint32_t pb_hi = pa_hi + 2 * BT_PLB;                              \
        const uint32_t pb_lo = pa_hi + 3 * BT_PLB;                              \
        const int lr = lane & 15, lc = (lane >> 4) << 3;                        \
        _Pragma("unroll")                                                       \
        for (int sub = 0; sub < 2; sub++) {                                     \
            const int kk0 = sub * 16;                                           \
            uint32_t bh[2][4], bl[2][4];                                        \
            _Pragma("unroll")                                                   \
            for (int g = 0; g < 2; g++) {                                       \
                uint32_t off = (uint32_t)(((wn + g * 16 + lr) * 40 + kk0 + lc) * 2); \
                ldsm_x4(bh[g], pb_hi + off);                                    \
                ldsm_x4(bl[g], pb_lo + off);                                    \
            }                                                                   \
            _Pragma("unroll")                                                   \
            for (int i = 0; i < 4; i++) {                                       \
                uint32_t ah[4], al[4];                                          \
                uint32_t offa = (uint32_t)(((wm + i * 16 + lr) * 40 + kk0 + lc) * 2); \
                ldsm_x4(ah, pa_hi + offa);                                      \
                ldsm_x4(al, pa_lo + offa);                                      \
                _Pragma("unroll")                                               \
                for (int j = 0; j < 4; j++) {                                   \
                    const int g = j >> 1, o = j & 1;                            \
                    mma_bf16(acc[i][j], ah, bh[g][o], bh[g][o + 2]);            \
                    mma_bf16(acc[i][j], ah, bl[g][o], bl[g][o + 2]);            \
                    mma_bf16(acc[i][j], al, bh[g][o], bh[g][o + 2]);            \
                }                                                               \
            }                                                                   \
        }                                                                       \
    }

    BT_LOAD(0, 0);
    int buf = 0;
    for (int c = 0; c < nch; c++) {
        const bool more = (c + 1) < nch;
        if (more) { BT_LOAD(c + 1, buf ^ 1); }
        if (more) asm volatile("cp.async.wait_group 1;" ::: "memory");
        else      asm volatile("cp.async.wait_group 0;" ::: "memory");
        __syncthreads();
        BT_COMPUTE(buf);
        __syncthreads();
        buf ^= 1;
    }

    const int er = lane >> 2;
    const int ec = (lane & 3) * 2;

    if (EMODE == 2) {
        // row-mean epilogue: no C store; psum over this thread's columns,
        // quad-shfl reduce, cross-warp smem reduce, write aux[row]/N.
        float* ps = (float*)smem_bt;            // [4][128]
        const int wnIdx = wid >> 1;
#pragma unroll
        for (int i = 0; i < 4; i++) {
            float s0 = 0.f, s1 = 0.f;
#pragma unroll
            for (int j = 0; j < 4; j++) {
                int gn = col0 + wn + j * 8 + ec;
                if (gn < N)     { s0 += acc[i][j][0]; s1 += acc[i][j][2]; }
                if (gn + 1 < N) { s0 += acc[i][j][1]; s1 += acc[i][j][3]; }
            }
            s0 += __shfl_xor_sync(0xffffffffu, s0, 1);
            s0 += __shfl_xor_sync(0xffffffffu, s0, 2);
            s1 += __shfl_xor_sync(0xffffffffu, s1, 1);
            s1 += __shfl_xor_sync(0xffffffffu, s1, 2);
            if ((lane & 3) == 0) {
                ps[wnIdx * 128 + wm + i * 16 + er]     = s0;
                ps[wnIdx * 128 + wm + i * 16 + er + 8] = s1;
            }
        }
        __syncthreads();
        if (tid < 128) {
            float a = ps[tid] + ps[128 + tid] + ps[256 + tid] + ps[384 + tid];
            aux[row0 + tid] = a / (float)N;
        }
        return;
    }

#pragma unroll
    for (int i = 0; i < 4; i++) {
#pragma unroll
        for (int j = 0; j < 4; j++) {
            int gm0 = row0 + wm + i * 16 + er;
            int gn  = col0 + wn + j * 8 + ec;
            if (gn >= N) continue;
            float v0 = acc[i][j][0], v1 = acc[i][j][1];
            float v2 = acc[i][j][2], v3 = acc[i][j][3];
            if (EMODE == 1) {
                float b0 = bias[gn];
                float b1 = (gn + 1 < N) ? bias[gn + 1] : 0.f;
                v0 = softplusf(v0 + b0); v1 = softplusf(v1 + b1);
                v2 = softplusf(v2 + b0); v3 = softplusf(v3 + b1);
            }
            if (gm0 < M) {
                Cb[(size_t)gm0 * ldc + gn] = v0;
                if (gn + 1 < N) Cb[(size_t)gm0 * ldc + gn + 1] = v1;
            }
            int gm1 = gm0 + 8;
            if (gm1 < M) {
                Cb[(size_t)gm1 * ldc + gn] = v2;
                if (gn + 1 < N) Cb[(size_t)gm1 * ldc + gn + 1] = v3;
            }
            if (EMODE == 3) {
                // dt-in planes: cols < DRA, rows gm0/gm1
                if (gn < DRA && gm0 < M) {
                    __nv_bfloat16 h, l;
                    split_bf(v0, h, l);
                    phi[(size_t)gm0 * KP_DTA + gn] = __bfloat16_as_ushort(h);
                    plo[(size_t)gm0 * KP_DTA + gn] = __bfloat16_as_ushort(l);
                    split_bf(v2, h, l);
                    phi[(size_t)(gm0 + 8) * KP_DTA + gn] = __bfloat16_as_ushort(h);
                    plo[(size_t)(gm0 + 8) * KP_DTA + gn] = __bfloat16_as_ushort(l);
                }
                if (gn + 1 < DRA && gm0 < M) {
                    __nv_bfloat16 h, l;
                    split_bf(v1, h, l);
                    phi[(size_t)gm0 * KP_DTA + gn + 1] = __bfloat16_as_ushort(h);
                    plo[(size_t)gm0 * KP_DTA + gn + 1] = __bfloat16_as_ushort(l);
                    split_bf(v3, h, l);
                    phi[(size_t)(gm0 + 8) * KP_DTA + gn + 1] = __bfloat16_as_ushort(h);
                    plo[(size_t)(gm0 + 8) * KP_DTA + gn + 1] = __bfloat16_as_ushort(l);
                }
            }
        }
    }
    if (EMODE == 3) {
        // zero the pad cols [DRA, KP_DTA) for this CTA's 128 rows
        for (int q = tid; q < 128 * (KP_DTA - DRA); q += 256) {
            int r = q / (KP_DTA - DRA);
            int cpad = DRA + q - r * (KP_DTA - DRA);
            size_t off = (size_t)(row0 + r) * KP_DTA + cpad;
            phi[off] = 0; plo[off] = 0;
        }
    }
#undef BT_LOAD
#undef BT_COMPUTE
}

// ---------------- guarded transpose-split: W[Ksrc,Nd] -> planes [Nd,Kd] ----------------
__global__ void tsplit_kernel(const float* __restrict__ w,
                              unsigned short* __restrict__ hi,
                              unsigned short* __restrict__ lo,
                              int Ksrc, int Nd, int Kd,
                              size_t wBatch, size_t oBatch)
{
    __shared__ float t[32][33];
    int n0 = blockIdx.x * 32, k0 = blockIdx.y * 32;
    const float* wb = w + (size_t)blockIdx.z * wBatch;
    unsigned short* hib = hi + (size_t)blockIdx.z * oBatch;
    unsigned short* lob = lo + (size_t)blockIdx.z * oBatch;
    int tx = threadIdx.x & 31, ty = threadIdx.x >> 5;
#pragma unroll
    for (int i = 0; i < 32; i += 8) {
        int kk = k0 + ty + i, nn = n0 + tx;
        t[ty + i][tx] = (kk < Ksrc && nn < Nd) ? wb[(size_t)kk * Nd + nn] : 0.f;
    }
    __syncthreads();
#pragma unroll
    for (int p = 0; p < 2; p++) {
        int q = threadIdx.x + p * 256;
        int n = q >> 4;
        int kp = q & 15;
        if (n0 + n >= Nd) continue;
        float v0 = t[2 * kp][n], v1 = t[2 * kp + 1][n];
        __nv_bfloat16 h0, l0, h1, l1;
        split_bf(v0, h0, l0); split_bf(v1, h1, l1);
        size_t off = (size_t)(n0 + n) * Kd + k0 + 2 * kp;
        __nv_bfloat162 hh; hh.x = h0; hh.y = h1;
        *(__nv_bfloat162*)(hib + off) = hh;
        __nv_bfloat162 ll; ll.x = l0; ll.y = l1;
        *(__nv_bfloat162*)(lob + off) = ll;
    }
}

// ---------------- general row split with pad (+optional silu(z)) ----------------
template<bool SILU>
__global__ void split_pad_kernel(const float* __restrict__ x, int ldx, int Ksrc,
                                 const float* __restrict__ z, int ldz,
                                 unsigned short* __restrict__ hi,
                                 unsigned short* __restrict__ lo,
                                 int Kd, int total4)
{
    int t = blockIdx.x * blockDim.x + threadIdx.x;
    if (t >= total4) return;
    size_t i4 = (size_t)t * 4;
    int row = (int)(i4 / Kd), k = (int)(i4 - (size_t)row * Kd);
    float v[4];
#pragma unroll
    for (int e = 0; e < 4; e++) {
        int kk = k + e;
        float val = 0.f;
        if (kk < Ksrc) {
            val = x[(size_t)row * ldx + kk];
            if (SILU) val *= siluf(z[(size_t)row * ldz + kk]);
        }
        v[e] = val;
    }
    store_split4(hi, lo, i4, v);
}

// ---------------- split-K reduce + split (+optional fp32 out) ----------------
__global__ void reduce_split_kernel(const float* __restrict__ part, int ldp, size_t stride,
                                    int ns, float* __restrict__ fout,
                                    unsigned short* __restrict__ hi,
                                    unsigned short* __restrict__ lo,
                                    int Kd, int total4)
{
    int t = blockIdx.x * blockDim.x + threadIdx.x;
    if (t >= total4) return;
    size_t i4 = (size_t)t * 4;
    int row = (int)(i4 / Kd), k = (int)(i4 - (size_t)row * Kd);
    float v[4];
#pragma unroll
    for (int e = 0; e < 4; e++) {
        int kk = k + e;
        float a = 0.f;
        if (kk < ldp) {
            size_t off = (size_t)row * ldp + kk;
            for (int s = 0; s < ns; s++) a += part[(size_t)s * stride + off];
            if (fout) fout[off] = a;
        }
        v[e] = a;
    }
    store_split4(hi, lo, i4, v);
}

// ---------------- plain fixed-order split-K reduction (final out) ----------------
__global__ void reduce_sum_kernel(const float* __restrict__ part, float* __restrict__ out,
                                  int total, size_t stride, int ns)
{
    int i = blockIdx.x * blockDim.x + threadIdx.x;
    if (i >= total) return;
    float a = 0.f;
    for (int s = 0; s < ns; s++) a += part[(size_t)s * stride + i];
    out[i] = a;
}

// ---------------- depthwise causal conv (k=4) + silu -> fp32 + planes ----------------
__global__ void conv_silu_kernel(const float* __restrict__ xz, int ldxz,
                                 const float* __restrict__ w, const float* __restrict__ bias,
                                 float* __restrict__ xi,
                                 unsigned short* __restrict__ hi,
                                 unsigned short* __restrict__ lo,
                                 int Bn, int L, int dinner, int Kd, int total4)
{
    int t = blockIdx.x * blockDim.x + threadIdx.x;
    if (t >= total4) return;
    size_t i4 = (size_t)t * 4;
    int ch = (int)(i4 % Kd);
    int l  = (int)((i4 / Kd) % L);
    int b  = (int)(i4 / ((size_t)Kd * L));
    size_t rowd = (size_t)b * L + l;
    if (ch >= dinner) {
        float zv[4] = {0.f, 0.f, 0.f, 0.f};
        store_split4(hi, lo, rowd * Kd + ch, zv);
        return;
    }
    const float* xb = xz + ((size_t)b * L) * ldxz + ch;

    float4 acc = *(const float4*)(bias + ch);
    float4 w0 = *(const float4*)(w + (ch + 0) * 4);
    float4 w1 = *(const float4*)(w + (ch + 1) * 4);
    float4 w2 = *(const float4*)(w + (ch + 2) * 4);
    float4 w3 = *(const float4*)(w + (ch + 3) * 4);

    float4 xx = *(const float4*)(xb + (size_t)l * ldxz);
    acc.x = fmaf(w0.w, xx.x, acc.x);
    acc.y = fmaf(w1.w, xx.y, acc.y);
    acc.z = fmaf(w2.w, xx.z, acc.z);
    acc.w = fmaf(w3.w, xx.w, acc.w);
    if (l >= 1) {
        float4 xm = *(const float4*)(xb + (size_t)(l - 1) * ldxz);
        acc.x = fmaf(w0.z, xm.x, acc.x);
        acc.y = fmaf(w1.z, xm.y, acc.y);
        acc.z = fmaf(w2.z, xm.z, acc.z);
        acc.w = fmaf(w3.z, xm.w, acc.w);
    }
    if (l >= 2) {
        float4 xm = *(const float4*)(xb + (size_t)(l - 2) * ldxz);
        acc.x = fmaf(w0.y, xm.x, acc.x);
        acc.y = fmaf(w1.y, xm.y, acc.y);
        acc.z = fmaf(w2.y, xm.z, acc.z);
        acc.w = fmaf(w3.y, xm.w, acc.w);
    }
    if (l >= 3) {
        float4 xm = *(const float4*)(xb + (size_t)(l - 3) * ldxz);
        acc.x = fmaf(w0.x, xm.x, acc.x);
        acc.y = fmaf(w1.x, xm.y, acc.y);
        acc.z = fmaf(w2.x, xm.z, acc.z);
        acc.w = fmaf(w3.x, xm.w, acc.w);
    }
    acc.x = siluf(acc.x); acc.y = siluf(acc.y);
    acc.z = siluf(acc.z); acc.w = siluf(acc.w);
    *(float4*)(xi + rowd * dinner + ch) = acc;
    float v[4] = {acc.x, acc.y, acc.z, acc.w};
    store_split4(hi, lo, rowd * Kd + ch, v);
}

// ---------------- selective scan ----------------
template<int TCH>
__global__ void scan_kernel(const float* __restrict__ u, const float* __restrict__ dt,
                            const float* __restrict__ xdbl, int ld_dbl, int boff, int coff,
                            const float* __restrict__ A_log, const float* __restrict__ Dp,
                            float* __restrict__ y, int Bn, int L, int dinner)
{
    int gwarp = (blockIdx.x * blockDim.x + threadIdx.x) >> 5;
    int lane  = threadIdx.x & 31;
    int half  = lane >> 4;
    int n     = lane & 15;
    int gd    = gwarp * 2 + half;
    if (gd >= Bn * dinner) return;
    int b   = gd / dinner;
    int dch = gd - b * dinner;

    float a  = -__expf(A_log[dch * NS + n]);
    float Dv = Dp[dch];
    float h  = 0.f;

    const float* urow  = u    + (size_t)b * L * dinner + dch;
    const float* dtrow = dt   + (size_t)b * L * dinner + dch;
    const float* brow  = xdbl + (size_t)b * L * ld_dbl + boff + n;
    const float* crow  = xdbl + (size_t)b * L * ld_dbl + coff + n;
    float*       yrow  = y    + (size_t)b * L * dinner + dch;

    float vdt[2][TCH], vu[2][TCH], vB[2][TCH], vC[2][TCH];

#define SCAN_LOAD(BUF, T0)                                                      \
    _Pragma("unroll")                                                           \
    for (int tt = 0; tt < TCH; tt++) {                                          \
        size_t t = (size_t)((T0) + tt);                                         \
        vdt[BUF][tt] = dtrow[t * dinner];                                       \
        vu[BUF][tt]  = urow[t * dinner];                                        \
        vB[BUF][tt]  = brow[t * ld_dbl];                                        \
        vC[BUF][tt]  = crow[t * ld_dbl];                                        \
    }

#define SCAN_COMPUTE(BUF, T0)                                                   \
    {                                                                           \
        float p[TCH];                                                           \
        _Pragma("unroll")                                                       \
        for (int tt = 0; tt < TCH; tt++) {                                      \
            float dA = __expf(vdt[BUF][tt] * a);                                \
            h = fmaf(dA, h, vdt[BUF][tt] * vB[BUF][tt] * vu[BUF][tt]);          \
            p[tt] = h * vC[BUF][tt] + ((n == 0) ? vu[BUF][tt] * Dv : 0.f);      \
        }                                                                       \
        _Pragma("unroll")                                                       \
        for (int tt = 0; tt < TCH; tt++) p[tt] += __shfl_xor_sync(0xffffffffu, p[tt], 8); \
        _Pragma("unroll")                                                       \
        for (int tt = 0; tt < TCH; tt++) p[tt] += __shfl_xor_sync(0xffffffffu, p[tt], 4); \
        _Pragma("unroll")                                                       \
        for (int tt = 0; tt < TCH; tt++) p[tt] += __shfl_xor_sync(0xffffffffu, p[tt], 2); \
        _Pragma("unroll")                                                       \
        for (int tt = 0; tt < TCH; tt++) p[tt] += __shfl_xor_sync(0xffffffffu, p[tt], 1); \
        _Pragma("unroll")                                                       \
        for (int tt = 0; tt < TCH; tt++)                                        \
            if (n == tt) yrow[(size_t)((T0) + tt) * dinner] = p[tt];            \
    }

    const int nch = L / TCH;
    SCAN_LOAD(0, 0);
    for (int c = 0; c < nch; c += 2) {
        if (c + 1 < nch) SCAN_LOAD(1, (c + 1) * TCH);
        SCAN_COMPUTE(0, c * TCH);
        if (c + 1 < nch) {
            if (c + 2 < nch) SCAN_LOAD(0, (c + 2) * TCH);
            SCAN_COMPUTE(1, (c + 1) * TCH);
        }
    }
#undef SCAN_LOAD
#undef SCAN_COMPUTE
}

// ---------------- softmax + top-k(98 of 1024) bitonic, fused ----------------
__global__ void topk_kernel(const float* __restrict__ s, int* __restrict__ ind,
                            float* __restrict__ vtop)
{
    __shared__ float sv[K_];
    __shared__ int   si[K_];
    __shared__ float red[32];
    int b = blockIdx.x, tid = threadIdx.x;
    int lane = tid & 31, w = tid >> 5;

    float lm = -1e30f;
    for (int i = tid; i < K_; i += 256) {
        float v = s[(size_t)b * K_ + i];
        sv[i] = v; si[i] = i;
        lm = fmaxf(lm, v);
    }
#pragma unroll
    for (int o = 16; o; o >>= 1) lm = fmaxf(lm, __shfl_xor_sync(0xffffffffu, lm, o));
    if (lane == 0) red[w] = lm;
    __syncthreads();
    if (tid < 32) {
        float t = (tid < 8) ? red[tid] : -1e30f;
#pragma unroll
        for (int o = 4; o; o >>= 1) t = fmaxf(t, __shfl_xor_sync(0xffffffffu, t, o));
        if (tid == 0) red[0] = t;
    }
    __syncthreads();
    float mx = red[0];
    __syncthreads();
    float ls = 0.f;
    for (int i = tid; i < K_; i += 256) {
        float e = __expf(sv[i] - mx);
        sv[i] = e;
        ls += e;
    }
#pragma unroll
    for (int o = 16; o; o >>= 1) ls += __shfl_xor_sync(0xffffffffu, ls, o);
    if (lane == 0) red[w] = ls;
    __syncthreads();
    if (tid < 32) {
        float t = (tid < 8) ? red[tid] : 0.f;
#pragma unroll
        for (int o = 4; o; o >>= 1) t += __shfl_xor_sync(0xffffffffu, t, o);
        if (tid == 0) red[0] = t;
    }
    __syncthreads();
    float inv = 1.f / red[0];
    for (int i = tid; i < K_; i += 256) sv[i] *= inv;
    __syncthreads();

    for (int k = 2; k <= K_; k <<= 1) {
        for (int j = k >> 1; j > 0; j >>= 1) {
            for (int i = tid; i < K_; i += 256) {
                int ixj = i ^ j;
                if (ixj > i) {
                    float v1 = sv[i], v2 = sv[ixj];
                    int   i1 = si[i], i2 = si[ixj];
                    bool lt_ji = (v2 > v1) || (v2 == v1 && i2 < i1);
                    bool lt_ij = (v1 > v2) || (v1 == v2 && i1 < i2);
                    bool asc = ((i & k) == 0);
                    if (asc ? lt_ji : lt_ij) {
                        sv[i] = v2; sv[ixj] = v1;
                        si[i] = i2; si[ixj] = i1;
                    }
                }
            }
            __syncthreads();
        }
    }
    for (int i = tid; i < N_; i += 256) {
        ind[b * N_ + i]  = si[i];
        vtop[b * N_ + i] = sv[i];
    }
}

// ---------------- h planes = split(imageFeature + gather(kf) * vtop) ----------------
__global__ void build_h_kernel(const float* __restrict__ imf, const float* __restrict__ kf,
                               const int* __restrict__ ind, const float* __restrict__ vtop,
                               unsigned short* __restrict__ hhi,
                               unsigned short* __restrict__ hlo)
{
    int idx = blockIdx.x * blockDim.x + threadIdx.x;
    int total = B_ * LC * DM_;
    if (idx >= total) return;
    int d = idx % DM_;
    int j = (idx / DM_) % LC;
    int b = idx / (DM_ * LC);
    int r = ind[b * N_ + j];
    float v = imf[(size_t)j * DM_ + d] +
              kf[((size_t)b * DM_ + d) * K_ + r] * vtop[b * N_ + j];
    __nv_bfloat16 h, l;
    split_bf(v, h, l);
    hhi[idx] = __bfloat16_as_ushort(h);
    hlo[idx] = __bfloat16_as_ushort(l);
}

// ---------------- host ----------------
extern "C" void kernel_launch(void* const* d_in, const int* in_sizes, int n_in,
                              void* d_out, int out_size)
{
    const float* imf      = (const float*)d_in[0];
    const float* kf       = (const float*)d_in[1];
    const float* a_in_w   = (const float*)d_in[2];
    const float* a_conv_w = (const float*)d_in[3];
    const float* a_conv_b = (const float*)d_in[4];
    const float* a_xproj_w= (const float*)d_in[5];
    const float* a_dt_w   = (const float*)d_in[6];
    const float* a_dt_b   = (const float*)d_in[7];
    const float* a_A_log  = (const float*)d_in[8];
    const float* a_D      = (const float*)d_in[9];
    const float* a_out_w  = (const float*)d_in[10];
    const float* c_in_w   = (const float*)d_in[11];
    const float* c_conv_w = (const float*)d_in[12];
    const float* c_conv_b = (const float*)d_in[13];
    const float* c_xproj_w= (const float*)d_in[14];
    const float* c_dt_w   = (const float*)d_in[15];
    const float* c_dt_b   = (const float*)d_in[16];
    const float* c_A_log  = (const float*)d_in[17];
    const float* c_D      = (const float*)d_in[18];
    const float* c_out_w  = (const float*)d_in[19];
    float* out = (float*)d_out;

    cudaFuncSetAttribute((const void*)gemm_bt<0>, cudaFuncAttributeMaxDynamicSharedMemorySize, BT_SMEM);
    cudaFuncSetAttribute((const void*)gemm_bt<1>, cudaFuncAttributeMaxDynamicSharedMemorySize, BT_SMEM);
    cudaFuncSetAttribute((const void*)gemm_bt<2>, cudaFuncAttributeMaxDynamicSharedMemorySize, BT_SMEM);
    cudaFuncSetAttribute((const void*)gemm_bt<3>, cudaFuncAttributeMaxDynamicSharedMemorySize, BT_SMEM);

    static cudaStream_t s2 = nullptr;
    static cudaEvent_t evF = nullptr, evJ = nullptr;
    if (s2 == nullptr) {
        cudaStreamCreateWithFlags(&s2, cudaStreamNonBlocking);
        cudaEventCreateWithFlags(&evF, cudaEventDisableTiming);
        cudaEventCreateWithFlags(&evJ, cudaEventDisableTiming);
    }

    float* sc = nullptr;
    cudaGetSymbolAddress((void**)&sc, g_scratch);
    unsigned short* bf = nullptr;
    cudaGetSymbolAddress((void**)&bf, g_bf);
    int*   p_ind  = nullptr;
    float* p_vtop = nullptr;
    cudaGetSymbolAddress((void**)&p_ind, g_ind);
    cudaGetSymbolAddress((void**)&p_vtop, g_vtop);

    float* scp    = sc + OFF_SCP;
    float* xza    = sc + OFF_XZA;
    float* xia    = sc + OFF_XIA;
    float* xdbla  = sc + OFF_XDBLA;
    float* dta    = sc + OFF_DTA;
    float* ya     = sc + OFF_YA;
    float* sbuf   = sc + OFF_S;
    float* xzc    = sc + OFF_XZC;
    float* xic    = sc + OFF_XIC;
    float* xdblc  = sc + OFF_XDBLC;
    float* xpcp   = sc + OFF_XPCP;
    float* dtc    = sc + OFF_DTC;
    float* yc     = sc + OFF_YC;
    float* outp   = sc + OFF_OUTP;

    const int Ma = B_ * K_;   // 8192
    const int Mc = B_ * LC;   // 784

    // ---- fork: all weight splits on s2 ----
    cudaEventRecord(evF, 0);
    cudaStreamWaitEvent(s2, evF, 0);

    tsplit_kernel<<<dim3((2 * DIC) / 32, DM_ / 32, 1), 256, 0, s2>>>(
        c_in_w, bf + BO_CINW_HI, bf + BO_CINW_LO, DM_, 2 * DIC, DM_, 0, 0);
    tsplit_kernel<<<dim3(DM_ / 32, DIC / 32, 1), 256, 0, s2>>>(
        c_out_w, bf + BO_COUTW_HI, bf + BO_COUTW_LO, DIC, DM_, DIC, 0, 0);
    tsplit_kernel<<<dim3(ceil_div(2 * DIA, 32), KP_SC / 32, 1), 256, 0, s2>>>(
        a_in_w, bf + BO_AINW_HI, bf + BO_AINW_LO, N_, 2 * DIA, KP_SC, 0, 0);
    tsplit_kernel<<<dim3(ceil_div(LDBA, 32), KP_A / 32, 1), 256, 0, s2>>>(
        a_xproj_w, bf + BO_AXPW_HI, bf + BO_AXPW_LO, DIA, LDBA, KP_A, 0, 0);
    tsplit_kernel<<<dim3(ceil_div(DIA, 32), KP_DTA / 32, 1), 256, 0, s2>>>(
        a_dt_w, bf + BO_ADTW_HI, bf + BO_ADTW_LO, DRA, DIA, KP_DTA, 0, 0);
    tsplit_kernel<<<dim3(ceil_div(N_, 32), KP_A / 32, 1), 256, 0, s2>>>(
        a_out_w, bf + BO_AOUTW_HI, bf + BO_AOUTW_LO, DIA, N_, KP_A, 0, 0);
    tsplit_kernel<<<dim3(ceil_div(LDBC, 32), DIC / 32, 1), 256, 0, s2>>>(
        c_xproj_w, bf + BO_CXPW_HI, bf + BO_CXPW_LO, DIC, LDBC, DIC, 0, 0);
    tsplit_kernel<<<dim3(DIC / 32, DRC / 32, 1), 256, 0, s2>>>(
        c_dt_w, bf + BO_CDTW_HI, bf + BO_CDTW_LO, DRC, DIC, DRC, 0, 0);
    cudaEventRecord(evJ, s2);

    // ---- main stream: kf/imf splits (needed by score) ----
    tsplit_kernel<<<dim3(K_ / 32, DM_ / 32, B_), 256>>>(
        kf, bf + BO_KFT_HI, bf + BO_KFT_LO, DM_, K_, DM_,
        (size_t)DM_ * K_, (size_t)K_ * DM_);
    split_pad_kernel<false><<<ceil_div((int)(BSZ_IMF / 4), 256), 256>>>(
        imf, DM_, DM_, nullptr, 0, bf + BO_IMF_HI, bf + BO_IMF_LO, DM_, (int)(BSZ_IMF / 4));

    // 0: score partials (split-K=4) -> planes (98->128 pad)
    gemm_bt<0><<<dim3(1, K_ / 128, B_ * SPLITK_SC), 256, BT_SMEM>>>(
        bf + BO_KFT_HI, bf + BO_KFT_LO, bf + BO_IMF_HI, bf + BO_IMF_LO,
        scp, N_, K_, N_, DM_, DM_, DM_, SPLITK_SC,
        (size_t)K_ * DM_, 0, (size_t)K_ * N_, SZ_SC1, nullptr, nullptr, nullptr, nullptr);
    reduce_split_kernel<<<ceil_div(Ma * KP_SC / 4, 256), 256>>>(
        scp, N_, SZ_SC1, SPLITK_SC, nullptr,
        bf + BO_SCPL_HI, bf + BO_SCPL_LO, KP_SC, Ma * KP_SC / 4);

    // ---- join: weights ready ----
    cudaStreamWaitEvent(0, evJ, 0);

    // 1: xza = score @ a_in_w
    gemm_bt<0><<<dim3(ceil_div(2 * DIA, 128), Ma / 128, 1), 256, BT_SMEM>>>(
        bf + BO_SCPL_HI, bf + BO_SCPL_LO, bf + BO_AINW_HI, bf + BO_AINW_LO,
        xza, 2 * DIA, Ma, 2 * DIA, KP_SC, KP_SC, KP_SC, 1, 0, 0, 0, 0,
        nullptr, nullptr, nullptr, nullptr);

    // 2: conv + silu (a) -> fp32 xia + planes
    conv_silu_kernel<<<ceil_div(Ma * KP_A / 4, 256), 256>>>(
        xza, 2 * DIA, a_conv_w, a_conv_b, xia,
        bf + BO_XIA_HI, bf + BO_XIA_LO, B_, LA, DIA, KP_A, Ma * KP_A / 4);

    // 3: x_dbl = xi @ a_xproj_w  (EMODE 3: also emits dt-in planes)
    gemm_bt<3><<<dim3(1, Ma / 128, 1), 256, BT_SMEM>>>(
        bf + BO_XIA_HI, bf + BO_XIA_LO, bf + BO_AXPW_HI, bf + BO_AXPW_LO,
        xdbla, LDBA, Ma, LDBA, KP_A, KP_A, KP_A, 1, 0, 0, 0, 0,
        nullptr, nullptr, bf + BO_DTAIN_HI, bf + BO_DTAIN_LO);

    // 4: dt = softplus(dtin @ a_dt_w + b)
    gemm_bt<1><<<dim3(ceil_div(DIA, 128), Ma / 128, 1), 256, BT_SMEM>>>(
        bf + BO_DTAIN_HI, bf + BO_DTAIN_LO, bf + BO_ADTW_HI, bf + BO_ADTW_LO,
        dta, DIA, Ma, DIA, KP_DTA, KP_DTA, KP_DTA, 1, 0, 0, 0, 0,
        a_dt_b, nullptr, nullptr, nullptr);

    // 5: selective scan (a)
    scan_kernel<8><<<(B_ * DIA / 2 * 32) / 256, 256>>>(
        xia, dta, xdbla, LDBA, DRA, DRA + NS, a_A_log, a_D, ya, B_, LA, DIA);

    // 6: y planes; mean(y @ a_out_w) -> sbuf (EMODE 2, no C store)
    split_pad_kernel<true><<<ceil_div(Ma * KP_A / 4, 256), 256>>>(
        ya, DIA, DIA, xza + DIA, 2 * DIA,
        bf + BO_YA_HI, bf + BO_YA_LO, KP_A, Ma * KP_A / 4);
    gemm_bt<2><<<dim3(1, Ma / 128, 1), 256, BT_SMEM>>>(
        bf + BO_YA_HI, bf + BO_YA_LO, bf + BO_AOUTW_HI, bf + BO_AOUTW_LO,
        nullptr, N_, Ma, N_, KP_A, KP_A, KP_A, 1, 0, 0, 0, 0,
        nullptr, sbuf, nullptr, nullptr);

    // 7-9: softmax+topk (fused) / gather
    topk_kernel<<<B_, 256>>>(sbuf, p_ind, p_vtop);
    build_h_kernel<<<ceil_div(B_ * LC * DM_, 256), 256>>>(
        imf, kf, p_ind, p_vtop, bf + BO_H_HI, bf + BO_H_LO);

    // 10: xzc = h @ c_in_w
    gemm_bt<0><<<dim3((2 * DIC) / 128, ceil_div(Mc, 128), 1), 256, BT_SMEM>>>(
        bf + BO_H_HI, bf + BO_H_LO, bf + BO_CINW_HI, bf + BO_CINW_LO,
        xzc, 2 * DIC, Mc, 2 * DIC, DM_, DM_, DM_, 1, 0, 0, 0, 0,
        nullptr, nullptr, nullptr, nullptr);

    // 11: conv + silu (c) -> fp32 xic + planes
    conv_silu_kernel<<<ceil_div(Mc * DIC / 4, 256), 256>>>(
        xzc, 2 * DIC, c_conv_w, c_conv_b, xic,
        bf + BO_XIC_HI, bf + BO_XIC_LO, B_, LC, DIC, DIC, Mc * DIC / 4);

    // 12: x_dbl partials = xi @ c_xproj_w (split-K=8) -> reduce+split
    gemm_bt<0><<<dim3(ceil_div(LDBC, 128), ceil_div(Mc, 128), SPLITK_XPC), 256, BT_SMEM>>>(
        bf + BO_XIC_HI, bf + BO_XIC_LO, bf + BO_CXPW_HI, bf + BO_CXPW_LO,
        xpcp, LDBC, Mc, LDBC, DIC, DIC, DIC, SPLITK_XPC,
        0, 0, 0, (size_t)Mc * LDBC, nullptr, nullptr, nullptr, nullptr);
    reduce_split_kernel<<<ceil_div(Mc * LDBC / 4, 256), 256>>>(
        xpcp, LDBC, (size_t)Mc * LDBC, SPLITK_XPC, xdblc,
        bf + BO_XDBLCP_HI, bf + BO_XDBLCP_LO, LDBC, Mc * LDBC / 4);

    // 13: dt = softplus(xdblc[:, :128] @ c_dt_w + b)
    gemm_bt<1><<<dim3(DIC / 128, ceil_div(Mc, 128), 1), 256, BT_SMEM>>>(
        bf + BO_XDBLCP_HI, bf + BO_XDBLCP_LO, bf + BO_CDTW_HI, bf + BO_CDTW_LO,
        dtc, DIC, Mc, DIC, DRC, LDBC, DRC, 1, 0, 0, 0, 0,
        c_dt_b, nullptr, nullptr, nullptr);

    // 14: selective scan (c)
    scan_kernel<7><<<(B_ * DIC / 2 * 32) / 256, 256>>>(
        xic, dtc, xdblc, LDBC, DRC, DRC + NS, c_A_log, c_D, yc, B_, LC, DIC);

    // 15: y planes; out partials (split-K=2)
    split_pad_kernel<true><<<ceil_div(Mc * DIC / 4, 256), 256>>>(
        yc, DIC, DIC, xzc + DIC, 2 * DIC,
        bf + BO_YC_HI, bf + BO_YC_LO, DIC, Mc * DIC / 4);
    gemm_bt<0><<<dim3(DM_ / 128, ceil_div(Mc, 128), SPLITK_COUT), 256, BT_SMEM>>>(
        bf + BO_YC_HI, bf + BO_YC_LO, bf + BO_COUTW_HI, bf + BO_COUTW_LO,
        outp, DM_, Mc, DM_, DIC, DIC, DIC, SPLITK_COUT,
        0, 0, 0, (size_t)Mc * DM_, nullptr, nullptr, nullptr, nullptr);

    // 16: reduce -> out
    reduce_sum_kernel<<<ceil_div(Mc * DM_, 256), 256>>>(
        outp, out, Mc * DM_, (size_t)Mc * DM_, SPLITK_COUT);
}